// round 3
// baseline (speedup 1.0000x reference)
#include <cuda_runtime.h>
#include <cstdint>
#include <cstddef>

// ===========================================================================
// SceneEncoder on GB300 — full fp32 baseline.
// Heavy path: fused K/V projection + FAVOR reduction over rg_out.
// ===========================================================================

#define NORM_RG   0.70710678118654752f   /* 4^-0.25  */
#define NORM_OBJ  0.35355339059327376f   /* 64^-0.25 */
#define STABF     0.001f
#define LNEPS     0.001f

// ------------------- scratch layout (float offsets) ------------------------
static constexpr size_t OFF_ROADX  = 0;                       // 65536*16
static constexpr size_t OFF_ROADQ  = OFF_ROADX  + 1048576;    // 65536*16
static constexpr size_t OFF_RPART  = OFF_ROADQ  + 1048576;    // 256*80
static constexpr size_t OFF_RGKV   = OFF_RPART  + 20480;      // 8*80
static constexpr size_t OFF_RGOUT  = OFF_RGKV   + 640;        // 65536*1024
static constexpr size_t OFF_KVPART = OFF_RGOUT  + 67108864;   // 2*8*16*64*4160
static constexpr size_t OFF_OBJKV  = OFF_KVPART + 68157440;   // 2*8*16*4160
static constexpr size_t OFF_XO     = OFF_OBJKV  + 1064960;    // 1024*1024
static constexpr size_t OFF_QP     = OFF_XO     + 1048576;
static constexpr size_t OFF_FAV    = OFF_QP     + 1048576;
static constexpr size_t OFF_ATTN   = OFF_FAV    + 1048576;
static constexpr size_t OFF_N      = OFF_ATTN   + 1048576;
static constexpr size_t OFF_Y      = OFF_N      + 1048576;
static constexpr size_t SCRATCH_FLOATS = OFF_Y + 1048576;     // ~579 MB

__device__ float g_s[SCRATCH_FLOATS];

// ===========================================================================
// Road stack (16 channels, 65536 tokens)
// ===========================================================================

__global__ __launch_bounds__(256) void k_road_dense(
    const float* __restrict__ rin, const float* __restrict__ W,
    const float* __restrict__ b, float* __restrict__ xout)
{
    __shared__ float Ws[128], bs[16];
    int tid = threadIdx.x;
    if (tid < 128) Ws[tid] = W[tid];
    if (tid < 16)  bs[tid] = b[tid];
    __syncthreads();
    size_t tok = (size_t)blockIdx.x * 256 + tid;
    const float4* rp = (const float4*)(rin + tok * 8);
    float4 a0 = rp[0], a1 = rp[1];
    float x[8] = {a0.x, a0.y, a0.z, a0.w, a1.x, a1.y, a1.z, a1.w};
    float o[16];
#pragma unroll
    for (int c = 0; c < 16; c++) {
        float s = bs[c];
#pragma unroll
        for (int d = 0; d < 8; d++) s += x[d] * Ws[d * 16 + c];
        o[c] = fmaxf(s, 0.f);
    }
    float4* op = (float4*)(xout + tok * 16);
    op[0] = make_float4(o[0], o[1], o[2], o[3]);
    op[1] = make_float4(o[4], o[5], o[6], o[7]);
    op[2] = make_float4(o[8], o[9], o[10], o[11]);
    op[3] = make_float4(o[12], o[13], o[14], o[15]);
}

// Per-token q projection + per-block partial reduction of FAVOR kv/ksum.
__global__ __launch_bounds__(256) void k_road_favA(
    const float* __restrict__ xin, float* __restrict__ qout,
    const float* __restrict__ qkvW, const float* __restrict__ qkvb,
    const float* __restrict__ Wk, const float* __restrict__ Wv,
    float* __restrict__ part)
{
    __shared__ float W16[256], b16[16], Wks[256], Wvs[256];
    __shared__ float wred[8 * 80];
    int tid = threadIdx.x;
    W16[tid] = qkvW[(tid >> 4) * 48 + (tid & 15)];   // first 16 cols of [16,48]
    Wks[tid] = Wk[tid];
    Wvs[tid] = Wv[tid];
    if (tid < 16) b16[tid] = qkvb[tid];
    __syncthreads();

    size_t tok = (size_t)blockIdx.x * 256 + tid;
    const float4* xp = (const float4*)(xin + tok * 16);
    float4 x0 = xp[0], x1 = xp[1], x2 = xp[2], x3 = xp[3];
    float x[16] = {x0.x, x0.y, x0.z, x0.w, x1.x, x1.y, x1.z, x1.w,
                   x2.x, x2.y, x2.z, x2.w, x3.x, x3.y, x3.z, x3.w};
    float q[16];
#pragma unroll
    for (int c = 0; c < 16; c++) {
        float s = b16[c];
#pragma unroll
        for (int d = 0; d < 16; d++) s += x[d] * W16[d * 16 + c];
        q[c] = fmaxf(s, 0.f);
    }
    float4* qo = (float4*)(qout + tok * 16);
    qo[0] = make_float4(q[0], q[1], q[2], q[3]);
    qo[1] = make_float4(q[4], q[5], q[6], q[7]);
    qo[2] = make_float4(q[8], q[9], q[10], q[11]);
    qo[3] = make_float4(q[12], q[13], q[14], q[15]);

    float kp[16], vh[16];
#pragma unroll
    for (int j = 0; j < 16; j++) {
        float sk = 0.f, sv = 0.f;
#pragma unroll
        for (int d = 0; d < 16; d++) {
            sk += q[d] * Wks[d * 16 + j];
            sv += q[d] * Wvs[d * 16 + j];
        }
        kp[j] = fmaxf(sk * NORM_RG, 0.f) + STABF;
        vh[j] = sv;
    }

    // reduce 80 values (64 kv products + 16 kp) across the block
    int lane = tid & 31, w = tid >> 5;
#pragma unroll
    for (int i = 0; i < 64; i++) {
        int hm = i >> 2;
        float v = kp[hm] * vh[(hm & 12) | (i & 3)];
#pragma unroll
        for (int off = 16; off > 0; off >>= 1) v += __shfl_down_sync(0xffffffffu, v, off);
        if (lane == 0) wred[w * 80 + i] = v;
    }
#pragma unroll
    for (int i = 0; i < 16; i++) {
        float v = kp[i];
#pragma unroll
        for (int off = 16; off > 0; off >>= 1) v += __shfl_down_sync(0xffffffffu, v, off);
        if (lane == 0) wred[w * 80 + 64 + i] = v;
    }
    __syncthreads();
    if (tid < 80) {
        float s = 0.f;
#pragma unroll
        for (int w2 = 0; w2 < 8; w2++) s += wred[w2 * 80 + tid];
        part[(size_t)blockIdx.x * 80 + tid] = s;
    }
}

__global__ void k_road_reduce(const float* __restrict__ part, float* __restrict__ kvout)
{
    int b = blockIdx.x, tid = threadIdx.x;  // 80 threads
    float s = 0.f;
    for (int k = 0; k < 32; k++) s += part[(size_t)(b * 32 + k) * 80 + tid];
    kvout[(size_t)b * 80 + tid] = s;
}

// Per-token: qp, num/den, Wo, residual+LN, fc+relu, residual+LN.
__global__ __launch_bounds__(256) void k_road_favB(
    float* __restrict__ x, const float* __restrict__ qbuf,
    const float* __restrict__ Wq, const float* __restrict__ Wo,
    const float* __restrict__ kvg,
    const float* __restrict__ lng, const float* __restrict__ lnb,
    const float* __restrict__ fcW, const float* __restrict__ fcb)
{
    __shared__ float Wqs[256], Wos[256], fcWs[256];
    __shared__ float fcbs[16], gs[16], bbs[16], kvs[64], kss[16];
    int tid = threadIdx.x;
    Wqs[tid] = Wq[tid];
    Wos[tid] = Wo[tid];
    fcWs[tid] = fcW[tid];
    if (tid < 16) { fcbs[tid] = fcb[tid]; gs[tid] = lng[tid]; bbs[tid] = lnb[tid]; }
    int b = blockIdx.x >> 5;
    if (tid < 64) kvs[tid] = kvg[(size_t)b * 80 + tid];
    if (tid < 16) kss[tid] = kvg[(size_t)b * 80 + 64 + tid];
    __syncthreads();

    size_t tok = (size_t)blockIdx.x * 256 + tid;
    const float4* qp4 = (const float4*)(qbuf + tok * 16);
    float4 q0 = qp4[0], q1 = qp4[1], q2 = qp4[2], q3 = qp4[3];
    float q[16] = {q0.x, q0.y, q0.z, q0.w, q1.x, q1.y, q1.z, q1.w,
                   q2.x, q2.y, q2.z, q2.w, q3.x, q3.y, q3.z, q3.w};
    float qp[16];
#pragma unroll
    for (int j = 0; j < 16; j++) {
        float s = 0.f;
#pragma unroll
        for (int d = 0; d < 16; d++) s += q[d] * Wqs[d * 16 + j];
        qp[j] = fmaxf(s * NORM_RG, 0.f) + STABF;
    }
    float outv[16];
#pragma unroll
    for (int h = 0; h < 4; h++) {
        float den = 0.f;
#pragma unroll
        for (int m = 0; m < 4; m++) den += qp[h * 4 + m] * kss[h * 4 + m];
        float inv = 1.f / den;
#pragma unroll
        for (int d = 0; d < 4; d++) {
            float nu = 0.f;
#pragma unroll
            for (int m = 0; m < 4; m++) nu += qp[h * 4 + m] * kvs[(h * 4 + m) * 4 + d];
            outv[h * 4 + d] = nu * inv;
        }
    }
    float attn[16];
#pragma unroll
    for (int e = 0; e < 16; e++) {
        float s = 0.f;
#pragma unroll
        for (int j = 0; j < 16; j++) s += outv[j] * Wos[j * 16 + e];
        attn[e] = s;
    }
    const float4* xp = (const float4*)(x + tok * 16);
    float4 x0 = xp[0], x1 = xp[1], x2 = xp[2], x3 = xp[3];
    float xv[16] = {x0.x, x0.y, x0.z, x0.w, x1.x, x1.y, x1.z, x1.w,
                    x2.x, x2.y, x2.z, x2.w, x3.x, x3.y, x3.z, x3.w};
    float t1[16];
#pragma unroll
    for (int c = 0; c < 16; c++) t1[c] = attn[c] + xv[c];

    // LN #1
    float mu = 0.f;
#pragma unroll
    for (int c = 0; c < 16; c++) mu += t1[c];
    mu *= (1.f / 16.f);
    float var = 0.f;
#pragma unroll
    for (int c = 0; c < 16; c++) { float d = t1[c] - mu; var += d * d; }
    var *= (1.f / 16.f);
    float rs = rsqrtf(var + LNEPS);
    float nn[16];
#pragma unroll
    for (int c = 0; c < 16; c++) nn[c] = (t1[c] - mu) * rs * gs[c] + bbs[c];

    float y[16];
#pragma unroll
    for (int c = 0; c < 16; c++) {
        float s = fcbs[c];
#pragma unroll
        for (int d = 0; d < 16; d++) s += nn[d] * fcWs[d * 16 + c];
        y[c] = fmaxf(s, 0.f);
    }
    float t2[16];
#pragma unroll
    for (int c = 0; c < 16; c++) t2[c] = nn[c] + y[c];
    // LN #2 (same gamma/beta)
    mu = 0.f;
#pragma unroll
    for (int c = 0; c < 16; c++) mu += t2[c];
    mu *= (1.f / 16.f);
    var = 0.f;
#pragma unroll
    for (int c = 0; c < 16; c++) { float d = t2[c] - mu; var += d * d; }
    var *= (1.f / 16.f);
    rs = rsqrtf(var + LNEPS);
    float o[16];
#pragma unroll
    for (int c = 0; c < 16; c++) o[c] = (t2[c] - mu) * rs * gs[c] + bbs[c];
    float4* op = (float4*)(x + tok * 16);
    op[0] = make_float4(o[0], o[1], o[2], o[3]);
    op[1] = make_float4(o[4], o[5], o[6], o[7]);
    op[2] = make_float4(o[8], o[9], o[10], o[11]);
    op[3] = make_float4(o[12], o[13], o[14], o[15]);
}

// rg_out = relu(x16 @ W[16,1024] + b) ; 16 tokens per block, 4 cols/thread
__global__ __launch_bounds__(256) void k_rg_expand(
    const float* __restrict__ x, const float* __restrict__ W,
    const float* __restrict__ b, float* __restrict__ out)
{
    __shared__ float xs[256];
    int tid = threadIdx.x;
    size_t tok0 = (size_t)blockIdx.x * 16;
    xs[tid] = x[tok0 * 16 + tid];
    __syncthreads();
    int c0 = tid * 4;
    float4 wv[16];
#pragma unroll
    for (int d = 0; d < 16; d++) wv[d] = *(const float4*)(W + d * 1024 + c0);
    float4 bb = *(const float4*)(b + c0);
#pragma unroll 4
    for (int tk = 0; tk < 16; tk++) {
        float4 a = bb;
#pragma unroll
        for (int d = 0; d < 16; d++) {
            float xv = xs[tk * 16 + d];
            a.x += xv * wv[d].x; a.y += xv * wv[d].y;
            a.z += xv * wv[d].z; a.w += xv * wv[d].w;
        }
        a.x = fmaxf(a.x, 0.f); a.y = fmaxf(a.y, 0.f);
        a.z = fmaxf(a.z, 0.f); a.w = fmaxf(a.w, 0.f);
        *(float4*)(out + (tok0 + tk) * 1024 + c0) = a;
    }
}

// ===========================================================================
// Fused K/V projection + FAVOR partial reduction (THE heavy kernel)
// grid: (h=16, tile=512, layer=2), 256 threads, 66048 B dyn smem
// ===========================================================================
__global__ __launch_bounds__(256) void k_kv_fused(
    const float* __restrict__ rgout, const float* __restrict__ Wk,
    const float* __restrict__ Wv, float* __restrict__ part)
{
    extern __shared__ float sm[];
    float* As = sm;               // [16][132]
    float* Bs = sm + 16 * 132;    // [16][128]
    int h = blockIdx.x, tile = blockIdx.y, layer = blockIdx.z;
    int tid = threadIdx.x;
    const float* Ag = rgout + (size_t)tile * 128 * 1024;
    size_t wbase = (size_t)layer * 1048576 + (size_t)h * 64;
    float acc[8][8] = {};
    int r0 = (tid >> 4) * 8, c0 = (tid & 15) * 8;

    for (int kb = 0; kb < 1024; kb += 16) {
#pragma unroll
        for (int s = 0; s < 2; s++) {
            int slot = tid * 2 + s;
            int m = slot >> 2, k4 = (slot & 3) * 4;
            float4 v = *(const float4*)(Ag + (size_t)m * 1024 + kb + k4);
            As[(k4 + 0) * 132 + m] = v.x;
            As[(k4 + 1) * 132 + m] = v.y;
            As[(k4 + 2) * 132 + m] = v.z;
            As[(k4 + 3) * 132 + m] = v.w;
        }
#pragma unroll
        for (int s = 0; s < 2; s++) {
            int slot = tid * 2 + s;
            int k = slot >> 5, n0 = (slot & 31) * 4;
            const float* Wp = (n0 < 64) ? Wk : Wv;
            float4 v = *(const float4*)(Wp + wbase + (size_t)(kb + k) * 1024 + (n0 & 63));
            *(float4*)&Bs[k * 128 + n0] = v;
        }
        __syncthreads();
#pragma unroll
        for (int kk = 0; kk < 16; kk++) {
            float4 a0 = *(float4*)&As[kk * 132 + r0];
            float4 a1 = *(float4*)&As[kk * 132 + r0 + 4];
            float4 b0 = *(float4*)&Bs[kk * 128 + c0];
            float4 b1 = *(float4*)&Bs[kk * 128 + c0 + 4];
            float ar[8] = {a0.x, a0.y, a0.z, a0.w, a1.x, a1.y, a1.z, a1.w};
            float br[8] = {b0.x, b0.y, b0.z, b0.w, b1.x, b1.y, b1.z, b1.w};
#pragma unroll
            for (int i = 0; i < 8; i++)
#pragma unroll
                for (int j = 0; j < 8; j++) acc[i][j] += ar[i] * br[j];
        }
        __syncthreads();
    }

    // K half (cols 0..63): kp = relu(k*norm)+stab
    if ((tid & 15) < 8) {
#pragma unroll
        for (int i = 0; i < 8; i++)
#pragma unroll
            for (int j = 0; j < 8; j++)
                acc[i][j] = fmaxf(acc[i][j] * NORM_OBJ, 0.f) + STABF;
    }
    // stage 128x128 tile (cols 0..63 kp, 64..127 v)
    float* S = sm;  // [128][129]
#pragma unroll
    for (int i = 0; i < 8; i++)
#pragma unroll
        for (int j = 0; j < 8; j++)
            S[(size_t)(r0 + i) * 129 + c0 + j] = acc[i][j];
    __syncthreads();

    // partial kv[m][d] = sum_s kp[s][m]*v[s][d]  (4x4 per thread)
    int pm0 = (tid >> 4) * 4, pd0 = (tid & 15) * 4;
    float r[4][4] = {};
    for (int s = 0; s < 128; s++) {
        const float* row = &S[(size_t)s * 129];
        float kp0 = row[pm0], kp1 = row[pm0 + 1], kp2 = row[pm0 + 2], kp3 = row[pm0 + 3];
        float v0 = row[64 + pd0], v1 = row[64 + pd0 + 1], v2 = row[64 + pd0 + 2], v3 = row[64 + pd0 + 3];
        r[0][0] += kp0 * v0; r[0][1] += kp0 * v1; r[0][2] += kp0 * v2; r[0][3] += kp0 * v3;
        r[1][0] += kp1 * v0; r[1][1] += kp1 * v1; r[1][2] += kp1 * v2; r[1][3] += kp1 * v3;
        r[2][0] += kp2 * v0; r[2][1] += kp2 * v1; r[2][2] += kp2 * v2; r[2][3] += kp2 * v3;
        r[3][0] += kp3 * v0; r[3][1] += kp3 * v1; r[3][2] += kp3 * v2; r[3][3] += kp3 * v3;
    }
    size_t pbase = ((((size_t)layer * 8 + (tile >> 6)) * 16 + h) * 64 + (tile & 63)) * 4160;
#pragma unroll
    for (int i = 0; i < 4; i++)
#pragma unroll
        for (int j = 0; j < 4; j++)
            part[pbase + (pm0 + i) * 64 + pd0 + j] = r[i][j];
    if (tid < 64) {
        float s = 0.f;
        for (int s2 = 0; s2 < 128; s2++) s += S[(size_t)s2 * 129 + tid];
        part[pbase + 4096 + tid] = s;
    }
}

__global__ void k_kv_reduce(const float* __restrict__ part, float* __restrict__ out)
{
    int j = blockIdx.x * 256 + threadIdx.x;
    if (j >= 4160) return;
    int bh = blockIdx.y, layer = blockIdx.z;
    size_t pb = ((size_t)layer * 128 + bh) * 64 * 4160;
    float s = 0.f;
#pragma unroll 8
    for (int t = 0; t < 64; t++) s += part[pb + (size_t)t * 4160 + j];
    out[((size_t)layer * 128 + bh) * 4160 + j] = s;
}

// ===========================================================================
// Generic small SGEMM (64x64 tiles) with fused epilogues, M,N,K mult of 64/16
// modes: 0 none | 1 bias+relu | 2 bias+relu+pos | 3 relu(x*scale)+STAB | 4 +aux
// ===========================================================================
__global__ __launch_bounds__(256) void k_sgemm64(
    const float* __restrict__ A, const float* __restrict__ B, float* __restrict__ C,
    int M, int N, int K, int mode, float scale,
    const float* __restrict__ bias, const float* __restrict__ aux)
{
    __shared__ float As[16 * 68];
    __shared__ float Bs[16 * 68];
    int tid = threadIdx.x;
    int m0 = blockIdx.y * 64, n0 = blockIdx.x * 64;
    int lm = tid >> 2, lk4 = (tid & 3) * 4;
    int lbk = tid >> 4, lbc = (tid & 15) * 4;
    int r0 = (tid >> 4) * 4, c0 = (tid & 15) * 4;
    float acc[4][4] = {};
    for (int kb = 0; kb < K; kb += 16) {
        float4 av = *(const float4*)(A + (size_t)(m0 + lm) * K + kb + lk4);
        As[(lk4 + 0) * 68 + lm] = av.x;
        As[(lk4 + 1) * 68 + lm] = av.y;
        As[(lk4 + 2) * 68 + lm] = av.z;
        As[(lk4 + 3) * 68 + lm] = av.w;
        *(float4*)&Bs[lbk * 68 + lbc] = *(const float4*)(B + (size_t)(kb + lbk) * N + n0 + lbc);
        __syncthreads();
#pragma unroll
        for (int kk = 0; kk < 16; kk++) {
            float4 a = *(float4*)&As[kk * 68 + r0];
            float4 b = *(float4*)&Bs[kk * 68 + c0];
            float ar[4] = {a.x, a.y, a.z, a.w};
            float br[4] = {b.x, b.y, b.z, b.w};
#pragma unroll
            for (int i = 0; i < 4; i++)
#pragma unroll
                for (int j = 0; j < 4; j++) acc[i][j] += ar[i] * br[j];
        }
        __syncthreads();
    }
#pragma unroll
    for (int i = 0; i < 4; i++) {
        int gm = m0 + r0 + i;
#pragma unroll
        for (int j = 0; j < 4; j++) {
            int gn = n0 + c0 + j;
            float v = acc[i][j];
            if (mode == 1)      v = fmaxf(v + bias[gn], 0.f);
            else if (mode == 2) v = fmaxf(v + bias[gn], 0.f) + aux[(size_t)(gm & 127) * N + gn];
            else if (mode == 3) v = fmaxf(v * scale, 0.f) + STABF;
            else if (mode == 4) v = v + aux[(size_t)gm * N + gn];
            C[(size_t)gm * N + gn] = v;
        }
    }
}

// ===========================================================================
// Obj FAVOR apply: out = (qp @ kv) / (qp . ksum), per (b,h)
// ===========================================================================
__global__ __launch_bounds__(256) void k_fav_apply(
    const float* __restrict__ qp, const float* __restrict__ kvg,
    float* __restrict__ fav, int layer)
{
    __shared__ float kvs[4096];
    __shared__ float kss[64];
    __shared__ float den[128];
    int h = blockIdx.x, b = blockIdx.y, tid = threadIdx.x;
    size_t base = ((size_t)layer * 128 + b * 16 + h) * 4160;
#pragma unroll
    for (int i = 0; i < 16; i++) kvs[tid + i * 256] = kvg[base + tid + i * 256];
    if (tid < 64) kss[tid] = kvg[base + 4096 + tid];
    __syncthreads();
    if (tid < 128) {
        const float* qr = qp + ((size_t)(b * 128 + tid)) * 1024 + h * 64;
        float s = 0.f;
#pragma unroll
        for (int m = 0; m < 64; m++) s += qr[m] * kss[m];
        den[tid] = s;
    }
    __syncthreads();
    int t = tid >> 1, d0 = (tid & 1) * 32;
    const float* qr = qp + ((size_t)(b * 128 + t)) * 1024 + h * 64;
    float a[32] = {};
    for (int m = 0; m < 64; m++) {
        float qv = qr[m];
#pragma unroll
        for (int j = 0; j < 32; j++) a[j] += qv * kvs[m * 64 + d0 + j];
    }
    float inv = 1.f / den[t];
    float* op = fav + ((size_t)(b * 128 + t)) * 1024 + h * 64 + d0;
#pragma unroll
    for (int j = 0; j < 32; j++) op[j] = a[j] * inv;
}

// ===========================================================================
// Row LayerNorm over 1024 channels; o = LN(a [+ b2])
// ===========================================================================
__global__ __launch_bounds__(256) void k_ln1024(
    const float* __restrict__ a, const float* __restrict__ b2,
    float* __restrict__ o, const float* __restrict__ g, const float* __restrict__ be)
{
    __shared__ float red[256];
    int row = blockIdx.x, tid = threadIdx.x;
    const float* ap = a + (size_t)row * 1024;
    float v[4];
    float s = 0.f;
#pragma unroll
    for (int j = 0; j < 4; j++) {
        int c = tid + j * 256;
        float x = ap[c];
        if (b2) x += b2[(size_t)row * 1024 + c];
        v[j] = x; s += x;
    }
    red[tid] = s; __syncthreads();
    for (int off = 128; off; off >>= 1) {
        if (tid < off) red[tid] += red[tid + off];
        __syncthreads();
    }
    float mu = red[0] * (1.f / 1024.f);
    __syncthreads();
    float s2 = 0.f;
#pragma unroll
    for (int j = 0; j < 4; j++) { float d = v[j] - mu; s2 += d * d; }
    red[tid] = s2; __syncthreads();
    for (int off = 128; off; off >>= 1) {
        if (tid < off) red[tid] += red[tid + off];
        __syncthreads();
    }
    float rs = rsqrtf(red[0] * (1.f / 1024.f) + LNEPS);
    float* op = o + (size_t)row * 1024;
#pragma unroll
    for (int j = 0; j < 4; j++) {
        int c = tid + j * 256;
        op[c] = (v[j] - mu) * rs * g[c] + be[c];
    }
}

// ===========================================================================
// Launch
// ===========================================================================
extern "C" void kernel_launch(void* const* d_in, const int* in_sizes, int n_in,
                              void* d_out, int out_size)
{
    const float* obj_inputs  = (const float*)d_in[0];
    const float* road_inputs = (const float*)d_in[1];
    const float* rg_dense_W  = (const float*)d_in[2];
    const float* rg_dense_b  = (const float*)d_in[3];
    const float* rg_qkv_W    = (const float*)d_in[4];
    const float* rg_qkv_b    = (const float*)d_in[5];
    const float* rg_Wq       = (const float*)d_in[6];
    const float* rg_Wk       = (const float*)d_in[7];
    const float* rg_Wv       = (const float*)d_in[8];
    const float* rg_Wo       = (const float*)d_in[9];
    const float* rg_ln_g     = (const float*)d_in[10];
    const float* rg_ln_b     = (const float*)d_in[11];
    const float* rg_fc_W     = (const float*)d_in[12];
    const float* rg_fc_b     = (const float*)d_in[13];
    const float* rg_out_W    = (const float*)d_in[14];
    const float* rg_out_b    = (const float*)d_in[15];
    const float* dense_W     = (const float*)d_in[16];
    const float* dense_b     = (const float*)d_in[17];
    const float* pos_emb     = (const float*)d_in[18];
    const float* Wq          = (const float*)d_in[19];
    const float* Wk          = (const float*)d_in[20];
    const float* Wv          = (const float*)d_in[21];
    const float* Wo          = (const float*)d_in[22];
    const float* ln_g        = (const float*)d_in[23];
    const float* ln_b        = (const float*)d_in[24];
    const float* fc_W        = (const float*)d_in[25];
    const float* fc_b        = (const float*)d_in[26];
    float* out = (float*)d_out;

    float* base = nullptr;
    cudaGetSymbolAddress((void**)&base, g_s);
    float* roadx  = base + OFF_ROADX;
    float* roadq  = base + OFF_ROADQ;
    float* rpart  = base + OFF_RPART;
    float* rgkv   = base + OFF_RGKV;
    float* rgout  = base + OFF_RGOUT;
    float* kvpart = base + OFF_KVPART;
    float* objkv  = base + OFF_OBJKV;
    float* xo     = base + OFF_XO;
    float* qpbuf  = base + OFF_QP;
    float* favb   = base + OFF_FAV;
    float* attnb  = base + OFF_ATTN;
    float* nbuf   = base + OFF_N;
    float* ybuf   = base + OFF_Y;

    cudaFuncSetAttribute(k_kv_fused, cudaFuncAttributeMaxDynamicSharedMemorySize, 66048);

    // ---- road stack ----
    k_road_dense<<<256, 256>>>(road_inputs, rg_dense_W, rg_dense_b, roadx);
    for (int i = 0; i < 2; i++) {
        k_road_favA<<<256, 256>>>(roadx, roadq, rg_qkv_W, rg_qkv_b,
                                  rg_Wk + i * 256, rg_Wv + i * 256, rpart);
        k_road_reduce<<<8, 80>>>(rpart, rgkv);
        k_road_favB<<<256, 256>>>(roadx, roadq, rg_Wq + i * 256, rg_Wo + i * 256,
                                  rgkv, rg_ln_g + i * 16, rg_ln_b + i * 16,
                                  rg_fc_W + i * 256, rg_fc_b + i * 16);
    }
    k_rg_expand<<<4096, 256>>>(roadx, rg_out_W, rg_out_b, rgout);

    // ---- heavy fused K/V + FAVOR reduction (both layers) ----
    k_kv_fused<<<dim3(16, 512, 2), 256, 66048>>>(rgout, Wk, Wv, kvpart);
    k_kv_reduce<<<dim3(17, 128, 2), 256>>>(kvpart, objkv);

    // ---- obj stack ----
    k_sgemm64<<<dim3(16, 16), 256>>>(obj_inputs, dense_W, xo,
                                     1024, 1024, 512, 2, 0.f, dense_b, pos_emb);
    for (int i = 0; i < 2; i++) {
        k_sgemm64<<<dim3(16, 16), 256>>>(xo, Wq + (size_t)i * 1048576, qpbuf,
                                         1024, 1024, 1024, 3, NORM_OBJ, nullptr, nullptr);
        k_fav_apply<<<dim3(16, 8), 256>>>(qpbuf, objkv, favb, i);
        k_sgemm64<<<dim3(16, 16), 256>>>(favb, Wo + (size_t)i * 1048576, attnb,
                                         1024, 1024, 1024, 4, 0.f, nullptr, xo);
        k_ln1024<<<1024, 256>>>(attnb, nullptr, nbuf, ln_g + i * 1024, ln_b + i * 1024);
        k_sgemm64<<<dim3(16, 16), 256>>>(nbuf, fc_W + (size_t)i * 1048576, ybuf,
                                         1024, 1024, 1024, 1, 0.f, fc_b + i * 1024, nullptr);
        k_ln1024<<<1024, 256>>>(nbuf, ybuf, (i == 0) ? xo : out,
                                ln_g + i * 1024, ln_b + i * 1024);
    }
}

// round 4
// speedup vs baseline: 1.0574x; 1.0574x over previous
#include <cuda_runtime.h>
#include <cstdint>
#include <cstddef>

// ===========================================================================
// SceneEncoder on GB300 — full fp32 baseline.
// Heavy path: fused K/V projection + FAVOR reduction over rg_out.
// ===========================================================================

#define NORM_RG   0.70710678118654752f   /* 4^-0.25  */
#define NORM_OBJ  0.35355339059327376f   /* 64^-0.25 */
#define STABF     0.001f
#define LNEPS     0.001f

// ------------------- scratch layout (float offsets) ------------------------
static constexpr size_t OFF_ROADX  = 0;                       // 65536*16
static constexpr size_t OFF_ROADQ  = OFF_ROADX  + 1048576;    // 65536*16
static constexpr size_t OFF_RPART  = OFF_ROADQ  + 1048576;    // 256*80
static constexpr size_t OFF_RGKV   = OFF_RPART  + 20480;      // 8*80
static constexpr size_t OFF_RGOUT  = OFF_RGKV   + 640;        // 65536*1024
static constexpr size_t OFF_KVPART = OFF_RGOUT  + 67108864;   // 2*8*16*64*4160
static constexpr size_t OFF_OBJKV  = OFF_KVPART + 68157440;   // 2*8*16*4160
static constexpr size_t OFF_XO     = OFF_OBJKV  + 1064960;    // 1024*1024
static constexpr size_t OFF_QP     = OFF_XO     + 1048576;
static constexpr size_t OFF_FAV    = OFF_QP     + 1048576;
static constexpr size_t OFF_ATTN   = OFF_FAV    + 1048576;
static constexpr size_t OFF_N      = OFF_ATTN   + 1048576;
static constexpr size_t OFF_Y      = OFF_N      + 1048576;
static constexpr size_t SCRATCH_FLOATS = OFF_Y + 1048576;     // ~579 MB

__device__ float g_s[SCRATCH_FLOATS];

// ===========================================================================
// Road stack (16 channels, 65536 tokens)
// ===========================================================================

__global__ __launch_bounds__(256) void k_road_dense(
    const float* __restrict__ rin, const float* __restrict__ W,
    const float* __restrict__ b, float* __restrict__ xout)
{
    __shared__ float Ws[128], bs[16];
    int tid = threadIdx.x;
    if (tid < 128) Ws[tid] = W[tid];
    if (tid < 16)  bs[tid] = b[tid];
    __syncthreads();
    size_t tok = (size_t)blockIdx.x * 256 + tid;
    const float4* rp = (const float4*)(rin + tok * 8);
    float4 a0 = rp[0], a1 = rp[1];
    float x[8] = {a0.x, a0.y, a0.z, a0.w, a1.x, a1.y, a1.z, a1.w};
    float o[16];
#pragma unroll
    for (int c = 0; c < 16; c++) {
        float s = bs[c];
#pragma unroll
        for (int d = 0; d < 8; d++) s += x[d] * Ws[d * 16 + c];
        o[c] = fmaxf(s, 0.f);
    }
    float4* op = (float4*)(xout + tok * 16);
    op[0] = make_float4(o[0], o[1], o[2], o[3]);
    op[1] = make_float4(o[4], o[5], o[6], o[7]);
    op[2] = make_float4(o[8], o[9], o[10], o[11]);
    op[3] = make_float4(o[12], o[13], o[14], o[15]);
}

// Per-token q projection + per-block partial reduction of FAVOR kv/ksum.
__global__ __launch_bounds__(256) void k_road_favA(
    const float* __restrict__ xin, float* __restrict__ qout,
    const float* __restrict__ qkvW, const float* __restrict__ qkvb,
    const float* __restrict__ Wk, const float* __restrict__ Wv,
    float* __restrict__ part)
{
    __shared__ float W16[256], b16[16], Wks[256], Wvs[256];
    __shared__ float wred[8 * 80];
    int tid = threadIdx.x;
    W16[tid] = qkvW[(tid >> 4) * 48 + (tid & 15)];   // first 16 cols of [16,48]
    Wks[tid] = Wk[tid];
    Wvs[tid] = Wv[tid];
    if (tid < 16) b16[tid] = qkvb[tid];
    __syncthreads();

    size_t tok = (size_t)blockIdx.x * 256 + tid;
    const float4* xp = (const float4*)(xin + tok * 16);
    float4 x0 = xp[0], x1 = xp[1], x2 = xp[2], x3 = xp[3];
    float x[16] = {x0.x, x0.y, x0.z, x0.w, x1.x, x1.y, x1.z, x1.w,
                   x2.x, x2.y, x2.z, x2.w, x3.x, x3.y, x3.z, x3.w};
    float q[16];
#pragma unroll
    for (int c = 0; c < 16; c++) {
        float s = b16[c];
#pragma unroll
        for (int d = 0; d < 16; d++) s += x[d] * W16[d * 16 + c];
        q[c] = fmaxf(s, 0.f);
    }
    float4* qo = (float4*)(qout + tok * 16);
    qo[0] = make_float4(q[0], q[1], q[2], q[3]);
    qo[1] = make_float4(q[4], q[5], q[6], q[7]);
    qo[2] = make_float4(q[8], q[9], q[10], q[11]);
    qo[3] = make_float4(q[12], q[13], q[14], q[15]);

    float kp[16], vh[16];
#pragma unroll
    for (int j = 0; j < 16; j++) {
        float sk = 0.f, sv = 0.f;
#pragma unroll
        for (int d = 0; d < 16; d++) {
            sk += q[d] * Wks[d * 16 + j];
            sv += q[d] * Wvs[d * 16 + j];
        }
        kp[j] = fmaxf(sk * NORM_RG, 0.f) + STABF;
        vh[j] = sv;
    }

    // reduce 80 values (64 kv products + 16 kp) across the block
    int lane = tid & 31, w = tid >> 5;
#pragma unroll
    for (int i = 0; i < 64; i++) {
        int hm = i >> 2;
        float v = kp[hm] * vh[(hm & 12) | (i & 3)];
#pragma unroll
        for (int off = 16; off > 0; off >>= 1) v += __shfl_down_sync(0xffffffffu, v, off);
        if (lane == 0) wred[w * 80 + i] = v;
    }
#pragma unroll
    for (int i = 0; i < 16; i++) {
        float v = kp[i];
#pragma unroll
        for (int off = 16; off > 0; off >>= 1) v += __shfl_down_sync(0xffffffffu, v, off);
        if (lane == 0) wred[w * 80 + 64 + i] = v;
    }
    __syncthreads();
    if (tid < 80) {
        float s = 0.f;
#pragma unroll
        for (int w2 = 0; w2 < 8; w2++) s += wred[w2 * 80 + tid];
        part[(size_t)blockIdx.x * 80 + tid] = s;
    }
}

__global__ void k_road_reduce(const float* __restrict__ part, float* __restrict__ kvout)
{
    int b = blockIdx.x, tid = threadIdx.x;  // 80 threads
    float s = 0.f;
    for (int k = 0; k < 32; k++) s += part[(size_t)(b * 32 + k) * 80 + tid];
    kvout[(size_t)b * 80 + tid] = s;
}

// Per-token: qp, num/den, Wo, residual+LN, fc+relu, residual+LN.
__global__ __launch_bounds__(256) void k_road_favB(
    float* __restrict__ x, const float* __restrict__ qbuf,
    const float* __restrict__ Wq, const float* __restrict__ Wo,
    const float* __restrict__ kvg,
    const float* __restrict__ lng, const float* __restrict__ lnb,
    const float* __restrict__ fcW, const float* __restrict__ fcb)
{
    __shared__ float Wqs[256], Wos[256], fcWs[256];
    __shared__ float fcbs[16], gs[16], bbs[16], kvs[64], kss[16];
    int tid = threadIdx.x;
    Wqs[tid] = Wq[tid];
    Wos[tid] = Wo[tid];
    fcWs[tid] = fcW[tid];
    if (tid < 16) { fcbs[tid] = fcb[tid]; gs[tid] = lng[tid]; bbs[tid] = lnb[tid]; }
    int b = blockIdx.x >> 5;
    if (tid < 64) kvs[tid] = kvg[(size_t)b * 80 + tid];
    if (tid < 16) kss[tid] = kvg[(size_t)b * 80 + 64 + tid];
    __syncthreads();

    size_t tok = (size_t)blockIdx.x * 256 + tid;
    const float4* qp4 = (const float4*)(qbuf + tok * 16);
    float4 q0 = qp4[0], q1 = qp4[1], q2 = qp4[2], q3 = qp4[3];
    float q[16] = {q0.x, q0.y, q0.z, q0.w, q1.x, q1.y, q1.z, q1.w,
                   q2.x, q2.y, q2.z, q2.w, q3.x, q3.y, q3.z, q3.w};
    float qp[16];
#pragma unroll
    for (int j = 0; j < 16; j++) {
        float s = 0.f;
#pragma unroll
        for (int d = 0; d < 16; d++) s += q[d] * Wqs[d * 16 + j];
        qp[j] = fmaxf(s * NORM_RG, 0.f) + STABF;
    }
    float outv[16];
#pragma unroll
    for (int h = 0; h < 4; h++) {
        float den = 0.f;
#pragma unroll
        for (int m = 0; m < 4; m++) den += qp[h * 4 + m] * kss[h * 4 + m];
        float inv = 1.f / den;
#pragma unroll
        for (int d = 0; d < 4; d++) {
            float nu = 0.f;
#pragma unroll
            for (int m = 0; m < 4; m++) nu += qp[h * 4 + m] * kvs[(h * 4 + m) * 4 + d];
            outv[h * 4 + d] = nu * inv;
        }
    }
    float attn[16];
#pragma unroll
    for (int e = 0; e < 16; e++) {
        float s = 0.f;
#pragma unroll
        for (int j = 0; j < 16; j++) s += outv[j] * Wos[j * 16 + e];
        attn[e] = s;
    }
    const float4* xp = (const float4*)(x + tok * 16);
    float4 x0 = xp[0], x1 = xp[1], x2 = xp[2], x3 = xp[3];
    float xv[16] = {x0.x, x0.y, x0.z, x0.w, x1.x, x1.y, x1.z, x1.w,
                    x2.x, x2.y, x2.z, x2.w, x3.x, x3.y, x3.z, x3.w};
    float t1[16];
#pragma unroll
    for (int c = 0; c < 16; c++) t1[c] = attn[c] + xv[c];

    // LN #1
    float mu = 0.f;
#pragma unroll
    for (int c = 0; c < 16; c++) mu += t1[c];
    mu *= (1.f / 16.f);
    float var = 0.f;
#pragma unroll
    for (int c = 0; c < 16; c++) { float d = t1[c] - mu; var += d * d; }
    var *= (1.f / 16.f);
    float rs = rsqrtf(var + LNEPS);
    float nn[16];
#pragma unroll
    for (int c = 0; c < 16; c++) nn[c] = (t1[c] - mu) * rs * gs[c] + bbs[c];

    float y[16];
#pragma unroll
    for (int c = 0; c < 16; c++) {
        float s = fcbs[c];
#pragma unroll
        for (int d = 0; d < 16; d++) s += nn[d] * fcWs[d * 16 + c];
        y[c] = fmaxf(s, 0.f);
    }
    float t2[16];
#pragma unroll
    for (int c = 0; c < 16; c++) t2[c] = nn[c] + y[c];
    // LN #2 (same gamma/beta)
    mu = 0.f;
#pragma unroll
    for (int c = 0; c < 16; c++) mu += t2[c];
    mu *= (1.f / 16.f);
    var = 0.f;
#pragma unroll
    for (int c = 0; c < 16; c++) { float d = t2[c] - mu; var += d * d; }
    var *= (1.f / 16.f);
    rs = rsqrtf(var + LNEPS);
    float o[16];
#pragma unroll
    for (int c = 0; c < 16; c++) o[c] = (t2[c] - mu) * rs * gs[c] + bbs[c];
    float4* op = (float4*)(x + tok * 16);
    op[0] = make_float4(o[0], o[1], o[2], o[3]);
    op[1] = make_float4(o[4], o[5], o[6], o[7]);
    op[2] = make_float4(o[8], o[9], o[10], o[11]);
    op[3] = make_float4(o[12], o[13], o[14], o[15]);
}

// rg_out = relu(x16 @ W[16,1024] + b) ; 16 tokens per block, 4 cols/thread
__global__ __launch_bounds__(256) void k_rg_expand(
    const float* __restrict__ x, const float* __restrict__ W,
    const float* __restrict__ b, float* __restrict__ out)
{
    __shared__ float xs[256];
    int tid = threadIdx.x;
    size_t tok0 = (size_t)blockIdx.x * 16;
    xs[tid] = x[tok0 * 16 + tid];
    __syncthreads();
    int c0 = tid * 4;
    float4 wv[16];
#pragma unroll
    for (int d = 0; d < 16; d++) wv[d] = *(const float4*)(W + d * 1024 + c0);
    float4 bb = *(const float4*)(b + c0);
#pragma unroll 4
    for (int tk = 0; tk < 16; tk++) {
        float4 a = bb;
#pragma unroll
        for (int d = 0; d < 16; d++) {
            float xv = xs[tk * 16 + d];
            a.x += xv * wv[d].x; a.y += xv * wv[d].y;
            a.z += xv * wv[d].z; a.w += xv * wv[d].w;
        }
        a.x = fmaxf(a.x, 0.f); a.y = fmaxf(a.y, 0.f);
        a.z = fmaxf(a.z, 0.f); a.w = fmaxf(a.w, 0.f);
        *(float4*)(out + (tok0 + tk) * 1024 + c0) = a;
    }
}

// ===========================================================================
// Fused K/V projection + FAVOR partial reduction (THE heavy kernel)
// grid: (h=16, tile=512, layer=2), 256 threads, 66048 B dyn smem
// ===========================================================================
__global__ __launch_bounds__(256) void k_kv_fused(
    const float* __restrict__ rgout, const float* __restrict__ Wk,
    const float* __restrict__ Wv, float* __restrict__ part)
{
    extern __shared__ float sm[];
    float* As = sm;               // [16][132]
    float* Bs = sm + 16 * 132;    // [16][128]
    int h = blockIdx.x, tile = blockIdx.y, layer = blockIdx.z;
    int tid = threadIdx.x;
    const float* Ag = rgout + (size_t)tile * 128 * 1024;
    size_t wbase = (size_t)layer * 1048576 + (size_t)h * 64;
    float acc[8][8] = {};
    int r0 = (tid >> 4) * 8, c0 = (tid & 15) * 8;

    for (int kb = 0; kb < 1024; kb += 16) {
#pragma unroll
        for (int s = 0; s < 2; s++) {
            int slot = tid * 2 + s;
            int m = slot >> 2, k4 = (slot & 3) * 4;
            float4 v = *(const float4*)(Ag + (size_t)m * 1024 + kb + k4);
            As[(k4 + 0) * 132 + m] = v.x;
            As[(k4 + 1) * 132 + m] = v.y;
            As[(k4 + 2) * 132 + m] = v.z;
            As[(k4 + 3) * 132 + m] = v.w;
        }
#pragma unroll
        for (int s = 0; s < 2; s++) {
            int slot = tid * 2 + s;
            int k = slot >> 5, n0 = (slot & 31) * 4;
            const float* Wp = (n0 < 64) ? Wk : Wv;
            float4 v = *(const float4*)(Wp + wbase + (size_t)(kb + k) * 1024 + (n0 & 63));
            *(float4*)&Bs[k * 128 + n0] = v;
        }
        __syncthreads();
#pragma unroll
        for (int kk = 0; kk < 16; kk++) {
            float4 a0 = *(float4*)&As[kk * 132 + r0];
            float4 a1 = *(float4*)&As[kk * 132 + r0 + 4];
            float4 b0 = *(float4*)&Bs[kk * 128 + c0];
            float4 b1 = *(float4*)&Bs[kk * 128 + c0 + 4];
            float ar[8] = {a0.x, a0.y, a0.z, a0.w, a1.x, a1.y, a1.z, a1.w};
            float br[8] = {b0.x, b0.y, b0.z, b0.w, b1.x, b1.y, b1.z, b1.w};
#pragma unroll
            for (int i = 0; i < 8; i++)
#pragma unroll
                for (int j = 0; j < 8; j++) acc[i][j] += ar[i] * br[j];
        }
        __syncthreads();
    }

    // K half (cols 0..63): kp = relu(k*norm)+stab
    if ((tid & 15) < 8) {
#pragma unroll
        for (int i = 0; i < 8; i++)
#pragma unroll
            for (int j = 0; j < 8; j++)
                acc[i][j] = fmaxf(acc[i][j] * NORM_OBJ, 0.f) + STABF;
    }
    // stage 128x128 tile (cols 0..63 kp, 64..127 v)
    float* S = sm;  // [128][129]
#pragma unroll
    for (int i = 0; i < 8; i++)
#pragma unroll
        for (int j = 0; j < 8; j++)
            S[(size_t)(r0 + i) * 129 + c0 + j] = acc[i][j];
    __syncthreads();

    // partial kv[m][d] = sum_s kp[s][m]*v[s][d]  (4x4 per thread)
    int pm0 = (tid >> 4) * 4, pd0 = (tid & 15) * 4;
    float r[4][4] = {};
    for (int s = 0; s < 128; s++) {
        const float* row = &S[(size_t)s * 129];
        float kp0 = row[pm0], kp1 = row[pm0 + 1], kp2 = row[pm0 + 2], kp3 = row[pm0 + 3];
        float v0 = row[64 + pd0], v1 = row[64 + pd0 + 1], v2 = row[64 + pd0 + 2], v3 = row[64 + pd0 + 3];
        r[0][0] += kp0 * v0; r[0][1] += kp0 * v1; r[0][2] += kp0 * v2; r[0][3] += kp0 * v3;
        r[1][0] += kp1 * v0; r[1][1] += kp1 * v1; r[1][2] += kp1 * v2; r[1][3] += kp1 * v3;
        r[2][0] += kp2 * v0; r[2][1] += kp2 * v1; r[2][2] += kp2 * v2; r[2][3] += kp2 * v3;
        r[3][0] += kp3 * v0; r[3][1] += kp3 * v1; r[3][2] += kp3 * v2; r[3][3] += kp3 * v3;
    }
    size_t pbase = ((((size_t)layer * 8 + (tile >> 6)) * 16 + h) * 64 + (tile & 63)) * 4160;
#pragma unroll
    for (int i = 0; i < 4; i++)
#pragma unroll
        for (int j = 0; j < 4; j++)
            part[pbase + (pm0 + i) * 64 + pd0 + j] = r[i][j];
    if (tid < 64) {
        float s = 0.f;
        for (int s2 = 0; s2 < 128; s2++) s += S[(size_t)s2 * 129 + tid];
        part[pbase + 4096 + tid] = s;
    }
}

__global__ void k_kv_reduce(const float* __restrict__ part, float* __restrict__ out)
{
    int j = blockIdx.x * 256 + threadIdx.x;
    if (j >= 4160) return;
    int bh = blockIdx.y, layer = blockIdx.z;
    size_t pb = ((size_t)layer * 128 + bh) * 64 * 4160;
    float s = 0.f;
#pragma unroll 8
    for (int t = 0; t < 64; t++) s += part[pb + (size_t)t * 4160 + j];
    out[((size_t)layer * 128 + bh) * 4160 + j] = s;
}

// ===========================================================================
// Generic small SGEMM (64x64 tiles) with fused epilogues, M,N,K mult of 64/16
// modes: 0 none | 1 bias+relu | 2 bias+relu+pos | 3 relu(x*scale)+STAB | 4 +aux
// ===========================================================================
__global__ __launch_bounds__(256) void k_sgemm64(
    const float* __restrict__ A, const float* __restrict__ B, float* __restrict__ C,
    int M, int N, int K, int mode, float scale,
    const float* __restrict__ bias, const float* __restrict__ aux)
{
    __shared__ float As[16 * 68];
    __shared__ float Bs[16 * 68];
    int tid = threadIdx.x;
    int m0 = blockIdx.y * 64, n0 = blockIdx.x * 64;
    int lm = tid >> 2, lk4 = (tid & 3) * 4;
    int lbk = tid >> 4, lbc = (tid & 15) * 4;
    int r0 = (tid >> 4) * 4, c0 = (tid & 15) * 4;
    float acc[4][4] = {};
    for (int kb = 0; kb < K; kb += 16) {
        float4 av = *(const float4*)(A + (size_t)(m0 + lm) * K + kb + lk4);
        As[(lk4 + 0) * 68 + lm] = av.x;
        As[(lk4 + 1) * 68 + lm] = av.y;
        As[(lk4 + 2) * 68 + lm] = av.z;
        As[(lk4 + 3) * 68 + lm] = av.w;
        *(float4*)&Bs[lbk * 68 + lbc] = *(const float4*)(B + (size_t)(kb + lbk) * N + n0 + lbc);
        __syncthreads();
#pragma unroll
        for (int kk = 0; kk < 16; kk++) {
            float4 a = *(float4*)&As[kk * 68 + r0];
            float4 b = *(float4*)&Bs[kk * 68 + c0];
            float ar[4] = {a.x, a.y, a.z, a.w};
            float br[4] = {b.x, b.y, b.z, b.w};
#pragma unroll
            for (int i = 0; i < 4; i++)
#pragma unroll
                for (int j = 0; j < 4; j++) acc[i][j] += ar[i] * br[j];
        }
        __syncthreads();
    }
#pragma unroll
    for (int i = 0; i < 4; i++) {
        int gm = m0 + r0 + i;
#pragma unroll
        for (int j = 0; j < 4; j++) {
            int gn = n0 + c0 + j;
            float v = acc[i][j];
            if (mode == 1)      v = fmaxf(v + bias[gn], 0.f);
            else if (mode == 2) v = fmaxf(v + bias[gn], 0.f) + aux[(size_t)(gm & 127) * N + gn];
            else if (mode == 3) v = fmaxf(v * scale, 0.f) + STABF;
            else if (mode == 4) v = v + aux[(size_t)gm * N + gn];
            C[(size_t)gm * N + gn] = v;
        }
    }
}

// ===========================================================================
// Obj FAVOR apply: out = (qp @ kv) / (qp . ksum), per (b,h)
// ===========================================================================
__global__ __launch_bounds__(256) void k_fav_apply(
    const float* __restrict__ qp, const float* __restrict__ kvg,
    float* __restrict__ fav, int layer)
{
    __shared__ float kvs[4096];
    __shared__ float kss[64];
    __shared__ float den[128];
    int h = blockIdx.x, b = blockIdx.y, tid = threadIdx.x;
    size_t base = ((size_t)layer * 128 + b * 16 + h) * 4160;
#pragma unroll
    for (int i = 0; i < 16; i++) kvs[tid + i * 256] = kvg[base + tid + i * 256];
    if (tid < 64) kss[tid] = kvg[base + 4096 + tid];
    __syncthreads();
    if (tid < 128) {
        const float* qr = qp + ((size_t)(b * 128 + tid)) * 1024 + h * 64;
        float s = 0.f;
#pragma unroll
        for (int m = 0; m < 64; m++) s += qr[m] * kss[m];
        den[tid] = s;
    }
    __syncthreads();
    int t = tid >> 1, d0 = (tid & 1) * 32;
    const float* qr = qp + ((size_t)(b * 128 + t)) * 1024 + h * 64;
    float a[32] = {};
    for (int m = 0; m < 64; m++) {
        float qv = qr[m];
#pragma unroll
        for (int j = 0; j < 32; j++) a[j] += qv * kvs[m * 64 + d0 + j];
    }
    float inv = 1.f / den[t];
    float* op = fav + ((size_t)(b * 128 + t)) * 1024 + h * 64 + d0;
#pragma unroll
    for (int j = 0; j < 32; j++) op[j] = a[j] * inv;
}

// ===========================================================================
// Row LayerNorm over 1024 channels; o = LN(a [+ b2])
// ===========================================================================
__global__ __launch_bounds__(256) void k_ln1024(
    const float* __restrict__ a, const float* __restrict__ b2,
    float* __restrict__ o, const float* __restrict__ g, const float* __restrict__ be)
{
    __shared__ float red[256];
    int row = blockIdx.x, tid = threadIdx.x;
    const float* ap = a + (size_t)row * 1024;
    float v[4];
    float s = 0.f;
#pragma unroll
    for (int j = 0; j < 4; j++) {
        int c = tid + j * 256;
        float x = ap[c];
        if (b2) x += b2[(size_t)row * 1024 + c];
        v[j] = x; s += x;
    }
    red[tid] = s; __syncthreads();
    for (int off = 128; off; off >>= 1) {
        if (tid < off) red[tid] += red[tid + off];
        __syncthreads();
    }
    float mu = red[0] * (1.f / 1024.f);
    __syncthreads();
    float s2 = 0.f;
#pragma unroll
    for (int j = 0; j < 4; j++) { float d = v[j] - mu; s2 += d * d; }
    red[tid] = s2; __syncthreads();
    for (int off = 128; off; off >>= 1) {
        if (tid < off) red[tid] += red[tid + off];
        __syncthreads();
    }
    float rs = rsqrtf(red[0] * (1.f / 1024.f) + LNEPS);
    float* op = o + (size_t)row * 1024;
#pragma unroll
    for (int j = 0; j < 4; j++) {
        int c = tid + j * 256;
        op[c] = (v[j] - mu) * rs * g[c] + be[c];
    }
}

// ===========================================================================
// Launch
// ===========================================================================
extern "C" void kernel_launch(void* const* d_in, const int* in_sizes, int n_in,
                              void* d_out, int out_size)
{
    const float* obj_inputs  = (const float*)d_in[0];
    const float* road_inputs = (const float*)d_in[1];
    const float* rg_dense_W  = (const float*)d_in[2];
    const float* rg_dense_b  = (const float*)d_in[3];
    const float* rg_qkv_W    = (const float*)d_in[4];
    const float* rg_qkv_b    = (const float*)d_in[5];
    const float* rg_Wq       = (const float*)d_in[6];
    const float* rg_Wk       = (const float*)d_in[7];
    const float* rg_Wv       = (const float*)d_in[8];
    const float* rg_Wo       = (const float*)d_in[9];
    const float* rg_ln_g     = (const float*)d_in[10];
    const float* rg_ln_b     = (const float*)d_in[11];
    const float* rg_fc_W     = (const float*)d_in[12];
    const float* rg_fc_b     = (const float*)d_in[13];
    const float* rg_out_W    = (const float*)d_in[14];
    const float* rg_out_b    = (const float*)d_in[15];
    const float* dense_W     = (const float*)d_in[16];
    const float* dense_b     = (const float*)d_in[17];
    const float* pos_emb     = (const float*)d_in[18];
    const float* Wq          = (const float*)d_in[19];
    const float* Wk          = (const float*)d_in[20];
    const float* Wv          = (const float*)d_in[21];
    const float* Wo          = (const float*)d_in[22];
    const float* ln_g        = (const float*)d_in[23];
    const float* ln_b        = (const float*)d_in[24];
    const float* fc_W        = (const float*)d_in[25];
    const float* fc_b        = (const float*)d_in[26];
    float* out = (float*)d_out;

    float* base = nullptr;
    cudaGetSymbolAddress((void**)&base, g_s);
    float* roadx  = base + OFF_ROADX;
    float* roadq  = base + OFF_ROADQ;
    float* rpart  = base + OFF_RPART;
    float* rgkv   = base + OFF_RGKV;
    float* rgout  = base + OFF_RGOUT;
    float* kvpart = base + OFF_KVPART;
    float* objkv  = base + OFF_OBJKV;
    float* xo     = base + OFF_XO;
    float* qpbuf  = base + OFF_QP;
    float* favb   = base + OFF_FAV;
    float* attnb  = base + OFF_ATTN;
    float* nbuf   = base + OFF_N;
    float* ybuf   = base + OFF_Y;

    cudaFuncSetAttribute(k_kv_fused, cudaFuncAttributeMaxDynamicSharedMemorySize, 66048);

    // ---- road stack ----
    k_road_dense<<<256, 256>>>(road_inputs, rg_dense_W, rg_dense_b, roadx);
    for (int i = 0; i < 2; i++) {
        k_road_favA<<<256, 256>>>(roadx, roadq, rg_qkv_W, rg_qkv_b,
                                  rg_Wk + i * 256, rg_Wv + i * 256, rpart);
        k_road_reduce<<<8, 80>>>(rpart, rgkv);
        k_road_favB<<<256, 256>>>(roadx, roadq, rg_Wq + i * 256, rg_Wo + i * 256,
                                  rgkv, rg_ln_g + i * 16, rg_ln_b + i * 16,
                                  rg_fc_W + i * 256, rg_fc_b + i * 16);
    }
    k_rg_expand<<<4096, 256>>>(roadx, rg_out_W, rg_out_b, rgout);

    // ---- heavy fused K/V + FAVOR reduction (both layers) ----
    k_kv_fused<<<dim3(16, 512, 2), 256, 66048>>>(rgout, Wk, Wv, kvpart);
    k_kv_reduce<<<dim3(17, 128, 2), 256>>>(kvpart, objkv);

    // ---- obj stack ----
    k_sgemm64<<<dim3(16, 16), 256>>>(obj_inputs, dense_W, xo,
                                     1024, 1024, 512, 2, 0.f, dense_b, pos_emb);
    for (int i = 0; i < 2; i++) {
        k_sgemm64<<<dim3(16, 16), 256>>>(xo, Wq + (size_t)i * 1048576, qpbuf,
                                         1024, 1024, 1024, 3, NORM_OBJ, nullptr, nullptr);
        k_fav_apply<<<dim3(16, 8), 256>>>(qpbuf, objkv, favb, i);
        k_sgemm64<<<dim3(16, 16), 256>>>(favb, Wo + (size_t)i * 1048576, attnb,
                                         1024, 1024, 1024, 4, 0.f, nullptr, xo);
        k_ln1024<<<1024, 256>>>(attnb, nullptr, nbuf, ln_g + i * 1024, ln_b + i * 1024);
        k_sgemm64<<<dim3(16, 16), 256>>>(nbuf, fc_W + (size_t)i * 1048576, ybuf,
                                         1024, 1024, 1024, 1, 0.f, fc_b + i * 1024, nullptr);
        k_ln1024<<<1024, 256>>>(nbuf, ybuf, (i == 0) ? xo : out,
                                ln_g + i * 1024, ln_b + i * 1024);
    }
}

// round 6
// speedup vs baseline: 1.9700x; 1.8629x over previous
#include <cuda_runtime.h>
#include <cuda_bf16.h>
#include <mma.h>
#include <cstdint>
#include <cstddef>

using namespace nvcuda;

#define NORM_RG   0.70710678118654752f
#define NORM_OBJ  0.35355339059327376f
#define STABF     0.001f
#define LNEPS     0.001f

// ---------------- scratch layout (float offsets) ----------------
static constexpr size_t OFF_ROADX  = 0;                        // 65536*16
static constexpr size_t OFF_ROADQ  = OFF_ROADX  + 1048576;
static constexpr size_t OFF_RPART  = OFF_ROADQ  + 1048576;     // 256*80
static constexpr size_t OFF_RGKV   = OFF_RPART  + 20480;       // 8*80
static constexpr size_t OFF_AH     = OFF_RGKV   + 640;         // 65536*1024 bf16
static constexpr size_t OFF_AL     = OFF_AH     + 33554432;
static constexpr size_t OFF_BH     = OFF_AL     + 33554432;    // 2*16*128*1024 bf16
static constexpr size_t OFF_BL     = OFF_BH     + 2097152;
static constexpr size_t OFF_KVPART = OFF_BL     + 2097152;     // 2*8*16*64*4160
static constexpr size_t OFF_OBJKV  = OFF_KVPART + 68157440;    // 2*128*4160
static constexpr size_t OFF_XO     = OFF_OBJKV  + 1064960;
static constexpr size_t OFF_QP     = OFF_XO     + 1048576;
static constexpr size_t OFF_FAV    = OFF_QP     + 1048576;
static constexpr size_t OFF_ATTN   = OFF_FAV    + 1048576;
static constexpr size_t OFF_N      = OFF_ATTN   + 1048576;
static constexpr size_t OFF_Y      = OFF_N      + 1048576;
static constexpr size_t SCRATCH_FLOATS = OFF_Y + 1048576;

__device__ float g_s[SCRATCH_FLOATS];

// =================== road stack (verified R3/R4) ===================
__global__ __launch_bounds__(256) void k_road_dense(
    const float* __restrict__ rin, const float* __restrict__ W,
    const float* __restrict__ b, float* __restrict__ xout)
{
    __shared__ float Ws[128], bs[16];
    int tid = threadIdx.x;
    if (tid < 128) Ws[tid] = W[tid];
    if (tid < 16)  bs[tid] = b[tid];
    __syncthreads();
    size_t tok = (size_t)blockIdx.x * 256 + tid;
    const float4* rp = (const float4*)(rin + tok * 8);
    float4 a0 = rp[0], a1 = rp[1];
    float x[8] = {a0.x, a0.y, a0.z, a0.w, a1.x, a1.y, a1.z, a1.w};
    float o[16];
#pragma unroll
    for (int c = 0; c < 16; c++) {
        float s = bs[c];
#pragma unroll
        for (int d = 0; d < 8; d++) s += x[d] * Ws[d * 16 + c];
        o[c] = fmaxf(s, 0.f);
    }
    float4* op = (float4*)(xout + tok * 16);
    op[0] = make_float4(o[0], o[1], o[2], o[3]);
    op[1] = make_float4(o[4], o[5], o[6], o[7]);
    op[2] = make_float4(o[8], o[9], o[10], o[11]);
    op[3] = make_float4(o[12], o[13], o[14], o[15]);
}

__global__ __launch_bounds__(256) void k_road_favA(
    const float* __restrict__ xin, float* __restrict__ qout,
    const float* __restrict__ qkvW, const float* __restrict__ qkvb,
    const float* __restrict__ Wk, const float* __restrict__ Wv,
    float* __restrict__ part)
{
    __shared__ float W16[256], b16[16], Wks[256], Wvs[256];
    __shared__ float wred[8 * 80];
    int tid = threadIdx.x;
    W16[tid] = qkvW[(tid >> 4) * 48 + (tid & 15)];
    Wks[tid] = Wk[tid];
    Wvs[tid] = Wv[tid];
    if (tid < 16) b16[tid] = qkvb[tid];
    __syncthreads();
    size_t tok = (size_t)blockIdx.x * 256 + tid;
    const float4* xp = (const float4*)(xin + tok * 16);
    float4 x0 = xp[0], x1 = xp[1], x2 = xp[2], x3 = xp[3];
    float x[16] = {x0.x, x0.y, x0.z, x0.w, x1.x, x1.y, x1.z, x1.w,
                   x2.x, x2.y, x2.z, x2.w, x3.x, x3.y, x3.z, x3.w};
    float q[16];
#pragma unroll
    for (int c = 0; c < 16; c++) {
        float s = b16[c];
#pragma unroll
        for (int d = 0; d < 16; d++) s += x[d] * W16[d * 16 + c];
        q[c] = fmaxf(s, 0.f);
    }
    float4* qo = (float4*)(qout + tok * 16);
    qo[0] = make_float4(q[0], q[1], q[2], q[3]);
    qo[1] = make_float4(q[4], q[5], q[6], q[7]);
    qo[2] = make_float4(q[8], q[9], q[10], q[11]);
    qo[3] = make_float4(q[12], q[13], q[14], q[15]);
    float kp[16], vh[16];
#pragma unroll
    for (int j = 0; j < 16; j++) {
        float sk = 0.f, sv = 0.f;
#pragma unroll
        for (int d = 0; d < 16; d++) {
            sk += q[d] * Wks[d * 16 + j];
            sv += q[d] * Wvs[d * 16 + j];
        }
        kp[j] = fmaxf(sk * NORM_RG, 0.f) + STABF;
        vh[j] = sv;
    }
    int lane = tid & 31, w = tid >> 5;
#pragma unroll
    for (int i = 0; i < 64; i++) {
        int hm = i >> 2;
        float v = kp[hm] * vh[(hm & 12) | (i & 3)];
#pragma unroll
        for (int off = 16; off > 0; off >>= 1) v += __shfl_down_sync(0xffffffffu, v, off);
        if (lane == 0) wred[w * 80 + i] = v;
    }
#pragma unroll
    for (int i = 0; i < 16; i++) {
        float v = kp[i];
#pragma unroll
        for (int off = 16; off > 0; off >>= 1) v += __shfl_down_sync(0xffffffffu, v, off);
        if (lane == 0) wred[w * 80 + 64 + i] = v;
    }
    __syncthreads();
    if (tid < 80) {
        float s = 0.f;
#pragma unroll
        for (int w2 = 0; w2 < 8; w2++) s += wred[w2 * 80 + tid];
        part[(size_t)blockIdx.x * 80 + tid] = s;
    }
}

__global__ void k_road_reduce(const float* __restrict__ part, float* __restrict__ kvout)
{
    int b = blockIdx.x, tid = threadIdx.x;
    float s = 0.f;
    for (int k = 0; k < 32; k++) s += part[(size_t)(b * 32 + k) * 80 + tid];
    kvout[(size_t)b * 80 + tid] = s;
}

__global__ __launch_bounds__(256) void k_road_favB(
    float* __restrict__ x, const float* __restrict__ qbuf,
    const float* __restrict__ Wq, const float* __restrict__ Wo,
    const float* __restrict__ kvg,
    const float* __restrict__ lng, const float* __restrict__ lnb,
    const float* __restrict__ fcW, const float* __restrict__ fcb)
{
    __shared__ float Wqs[256], Wos[256], fcWs[256];
    __shared__ float fcbs[16], gs[16], bbs[16], kvs[64], kss[16];
    int tid = threadIdx.x;
    Wqs[tid] = Wq[tid];
    Wos[tid] = Wo[tid];
    fcWs[tid] = fcW[tid];
    if (tid < 16) { fcbs[tid] = fcb[tid]; gs[tid] = lng[tid]; bbs[tid] = lnb[tid]; }
    int b = blockIdx.x >> 5;
    if (tid < 64) kvs[tid] = kvg[(size_t)b * 80 + tid];
    if (tid < 16) kss[tid] = kvg[(size_t)b * 80 + 64 + tid];
    __syncthreads();
    size_t tok = (size_t)blockIdx.x * 256 + tid;
    const float4* qp4 = (const float4*)(qbuf + tok * 16);
    float4 q0 = qp4[0], q1 = qp4[1], q2 = qp4[2], q3 = qp4[3];
    float q[16] = {q0.x, q0.y, q0.z, q0.w, q1.x, q1.y, q1.z, q1.w,
                   q2.x, q2.y, q2.z, q2.w, q3.x, q3.y, q3.z, q3.w};
    float qp[16];
#pragma unroll
    for (int j = 0; j < 16; j++) {
        float s = 0.f;
#pragma unroll
        for (int d = 0; d < 16; d++) s += q[d] * Wqs[d * 16 + j];
        qp[j] = fmaxf(s * NORM_RG, 0.f) + STABF;
    }
    float outv[16];
#pragma unroll
    for (int h = 0; h < 4; h++) {
        float den = 0.f;
#pragma unroll
        for (int m = 0; m < 4; m++) den += qp[h * 4 + m] * kss[h * 4 + m];
        float inv = 1.f / den;
#pragma unroll
        for (int d = 0; d < 4; d++) {
            float nu = 0.f;
#pragma unroll
            for (int m = 0; m < 4; m++) nu += qp[h * 4 + m] * kvs[(h * 4 + m) * 4 + d];
            outv[h * 4 + d] = nu * inv;
        }
    }
    float attn[16];
#pragma unroll
    for (int e = 0; e < 16; e++) {
        float s = 0.f;
#pragma unroll
        for (int j = 0; j < 16; j++) s += outv[j] * Wos[j * 16 + e];
        attn[e] = s;
    }
    const float4* xp = (const float4*)(x + tok * 16);
    float4 x0 = xp[0], x1 = xp[1], x2 = xp[2], x3 = xp[3];
    float xv[16] = {x0.x, x0.y, x0.z, x0.w, x1.x, x1.y, x1.z, x1.w,
                    x2.x, x2.y, x2.z, x2.w, x3.x, x3.y, x3.z, x3.w};
    float t1[16];
#pragma unroll
    for (int c = 0; c < 16; c++) t1[c] = attn[c] + xv[c];
    float mu = 0.f;
#pragma unroll
    for (int c = 0; c < 16; c++) mu += t1[c];
    mu *= (1.f / 16.f);
    float var = 0.f;
#pragma unroll
    for (int c = 0; c < 16; c++) { float d = t1[c] - mu; var += d * d; }
    var *= (1.f / 16.f);
    float rs = rsqrtf(var + LNEPS);
    float nn[16];
#pragma unroll
    for (int c = 0; c < 16; c++) nn[c] = (t1[c] - mu) * rs * gs[c] + bbs[c];
    float y[16];
#pragma unroll
    for (int c = 0; c < 16; c++) {
        float s = fcbs[c];
#pragma unroll
        for (int d = 0; d < 16; d++) s += nn[d] * fcWs[d * 16 + c];
        y[c] = fmaxf(s, 0.f);
    }
    float t2[16];
#pragma unroll
    for (int c = 0; c < 16; c++) t2[c] = nn[c] + y[c];
    mu = 0.f;
#pragma unroll
    for (int c = 0; c < 16; c++) mu += t2[c];
    mu *= (1.f / 16.f);
    var = 0.f;
#pragma unroll
    for (int c = 0; c < 16; c++) { float d = t2[c] - mu; var += d * d; }
    var *= (1.f / 16.f);
    rs = rsqrtf(var + LNEPS);
    float o[16];
#pragma unroll
    for (int c = 0; c < 16; c++) o[c] = (t2[c] - mu) * rs * gs[c] + bbs[c];
    float4* op = (float4*)(x + tok * 16);
    op[0] = make_float4(o[0], o[1], o[2], o[3]);
    op[1] = make_float4(o[4], o[5], o[6], o[7]);
    op[2] = make_float4(o[8], o[9], o[10], o[11]);
    op[3] = make_float4(o[12], o[13], o[14], o[15]);
}

// rg_out = relu(x16 @ W + b), emitted split into bf16 hi/lo
__global__ __launch_bounds__(256) void k_rg_expand_split(
    const float* __restrict__ x, const float* __restrict__ W,
    const float* __restrict__ b, __nv_bfloat16* __restrict__ AH,
    __nv_bfloat16* __restrict__ AL)
{
    __shared__ float xs[256];
    int tid = threadIdx.x;
    size_t tok0 = (size_t)blockIdx.x * 16;
    xs[tid] = x[tok0 * 16 + tid];
    __syncthreads();
    int c0 = tid * 4;
    float4 wv[16];
#pragma unroll
    for (int d = 0; d < 16; d++) wv[d] = *(const float4*)(W + d * 1024 + c0);
    float4 bb = *(const float4*)(b + c0);
#pragma unroll 4
    for (int tk = 0; tk < 16; tk++) {
        float4 a = bb;
#pragma unroll
        for (int d = 0; d < 16; d++) {
            float xv = xs[tk * 16 + d];
            a.x += xv * wv[d].x; a.y += xv * wv[d].y;
            a.z += xv * wv[d].z; a.w += xv * wv[d].w;
        }
        float o[4] = {fmaxf(a.x, 0.f), fmaxf(a.y, 0.f), fmaxf(a.z, 0.f), fmaxf(a.w, 0.f)};
        size_t base = (tok0 + tk) * 1024 + c0;
        __nv_bfloat16 hi[4], lo[4];
#pragma unroll
        for (int i = 0; i < 4; i++) {
            hi[i] = __float2bfloat16(o[i]);
            lo[i] = __float2bfloat16(o[i] - __bfloat162float(hi[i]));
        }
        *(__nv_bfloat162*)(AH + base)     = __nv_bfloat162{hi[0], hi[1]};
        *(__nv_bfloat162*)(AH + base + 2) = __nv_bfloat162{hi[2], hi[3]};
        *(__nv_bfloat162*)(AL + base)     = __nv_bfloat162{lo[0], lo[1]};
        *(__nv_bfloat162*)(AL + base + 2) = __nv_bfloat162{lo[2], lo[3]};
    }
}

// pack Wk|Wv (N,H,h,d) -> B [layer][h][n=128][k=1024] bf16 hi/lo (K-major rows)
__global__ void k_wpack(const float* __restrict__ Wk, const float* __restrict__ Wv,
                        __nv_bfloat16* __restrict__ BH, __nv_bfloat16* __restrict__ BL)
{
    int blk = blockIdx.x;
    int n = blk & 127, hh = (blk >> 7) & 15, l = blk >> 11;
    const float* src = (n < 64 ? Wk : Wv) + (size_t)l * 1048576 + hh * 64 + (n & 63);
    size_t dst = (size_t)blk * 1024;
    int k0 = threadIdx.x * 4;
#pragma unroll
    for (int i = 0; i < 4; i++) {
        int k = k0 + i;
        float v = src[(size_t)k * 1024];
        __nv_bfloat16 hi = __float2bfloat16(v);
        BH[dst + k] = hi;
        BL[dst + k] = __float2bfloat16(v - __bfloat162float(hi));
    }
}

// ============ heavy kernel: WMMA bf16x3 K/V projection + FAVOR reduction ====
// grid (h=16, tile=512, layer=2), 256 thr, dyn smem 73728
__global__ __launch_bounds__(256) void k_kv_mma(
    const __nv_bfloat16* __restrict__ AH, const __nv_bfloat16* __restrict__ AL,
    const __nv_bfloat16* __restrict__ BH, const __nv_bfloat16* __restrict__ BL,
    float* __restrict__ part)
{
    extern __shared__ char sm[];
    __nv_bfloat16* Ah = (__nv_bfloat16*)sm;        // [128][72]
    __nv_bfloat16* Al = Ah + 128 * 72;
    __nv_bfloat16* Bh = Al + 128 * 72;
    __nv_bfloat16* Bl = Bh + 128 * 72;
    int h = blockIdx.x, tile = blockIdx.y, layer = blockIdx.z;
    int tid = threadIdx.x, wid = tid >> 5;
    int wm = wid & 3, wn = wid >> 2;               // 4x2 warps: 32 rows x 64 cols

    size_t abase = (size_t)tile * 128 * 1024;
    size_t bbase = (size_t)(layer * 16 + h) * 128 * 1024;

    wmma::fragment<wmma::accumulator, 16, 16, 16, float> acc[2][4];
#pragma unroll
    for (int i = 0; i < 2; i++)
#pragma unroll
        for (int j = 0; j < 4; j++) wmma::fill_fragment(acc[i][j], 0.f);

    for (int kb = 0; kb < 1024; kb += 64) {
#pragma unroll
        for (int it = 0; it < 16; it++) {
            int gslot = it * 256 + tid;
            int t = gslot >> 10;
            int slot = gslot & 1023;
            int row = slot >> 3, ko = slot & 7;
            const __nv_bfloat16* src =
                (t == 0 ? AH + abase : t == 1 ? AL + abase : t == 2 ? BH + bbase : BL + bbase)
                + (size_t)row * 1024 + kb + ko * 8;
            uint4 v = *(const uint4*)src;
            __nv_bfloat16* dst = (t == 0 ? Ah : t == 1 ? Al : t == 2 ? Bh : Bl) + row * 72 + ko * 8;
            *(uint4*)dst = v;
        }
        __syncthreads();
#pragma unroll
        for (int ks = 0; ks < 4; ks++) {
            int k0 = ks * 16;
            wmma::fragment<wmma::matrix_a, 16, 16, 16, __nv_bfloat16, wmma::row_major> fah[2], fal[2];
#pragma unroll
            for (int m = 0; m < 2; m++) {
                wmma::load_matrix_sync(fah[m], Ah + (wm * 32 + m * 16) * 72 + k0, 72);
                wmma::load_matrix_sync(fal[m], Al + (wm * 32 + m * 16) * 72 + k0, 72);
            }
#pragma unroll
            for (int n = 0; n < 4; n++) {
                wmma::fragment<wmma::matrix_b, 16, 16, 16, __nv_bfloat16, wmma::col_major> fbh, fbl;
                wmma::load_matrix_sync(fbh, Bh + (wn * 64 + n * 16) * 72 + k0, 72);
                wmma::load_matrix_sync(fbl, Bl + (wn * 64 + n * 16) * 72 + k0, 72);
#pragma unroll
                for (int m = 0; m < 2; m++) {
                    wmma::mma_sync(acc[m][n], fah[m], fbh, acc[m][n]);
                    wmma::mma_sync(acc[m][n], fah[m], fbl, acc[m][n]);
                    wmma::mma_sync(acc[m][n], fal[m], fbh, acc[m][n]);
                }
            }
        }
        __syncthreads();
    }

    // stage D[128 tokens][128 cols] to SMEM (stride 132 floats)
    float* S = (float*)sm;
#pragma unroll
    for (int m = 0; m < 2; m++)
#pragma unroll
        for (int n = 0; n < 4; n++)
            wmma::store_matrix_sync(S + (size_t)(wm * 32 + m * 16) * 132 + wn * 64 + n * 16,
                                    acc[m][n], 132, wmma::mem_row_major);
    __syncthreads();

    // partial kv[m][d] = sum_s kp[s][m]*v[s][d], kp transform folded into reads
    int pm0 = (tid >> 4) * 4, pd0 = (tid & 15) * 4;
    float r[4][4] = {};
    for (int s = 0; s < 128; s++) {
        const float* row = &S[(size_t)s * 132];
        float k0 = fmaxf(row[pm0]     * NORM_OBJ, 0.f) + STABF;
        float k1 = fmaxf(row[pm0 + 1] * NORM_OBJ, 0.f) + STABF;
        float k2 = fmaxf(row[pm0 + 2] * NORM_OBJ, 0.f) + STABF;
        float k3 = fmaxf(row[pm0 + 3] * NORM_OBJ, 0.f) + STABF;
        float v0 = row[64 + pd0], v1 = row[64 + pd0 + 1], v2 = row[64 + pd0 + 2], v3 = row[64 + pd0 + 3];
        r[0][0] += k0 * v0; r[0][1] += k0 * v1; r[0][2] += k0 * v2; r[0][3] += k0 * v3;
        r[1][0] += k1 * v0; r[1][1] += k1 * v1; r[1][2] += k1 * v2; r[1][3] += k1 * v3;
        r[2][0] += k2 * v0; r[2][1] += k2 * v1; r[2][2] += k2 * v2; r[2][3] += k2 * v3;
        r[3][0] += k3 * v0; r[3][1] += k3 * v1; r[3][2] += k3 * v2; r[3][3] += k3 * v3;
    }
    size_t pbase = ((((size_t)layer * 8 + (tile >> 6)) * 16 + h) * 64 + (tile & 63)) * 4160;
#pragma unroll
    for (int i = 0; i < 4; i++)
#pragma unroll
        for (int j = 0; j < 4; j++)
            part[pbase + (pm0 + i) * 64 + pd0 + j] = r[i][j];
    if (tid < 64) {
        float s = 0.f;
        for (int s2 = 0; s2 < 128; s2++)
            s += fmaxf(S[(size_t)s2 * 132 + tid] * NORM_OBJ, 0.f) + STABF;
        part[pbase + 4096 + tid] = s;
    }
}

__global__ void k_kv_reduce(const float* __restrict__ part, float* __restrict__ out)
{
    int j = blockIdx.x * 256 + threadIdx.x;
    if (j >= 4160) return;
    int bh = blockIdx.y, layer = blockIdx.z;
    size_t pb = ((size_t)layer * 128 + bh) * 64 * 4160;
    float s = 0.f;
#pragma unroll 8
    for (int t = 0; t < 64; t++) s += part[pb + (size_t)t * 4160 + j];
    out[((size_t)layer * 128 + bh) * 4160 + j] = s;
}

// =================== obj stack (verified R3/R4) ===================
__global__ __launch_bounds__(256) void k_sgemm64(
    const float* __restrict__ A, const float* __restrict__ B, float* __restrict__ C,
    int M, int N, int K, int mode, float scale,
    const float* __restrict__ bias, const float* __restrict__ aux)
{
    __shared__ float As[16 * 68];
    __shared__ float Bs[16 * 68];
    int tid = threadIdx.x;
    int m0 = blockIdx.y * 64, n0 = blockIdx.x * 64;
    int lm = tid >> 2, lk4 = (tid & 3) * 4;
    int lbk = tid >> 4, lbc = (tid & 15) * 4;
    int r0 = (tid >> 4) * 4, c0 = (tid & 15) * 4;
    float acc[4][4] = {};
    for (int kb = 0; kb < K; kb += 16) {
        float4 av = *(const float4*)(A + (size_t)(m0 + lm) * K + kb + lk4);
        As[(lk4 + 0) * 68 + lm] = av.x;
        As[(lk4 + 1) * 68 + lm] = av.y;
        As[(lk4 + 2) * 68 + lm] = av.z;
        As[(lk4 + 3) * 68 + lm] = av.w;
        *(float4*)&Bs[lbk * 68 + lbc] = *(const float4*)(B + (size_t)(kb + lbk) * N + n0 + lbc);
        __syncthreads();
#pragma unroll
        for (int kk = 0; kk < 16; kk++) {
            float4 a = *(float4*)&As[kk * 68 + r0];
            float4 b = *(float4*)&Bs[kk * 68 + c0];
            float ar[4] = {a.x, a.y, a.z, a.w};
            float br[4] = {b.x, b.y, b.z, b.w};
#pragma unroll
            for (int i = 0; i < 4; i++)
#pragma unroll
                for (int j = 0; j < 4; j++) acc[i][j] += ar[i] * br[j];
        }
        __syncthreads();
    }
#pragma unroll
    for (int i = 0; i < 4; i++) {
        int gm = m0 + r0 + i;
#pragma unroll
        for (int j = 0; j < 4; j++) {
            int gn = n0 + c0 + j;
            float v = acc[i][j];
            if (mode == 1)      v = fmaxf(v + bias[gn], 0.f);
            else if (mode == 2) v = fmaxf(v + bias[gn], 0.f) + aux[(size_t)(gm & 127) * N + gn];
            else if (mode == 3) v = fmaxf(v * scale, 0.f) + STABF;
            else if (mode == 4) v = v + aux[(size_t)gm * N + gn];
            C[(size_t)gm * N + gn] = v;
        }
    }
}

__global__ __launch_bounds__(256) void k_fav_apply(
    const float* __restrict__ qp, const float* __restrict__ kvg,
    float* __restrict__ fav, int layer)
{
    __shared__ float kvs[4096];
    __shared__ float kss[64];
    __shared__ float den[128];
    int h = blockIdx.x, b = blockIdx.y, tid = threadIdx.x;
    size_t base = ((size_t)layer * 128 + b * 16 + h) * 4160;
#pragma unroll
    for (int i = 0; i < 16; i++) kvs[tid + i * 256] = kvg[base + tid + i * 256];
    if (tid < 64) kss[tid] = kvg[base + 4096 + tid];
    __syncthreads();
    if (tid < 128) {
        const float* qr = qp + ((size_t)(b * 128 + tid)) * 1024 + h * 64;
        float s = 0.f;
#pragma unroll
        for (int m = 0; m < 64; m++) s += qr[m] * kss[m];
        den[tid] = s;
    }
    __syncthreads();
    int t = tid >> 1, d0 = (tid & 1) * 32;
    const float* qr = qp + ((size_t)(b * 128 + t)) * 1024 + h * 64;
    float a[32] = {};
    for (int m = 0; m < 64; m++) {
        float qv = qr[m];
#pragma unroll
        for (int j = 0; j < 32; j++) a[j] += qv * kvs[m * 64 + d0 + j];
    }
    float inv = 1.f / den[t];
    float* op = fav + ((size_t)(b * 128 + t)) * 1024 + h * 64 + d0;
#pragma unroll
    for (int j = 0; j < 32; j++) op[j] = a[j] * inv;
}

__global__ __launch_bounds__(256) void k_ln1024(
    const float* __restrict__ a, const float* __restrict__ b2,
    float* __restrict__ o, const float* __restrict__ g, const float* __restrict__ be)
{
    __shared__ float red[256];
    int row = blockIdx.x, tid = threadIdx.x;
    const float* ap = a + (size_t)row * 1024;
    float v[4];
    float s = 0.f;
#pragma unroll
    for (int j = 0; j < 4; j++) {
        int c = tid + j * 256;
        float x = ap[c];
        if (b2) x += b2[(size_t)row * 1024 + c];
        v[j] = x; s += x;
    }
    red[tid] = s; __syncthreads();
    for (int off = 128; off; off >>= 1) {
        if (tid < off) red[tid] += red[tid + off];
        __syncthreads();
    }
    float mu = red[0] * (1.f / 1024.f);
    __syncthreads();
    float s2 = 0.f;
#pragma unroll
    for (int j = 0; j < 4; j++) { float d = v[j] - mu; s2 += d * d; }
    red[tid] = s2; __syncthreads();
    for (int off = 128; off; off >>= 1) {
        if (tid < off) red[tid] += red[tid + off];
        __syncthreads();
    }
    float rs = rsqrtf(red[0] * (1.f / 1024.f) + LNEPS);
    float* op = o + (size_t)row * 1024;
#pragma unroll
    for (int j = 0; j < 4; j++) {
        int c = tid + j * 256;
        op[c] = (v[j] - mu) * rs * g[c] + be[c];
    }
}

// =================== launch ===================
extern "C" void kernel_launch(void* const* d_in, const int* in_sizes, int n_in,
                              void* d_out, int out_size)
{
    const float* obj_inputs  = (const float*)d_in[0];
    const float* road_inputs = (const float*)d_in[1];
    const float* rg_dense_W  = (const float*)d_in[2];
    const float* rg_dense_b  = (const float*)d_in[3];
    const float* rg_qkv_W    = (const float*)d_in[4];
    const float* rg_qkv_b    = (const float*)d_in[5];
    const float* rg_Wq       = (const float*)d_in[6];
    const float* rg_Wk       = (const float*)d_in[7];
    const float* rg_Wv       = (const float*)d_in[8];
    const float* rg_Wo       = (const float*)d_in[9];
    const float* rg_ln_g     = (const float*)d_in[10];
    const float* rg_ln_b     = (const float*)d_in[11];
    const float* rg_fc_W     = (const float*)d_in[12];
    const float* rg_fc_b     = (const float*)d_in[13];
    const float* rg_out_W    = (const float*)d_in[14];
    const float* rg_out_b    = (const float*)d_in[15];
    const float* dense_W     = (const float*)d_in[16];
    const float* dense_b     = (const float*)d_in[17];
    const float* pos_emb     = (const float*)d_in[18];
    const float* Wq          = (const float*)d_in[19];
    const float* Wk          = (const float*)d_in[20];
    const float* Wv          = (const float*)d_in[21];
    const float* Wo          = (const float*)d_in[22];
    const float* ln_g        = (const float*)d_in[23];
    const float* ln_b        = (const float*)d_in[24];
    const float* fc_W        = (const float*)d_in[25];
    const float* fc_b        = (const float*)d_in[26];
    float* out = (float*)d_out;

    float* base = nullptr;
    cudaGetSymbolAddress((void**)&base, g_s);
    float* roadx  = base + OFF_ROADX;
    float* roadq  = base + OFF_ROADQ;
    float* rpart  = base + OFF_RPART;
    float* rgkv   = base + OFF_RGKV;
    __nv_bfloat16* AH = (__nv_bfloat16*)(base + OFF_AH);
    __nv_bfloat16* AL = (__nv_bfloat16*)(base + OFF_AL);
    __nv_bfloat16* BH = (__nv_bfloat16*)(base + OFF_BH);
    __nv_bfloat16* BL = (__nv_bfloat16*)(base + OFF_BL);
    float* kvpart = base + OFF_KVPART;
    float* objkv  = base + OFF_OBJKV;
    float* xo     = base + OFF_XO;
    float* qpbuf  = base + OFF_QP;
    float* favb   = base + OFF_FAV;
    float* attnb  = base + OFF_ATTN;
    float* nbuf   = base + OFF_N;
    float* ybuf   = base + OFF_Y;

    cudaFuncSetAttribute(k_kv_mma, cudaFuncAttributeMaxDynamicSharedMemorySize, 73728);

    // road stack
    k_road_dense<<<256, 256>>>(road_inputs, rg_dense_W, rg_dense_b, roadx);
    for (int i = 0; i < 2; i++) {
        k_road_favA<<<256, 256>>>(roadx, roadq, rg_qkv_W, rg_qkv_b,
                                  rg_Wk + i * 256, rg_Wv + i * 256, rpart);
        k_road_reduce<<<8, 80>>>(rpart, rgkv);
        k_road_favB<<<256, 256>>>(roadx, roadq, rg_Wq + i * 256, rg_Wo + i * 256,
                                  rgkv, rg_ln_g + i * 16, rg_ln_b + i * 16,
                                  rg_fc_W + i * 256, rg_fc_b + i * 16);
    }
    k_wpack<<<4096, 256>>>(Wk, Wv, BH, BL);
    k_rg_expand_split<<<4096, 256>>>(roadx, rg_out_W, rg_out_b, AH, AL);

    // heavy tensor-core K/V + FAVOR reduction
    k_kv_mma<<<dim3(16, 512, 2), 256, 73728>>>(AH, AL, BH, BL, kvpart);
    k_kv_reduce<<<dim3(17, 128, 2), 256>>>(kvpart, objkv);

    // obj stack
    k_sgemm64<<<dim3(16, 16), 256>>>(obj_inputs, dense_W, xo,
                                     1024, 1024, 512, 2, 0.f, dense_b, pos_emb);
    for (int i = 0; i < 2; i++) {
        k_sgemm64<<<dim3(16, 16), 256>>>(xo, Wq + (size_t)i * 1048576, qpbuf,
                                         1024, 1024, 1024, 3, NORM_OBJ, nullptr, nullptr);
        k_fav_apply<<<dim3(16, 8), 256>>>(qpbuf, objkv, favb, i);
        k_sgemm64<<<dim3(16, 16), 256>>>(favb, Wo + (size_t)i * 1048576, attnb,
                                         1024, 1024, 1024, 4, 0.f, nullptr, xo);
        k_ln1024<<<1024, 256>>>(attnb, nullptr, nbuf, ln_g + i * 1024, ln_b + i * 1024);
        k_sgemm64<<<dim3(16, 16), 256>>>(nbuf, fc_W + (size_t)i * 1048576, ybuf,
                                         1024, 1024, 1024, 1, 0.f, fc_b + i * 1024, nullptr);
        k_ln1024<<<1024, 256>>>(nbuf, ybuf, (i == 0) ? xo : out,
                                ln_g + i * 1024, ln_b + i * 1024);
    }
}

// round 7
// speedup vs baseline: 3.3017x; 1.6760x over previous
#include <cuda_runtime.h>
#include <cuda_fp16.h>
#include <mma.h>
#include <cstdint>
#include <cstddef>

using namespace nvcuda;

#define NORM_RG   0.70710678118654752f
#define NORM_OBJ  0.35355339059327376f
#define STABF     0.001f
#define LNEPS     0.001f

// ---------------- scratch layout (float offsets) ----------------
static constexpr size_t OFF_ROADX  = 0;                        // 65536*16
static constexpr size_t OFF_ROADQ  = OFF_ROADX  + 1048576;
static constexpr size_t OFF_RPART  = OFF_ROADQ  + 1048576;     // 256*80
static constexpr size_t OFF_RGKV   = OFF_RPART  + 20480;       // 8*80
static constexpr size_t OFF_AH     = OFF_RGKV   + 640;         // 65536*1024 fp16
static constexpr size_t OFF_AL     = OFF_AH     + 33554432;
static constexpr size_t OFF_BH     = OFF_AL     + 33554432;    // 2*16*128*1024 fp16
static constexpr size_t OFF_BL     = OFF_BH     + 2097152;     // (unused now)
static constexpr size_t OFF_KVPART = OFF_BL     + 2097152;     // 2*8*16*64*4160
static constexpr size_t OFF_OBJKV  = OFF_KVPART + 68157440;    // 2*128*4160
static constexpr size_t OFF_XO     = OFF_OBJKV  + 1064960;
static constexpr size_t OFF_QP     = OFF_XO     + 1048576;
static constexpr size_t OFF_FAV    = OFF_QP     + 1048576;
static constexpr size_t OFF_ATTN   = OFF_FAV    + 1048576;
static constexpr size_t OFF_N      = OFF_ATTN   + 1048576;
static constexpr size_t OFF_Y      = OFF_N      + 1048576;
static constexpr size_t SCRATCH_FLOATS = OFF_Y + 1048576;

__device__ __align__(256) float g_s[SCRATCH_FLOATS];

// cp.async helpers (sm_80+, legal in compute_103)
#define CP16(dst, src) asm volatile("cp.async.ca.shared.global [%0], [%1], 16;" :: "r"(dst), "l"(src))
#define CPCOMMIT() asm volatile("cp.async.commit_group;" ::: "memory")
#define CPWAIT1() asm volatile("cp.async.wait_group 1;" ::: "memory")
#define CPWAIT0() asm volatile("cp.async.wait_group 0;" ::: "memory")

// =================== road stack (verified R3-R6) ===================
__global__ __launch_bounds__(256) void k_road_dense(
    const float* __restrict__ rin, const float* __restrict__ W,
    const float* __restrict__ b, float* __restrict__ xout)
{
    __shared__ float Ws[128], bs[16];
    int tid = threadIdx.x;
    if (tid < 128) Ws[tid] = W[tid];
    if (tid < 16)  bs[tid] = b[tid];
    __syncthreads();
    size_t tok = (size_t)blockIdx.x * 256 + tid;
    const float4* rp = (const float4*)(rin + tok * 8);
    float4 a0 = rp[0], a1 = rp[1];
    float x[8] = {a0.x, a0.y, a0.z, a0.w, a1.x, a1.y, a1.z, a1.w};
    float o[16];
#pragma unroll
    for (int c = 0; c < 16; c++) {
        float s = bs[c];
#pragma unroll
        for (int d = 0; d < 8; d++) s += x[d] * Ws[d * 16 + c];
        o[c] = fmaxf(s, 0.f);
    }
    float4* op = (float4*)(xout + tok * 16);
    op[0] = make_float4(o[0], o[1], o[2], o[3]);
    op[1] = make_float4(o[4], o[5], o[6], o[7]);
    op[2] = make_float4(o[8], o[9], o[10], o[11]);
    op[3] = make_float4(o[12], o[13], o[14], o[15]);
}

__global__ __launch_bounds__(256) void k_road_favA(
    const float* __restrict__ xin, float* __restrict__ qout,
    const float* __restrict__ qkvW, const float* __restrict__ qkvb,
    const float* __restrict__ Wk, const float* __restrict__ Wv,
    float* __restrict__ part)
{
    __shared__ float W16[256], b16[16], Wks[256], Wvs[256];
    __shared__ float wred[8 * 80];
    int tid = threadIdx.x;
    W16[tid] = qkvW[(tid >> 4) * 48 + (tid & 15)];
    Wks[tid] = Wk[tid];
    Wvs[tid] = Wv[tid];
    if (tid < 16) b16[tid] = qkvb[tid];
    __syncthreads();
    size_t tok = (size_t)blockIdx.x * 256 + tid;
    const float4* xp = (const float4*)(xin + tok * 16);
    float4 x0 = xp[0], x1 = xp[1], x2 = xp[2], x3 = xp[3];
    float x[16] = {x0.x, x0.y, x0.z, x0.w, x1.x, x1.y, x1.z, x1.w,
                   x2.x, x2.y, x2.z, x2.w, x3.x, x3.y, x3.z, x3.w};
    float q[16];
#pragma unroll
    for (int c = 0; c < 16; c++) {
        float s = b16[c];
#pragma unroll
        for (int d = 0; d < 16; d++) s += x[d] * W16[d * 16 + c];
        q[c] = fmaxf(s, 0.f);
    }
    float4* qo = (float4*)(qout + tok * 16);
    qo[0] = make_float4(q[0], q[1], q[2], q[3]);
    qo[1] = make_float4(q[4], q[5], q[6], q[7]);
    qo[2] = make_float4(q[8], q[9], q[10], q[11]);
    qo[3] = make_float4(q[12], q[13], q[14], q[15]);
    float kp[16], vh[16];
#pragma unroll
    for (int j = 0; j < 16; j++) {
        float sk = 0.f, sv = 0.f;
#pragma unroll
        for (int d = 0; d < 16; d++) {
            sk += q[d] * Wks[d * 16 + j];
            sv += q[d] * Wvs[d * 16 + j];
        }
        kp[j] = fmaxf(sk * NORM_RG, 0.f) + STABF;
        vh[j] = sv;
    }
    int lane = tid & 31, w = tid >> 5;
#pragma unroll
    for (int i = 0; i < 64; i++) {
        int hm = i >> 2;
        float v = kp[hm] * vh[(hm & 12) | (i & 3)];
#pragma unroll
        for (int off = 16; off > 0; off >>= 1) v += __shfl_down_sync(0xffffffffu, v, off);
        if (lane == 0) wred[w * 80 + i] = v;
    }
#pragma unroll
    for (int i = 0; i < 16; i++) {
        float v = kp[i];
#pragma unroll
        for (int off = 16; off > 0; off >>= 1) v += __shfl_down_sync(0xffffffffu, v, off);
        if (lane == 0) wred[w * 80 + 64 + i] = v;
    }
    __syncthreads();
    if (tid < 80) {
        float s = 0.f;
#pragma unroll
        for (int w2 = 0; w2 < 8; w2++) s += wred[w2 * 80 + tid];
        part[(size_t)blockIdx.x * 80 + tid] = s;
    }
}

__global__ void k_road_reduce(const float* __restrict__ part, float* __restrict__ kvout)
{
    int b = blockIdx.x, tid = threadIdx.x;
    float s = 0.f;
    for (int k = 0; k < 32; k++) s += part[(size_t)(b * 32 + k) * 80 + tid];
    kvout[(size_t)b * 80 + tid] = s;
}

__global__ __launch_bounds__(256) void k_road_favB(
    float* __restrict__ x, const float* __restrict__ qbuf,
    const float* __restrict__ Wq, const float* __restrict__ Wo,
    const float* __restrict__ kvg,
    const float* __restrict__ lng, const float* __restrict__ lnb,
    const float* __restrict__ fcW, const float* __restrict__ fcb)
{
    __shared__ float Wqs[256], Wos[256], fcWs[256];
    __shared__ float fcbs[16], gs[16], bbs[16], kvs[64], kss[16];
    int tid = threadIdx.x;
    Wqs[tid] = Wq[tid];
    Wos[tid] = Wo[tid];
    fcWs[tid] = fcW[tid];
    if (tid < 16) { fcbs[tid] = fcb[tid]; gs[tid] = lng[tid]; bbs[tid] = lnb[tid]; }
    int b = blockIdx.x >> 5;
    if (tid < 64) kvs[tid] = kvg[(size_t)b * 80 + tid];
    if (tid < 16) kss[tid] = kvg[(size_t)b * 80 + 64 + tid];
    __syncthreads();
    size_t tok = (size_t)blockIdx.x * 256 + tid;
    const float4* qp4 = (const float4*)(qbuf + tok * 16);
    float4 q0 = qp4[0], q1 = qp4[1], q2 = qp4[2], q3 = qp4[3];
    float q[16] = {q0.x, q0.y, q0.z, q0.w, q1.x, q1.y, q1.z, q1.w,
                   q2.x, q2.y, q2.z, q2.w, q3.x, q3.y, q3.z, q3.w};
    float qp[16];
#pragma unroll
    for (int j = 0; j < 16; j++) {
        float s = 0.f;
#pragma unroll
        for (int d = 0; d < 16; d++) s += q[d] * Wqs[d * 16 + j];
        qp[j] = fmaxf(s * NORM_RG, 0.f) + STABF;
    }
    float outv[16];
#pragma unroll
    for (int h = 0; h < 4; h++) {
        float den = 0.f;
#pragma unroll
        for (int m = 0; m < 4; m++) den += qp[h * 4 + m] * kss[h * 4 + m];
        float inv = 1.f / den;
#pragma unroll
        for (int d = 0; d < 4; d++) {
            float nu = 0.f;
#pragma unroll
            for (int m = 0; m < 4; m++) nu += qp[h * 4 + m] * kvs[(h * 4 + m) * 4 + d];
            outv[h * 4 + d] = nu * inv;
        }
    }
    float attn[16];
#pragma unroll
    for (int e = 0; e < 16; e++) {
        float s = 0.f;
#pragma unroll
        for (int j = 0; j < 16; j++) s += outv[j] * Wos[j * 16 + e];
        attn[e] = s;
    }
    const float4* xp = (const float4*)(x + tok * 16);
    float4 x0 = xp[0], x1 = xp[1], x2 = xp[2], x3 = xp[3];
    float xv[16] = {x0.x, x0.y, x0.z, x0.w, x1.x, x1.y, x1.z, x1.w,
                    x2.x, x2.y, x2.z, x2.w, x3.x, x3.y, x3.z, x3.w};
    float t1[16];
#pragma unroll
    for (int c = 0; c < 16; c++) t1[c] = attn[c] + xv[c];
    float mu = 0.f;
#pragma unroll
    for (int c = 0; c < 16; c++) mu += t1[c];
    mu *= (1.f / 16.f);
    float var = 0.f;
#pragma unroll
    for (int c = 0; c < 16; c++) { float d = t1[c] - mu; var += d * d; }
    var *= (1.f / 16.f);
    float rs = rsqrtf(var + LNEPS);
    float nn[16];
#pragma unroll
    for (int c = 0; c < 16; c++) nn[c] = (t1[c] - mu) * rs * gs[c] + bbs[c];
    float y[16];
#pragma unroll
    for (int c = 0; c < 16; c++) {
        float s = fcbs[c];
#pragma unroll
        for (int d = 0; d < 16; d++) s += nn[d] * fcWs[d * 16 + c];
        y[c] = fmaxf(s, 0.f);
    }
    float t2[16];
#pragma unroll
    for (int c = 0; c < 16; c++) t2[c] = nn[c] + y[c];
    mu = 0.f;
#pragma unroll
    for (int c = 0; c < 16; c++) mu += t2[c];
    mu *= (1.f / 16.f);
    var = 0.f;
#pragma unroll
    for (int c = 0; c < 16; c++) { float d = t2[c] - mu; var += d * d; }
    var *= (1.f / 16.f);
    rs = rsqrtf(var + LNEPS);
    float o[16];
#pragma unroll
    for (int c = 0; c < 16; c++) o[c] = (t2[c] - mu) * rs * gs[c] + bbs[c];
    float4* op = (float4*)(x + tok * 16);
    op[0] = make_float4(o[0], o[1], o[2], o[3]);
    op[1] = make_float4(o[4], o[5], o[6], o[7]);
    op[2] = make_float4(o[8], o[9], o[10], o[11]);
    op[3] = make_float4(o[12], o[13], o[14], o[15]);
}

// rg_out = relu(x16 @ W + b), emitted split into fp16 hi/lo
__global__ __launch_bounds__(256) void k_rg_expand_split(
    const float* __restrict__ x, const float* __restrict__ W,
    const float* __restrict__ b, __half* __restrict__ AH,
    __half* __restrict__ AL)
{
    __shared__ float xs[256];
    int tid = threadIdx.x;
    size_t tok0 = (size_t)blockIdx.x * 16;
    xs[tid] = x[tok0 * 16 + tid];
    __syncthreads();
    int c0 = tid * 4;
    float4 wv[16];
#pragma unroll
    for (int d = 0; d < 16; d++) wv[d] = *(const float4*)(W + d * 1024 + c0);
    float4 bb = *(const float4*)(b + c0);
#pragma unroll 4
    for (int tk = 0; tk < 16; tk++) {
        float4 a = bb;
#pragma unroll
        for (int d = 0; d < 16; d++) {
            float xv = xs[tk * 16 + d];
            a.x += xv * wv[d].x; a.y += xv * wv[d].y;
            a.z += xv * wv[d].z; a.w += xv * wv[d].w;
        }
        float o[4] = {fmaxf(a.x, 0.f), fmaxf(a.y, 0.f), fmaxf(a.z, 0.f), fmaxf(a.w, 0.f)};
        size_t base = (tok0 + tk) * 1024 + c0;
        __half hi[4], lo[4];
#pragma unroll
        for (int i = 0; i < 4; i++) {
            hi[i] = __float2half(o[i]);
            lo[i] = __float2half(o[i] - __half2float(hi[i]));
        }
        *(__half2*)(AH + base)     = __half2{hi[0], hi[1]};
        *(__half2*)(AH + base + 2) = __half2{hi[2], hi[3]};
        *(__half2*)(AL + base)     = __half2{lo[0], lo[1]};
        *(__half2*)(AL + base + 2) = __half2{lo[2], lo[3]};
    }
}

// pack Wk|Wv (N,H,h,d) -> B [layer][h][n=128][k=1024] fp16 (K-major rows)
__global__ void k_wpack(const float* __restrict__ Wk, const float* __restrict__ Wv,
                        __half* __restrict__ BH)
{
    int blk = blockIdx.x;
    int n = blk & 127, hh = (blk >> 7) & 15, l = blk >> 11;
    const float* src = (n < 64 ? Wk : Wv) + (size_t)l * 1048576 + hh * 64 + (n & 63);
    size_t dst = (size_t)blk * 1024;
    int k0 = threadIdx.x * 4;
#pragma unroll
    for (int i = 0; i < 4; i++) {
        int k = k0 + i;
        BH[dst + k] = __float2half(src[(size_t)k * 1024]);
    }
}

// ====== heavy kernel: WMMA fp16x2 K/V projection + FAVOR reduction ======
// grid (h=16, tile=512, layer=2), 256 thr, dyn smem 110592 (2 stages)
__global__ __launch_bounds__(256) void k_kv_mma(
    const __half* __restrict__ AH, const __half* __restrict__ AL,
    const __half* __restrict__ BH, float* __restrict__ part)
{
    extern __shared__ char sm[];
    int h = blockIdx.x, tile = blockIdx.y, layer = blockIdx.z;
    int tid = threadIdx.x, wid = tid >> 5;
    int wm = wid & 3, wn = wid >> 2;               // 4x2 warps: 32 rows x 64 cols
    size_t abase = (size_t)tile * 128 * 1024;
    size_t bbase = (size_t)(layer * 16 + h) * 128 * 1024;
    uint32_t smb = (uint32_t)__cvta_generic_to_shared(sm);

    wmma::fragment<wmma::accumulator, 16, 16, 16, float> acc[2][4];
#pragma unroll
    for (int i = 0; i < 2; i++)
#pragma unroll
        for (int j = 0; j < 4; j++) wmma::fill_fragment(acc[i][j], 0.f);

    // stage layout: [stage 0|1] x {Ah[128][72], Al[128][72], Bh[128][72]} fp16
    // fill stage st with k-block kb via cp.async (3072 x 16B chunks / 256 thr)
    auto fill = [&](int st, int kb) {
#pragma unroll
        for (int it = 0; it < 12; it++) {
            int gslot = it * 256 + tid;
            int t = gslot >> 10, slot = gslot & 1023;
            int row = slot >> 3, ko = slot & 7;
            const __half* src =
                (t == 0 ? AH + abase : t == 1 ? AL + abase : BH + bbase)
                + (size_t)row * 1024 + kb + ko * 8;
            uint32_t dst = smb + st * 55296 + t * 18432 + row * 144 + ko * 16;
            CP16(dst, src);
        }
        CPCOMMIT();
    };

    fill(0, 0);
    for (int ib = 0; ib < 16; ib++) {
        if (ib < 15) { fill((ib + 1) & 1, (ib + 1) * 64); CPWAIT1(); }
        else         { CPWAIT0(); }
        __syncthreads();
        const __half* Ah = (const __half*)(sm + (ib & 1) * 55296);
        const __half* Al = Ah + 128 * 72;
        const __half* Bh = Al + 128 * 72;
#pragma unroll
        for (int ks = 0; ks < 4; ks++) {
            int k0 = ks * 16;
            wmma::fragment<wmma::matrix_a, 16, 16, 16, __half, wmma::row_major> fah[2], fal[2];
#pragma unroll
            for (int m = 0; m < 2; m++) {
                wmma::load_matrix_sync(fah[m], Ah + (wm * 32 + m * 16) * 72 + k0, 72);
                wmma::load_matrix_sync(fal[m], Al + (wm * 32 + m * 16) * 72 + k0, 72);
            }
#pragma unroll
            for (int n = 0; n < 4; n++) {
                wmma::fragment<wmma::matrix_b, 16, 16, 16, __half, wmma::col_major> fbh;
                wmma::load_matrix_sync(fbh, Bh + (wn * 64 + n * 16) * 72 + k0, 72);
#pragma unroll
                for (int m = 0; m < 2; m++) {
                    wmma::mma_sync(acc[m][n], fah[m], fbh, acc[m][n]);
                    wmma::mma_sync(acc[m][n], fal[m], fbh, acc[m][n]);
                }
            }
        }
        __syncthreads();
    }

    // stage D[128 tokens][128 cols] to SMEM (stride 132 floats)
    float* S = (float*)sm;
#pragma unroll
    for (int m = 0; m < 2; m++)
#pragma unroll
        for (int n = 0; n < 4; n++)
            wmma::store_matrix_sync(S + (size_t)(wm * 32 + m * 16) * 132 + wn * 64 + n * 16,
                                    acc[m][n], 132, wmma::mem_row_major);
    __syncthreads();

    // partial kv[m][d] = sum_s kp[s][m]*v[s][d], kp transform folded into reads
    int pm0 = (tid >> 4) * 4, pd0 = (tid & 15) * 4;
    float r[4][4] = {};
    for (int s = 0; s < 128; s++) {
        const float* row = &S[(size_t)s * 132];
        float4 kq = *(const float4*)&row[pm0];
        float4 vq = *(const float4*)&row[64 + pd0];
        float k0 = fmaxf(kq.x * NORM_OBJ, 0.f) + STABF;
        float k1 = fmaxf(kq.y * NORM_OBJ, 0.f) + STABF;
        float k2 = fmaxf(kq.z * NORM_OBJ, 0.f) + STABF;
        float k3 = fmaxf(kq.w * NORM_OBJ, 0.f) + STABF;
        r[0][0] += k0 * vq.x; r[0][1] += k0 * vq.y; r[0][2] += k0 * vq.z; r[0][3] += k0 * vq.w;
        r[1][0] += k1 * vq.x; r[1][1] += k1 * vq.y; r[1][2] += k1 * vq.z; r[1][3] += k1 * vq.w;
        r[2][0] += k2 * vq.x; r[2][1] += k2 * vq.y; r[2][2] += k2 * vq.z; r[2][3] += k2 * vq.w;
        r[3][0] += k3 * vq.x; r[3][1] += k3 * vq.y; r[3][2] += k3 * vq.z; r[3][3] += k3 * vq.w;
    }
    size_t pbase = ((((size_t)layer * 8 + (tile >> 6)) * 16 + h) * 64 + (tile & 63)) * 4160;
#pragma unroll
    for (int i = 0; i < 4; i++)
#pragma unroll
        for (int j = 0; j < 4; j++)
            part[pbase + (pm0 + i) * 64 + pd0 + j] = r[i][j];
    if (tid < 64) {
        float s = 0.f;
        for (int s2 = 0; s2 < 128; s2++)
            s += fmaxf(S[(size_t)s2 * 132 + tid] * NORM_OBJ, 0.f) + STABF;
        part[pbase + 4096 + tid] = s;
    }
}

__global__ void k_kv_reduce(const float* __restrict__ part, float* __restrict__ out)
{
    int j = blockIdx.x * 256 + threadIdx.x;
    if (j >= 4160) return;
    int bh = blockIdx.y, layer = blockIdx.z;
    size_t pb = ((size_t)layer * 128 + bh) * 64 * 4160;
    float s = 0.f;
#pragma unroll 8
    for (int t = 0; t < 64; t++) s += part[pb + (size_t)t * 4160 + j];
    out[((size_t)layer * 128 + bh) * 4160 + j] = s;
}

// =================== obj stack (verified R3-R6) ===================
__global__ __launch_bounds__(256) void k_sgemm64(
    const float* __restrict__ A, const float* __restrict__ B, float* __restrict__ C,
    int M, int N, int K, int mode, float scale,
    const float* __restrict__ bias, const float* __restrict__ aux)
{
    __shared__ float As[16 * 68];
    __shared__ float Bs[16 * 68];
    int tid = threadIdx.x;
    int m0 = blockIdx.y * 64, n0 = blockIdx.x * 64;
    int lm = tid >> 2, lk4 = (tid & 3) * 4;
    int lbk = tid >> 4, lbc = (tid & 15) * 4;
    int r0 = (tid >> 4) * 4, c0 = (tid & 15) * 4;
    float acc[4][4] = {};
    for (int kb = 0; kb < K; kb += 16) {
        float4 av = *(const float4*)(A + (size_t)(m0 + lm) * K + kb + lk4);
        As[(lk4 + 0) * 68 + lm] = av.x;
        As[(lk4 + 1) * 68 + lm] = av.y;
        As[(lk4 + 2) * 68 + lm] = av.z;
        As[(lk4 + 3) * 68 + lm] = av.w;
        *(float4*)&Bs[lbk * 68 + lbc] = *(const float4*)(B + (size_t)(kb + lbk) * N + n0 + lbc);
        __syncthreads();
#pragma unroll
        for (int kk = 0; kk < 16; kk++) {
            float4 a = *(float4*)&As[kk * 68 + r0];
            float4 b = *(float4*)&Bs[kk * 68 + c0];
            float ar[4] = {a.x, a.y, a.z, a.w};
            float br[4] = {b.x, b.y, b.z, b.w};
#pragma unroll
            for (int i = 0; i < 4; i++)
#pragma unroll
                for (int j = 0; j < 4; j++) acc[i][j] += ar[i] * br[j];
        }
        __syncthreads();
    }
#pragma unroll
    for (int i = 0; i < 4; i++) {
        int gm = m0 + r0 + i;
#pragma unroll
        for (int j = 0; j < 4; j++) {
            int gn = n0 + c0 + j;
            float v = acc[i][j];
            if (mode == 1)      v = fmaxf(v + bias[gn], 0.f);
            else if (mode == 2) v = fmaxf(v + bias[gn], 0.f) + aux[(size_t)(gm & 127) * N + gn];
            else if (mode == 3) v = fmaxf(v * scale, 0.f) + STABF;
            else if (mode == 4) v = v + aux[(size_t)gm * N + gn];
            C[(size_t)gm * N + gn] = v;
        }
    }
}

__global__ __launch_bounds__(256) void k_fav_apply(
    const float* __restrict__ qp, const float* __restrict__ kvg,
    float* __restrict__ fav, int layer)
{
    __shared__ float kvs[4096];
    __shared__ float kss[64];
    __shared__ float den[128];
    int h = blockIdx.x, b = blockIdx.y, tid = threadIdx.x;
    size_t base = ((size_t)layer * 128 + b * 16 + h) * 4160;
#pragma unroll
    for (int i = 0; i < 16; i++) kvs[tid + i * 256] = kvg[base + tid + i * 256];
    if (tid < 64) kss[tid] = kvg[base + 4096 + tid];
    __syncthreads();
    if (tid < 128) {
        const float* qr = qp + ((size_t)(b * 128 + tid)) * 1024 + h * 64;
        float s = 0.f;
#pragma unroll
        for (int m = 0; m < 64; m++) s += qr[m] * kss[m];
        den[tid] = s;
    }
    __syncthreads();
    int t = tid >> 1, d0 = (tid & 1) * 32;
    const float* qr = qp + ((size_t)(b * 128 + t)) * 1024 + h * 64;
    float a[32] = {};
    for (int m = 0; m < 64; m++) {
        float qv = qr[m];
#pragma unroll
        for (int j = 0; j < 32; j++) a[j] += qv * kvs[m * 64 + d0 + j];
    }
    float inv = 1.f / den[t];
    float* op = fav + ((size_t)(b * 128 + t)) * 1024 + h * 64 + d0;
#pragma unroll
    for (int j = 0; j < 32; j++) op[j] = a[j] * inv;
}

__global__ __launch_bounds__(256) void k_ln1024(
    const float* __restrict__ a, const float* __restrict__ b2,
    float* __restrict__ o, const float* __restrict__ g, const float* __restrict__ be)
{
    __shared__ float red[256];
    int row = blockIdx.x, tid = threadIdx.x;
    const float* ap = a + (size_t)row * 1024;
    float v[4];
    float s = 0.f;
#pragma unroll
    for (int j = 0; j < 4; j++) {
        int c = tid + j * 256;
        float x = ap[c];
        if (b2) x += b2[(size_t)row * 1024 + c];
        v[j] = x; s += x;
    }
    red[tid] = s; __syncthreads();
    for (int off = 128; off; off >>= 1) {
        if (tid < off) red[tid] += red[tid + off];
        __syncthreads();
    }
    float mu = red[0] * (1.f / 1024.f);
    __syncthreads();
    float s2 = 0.f;
#pragma unroll
    for (int j = 0; j < 4; j++) { float d = v[j] - mu; s2 += d * d; }
    red[tid] = s2; __syncthreads();
    for (int off = 128; off; off >>= 1) {
        if (tid < off) red[tid] += red[tid + off];
        __syncthreads();
    }
    float rs = rsqrtf(red[0] * (1.f / 1024.f) + LNEPS);
    float* op = o + (size_t)row * 1024;
#pragma unroll
    for (int j = 0; j < 4; j++) {
        int c = tid + j * 256;
        op[c] = (v[j] - mu) * rs * g[c] + be[c];
    }
}

// =================== launch ===================
extern "C" void kernel_launch(void* const* d_in, const int* in_sizes, int n_in,
                              void* d_out, int out_size)
{
    const float* obj_inputs  = (const float*)d_in[0];
    const float* road_inputs = (const float*)d_in[1];
    const float* rg_dense_W  = (const float*)d_in[2];
    const float* rg_dense_b  = (const float*)d_in[3];
    const float* rg_qkv_W    = (const float*)d_in[4];
    const float* rg_qkv_b    = (const float*)d_in[5];
    const float* rg_Wq       = (const float*)d_in[6];
    const float* rg_Wk       = (const float*)d_in[7];
    const float* rg_Wv       = (const float*)d_in[8];
    const float* rg_Wo       = (const float*)d_in[9];
    const float* rg_ln_g     = (const float*)d_in[10];
    const float* rg_ln_b     = (const float*)d_in[11];
    const float* rg_fc_W     = (const float*)d_in[12];
    const float* rg_fc_b     = (const float*)d_in[13];
    const float* rg_out_W    = (const float*)d_in[14];
    const float* rg_out_b    = (const float*)d_in[15];
    const float* dense_W     = (const float*)d_in[16];
    const float* dense_b     = (const float*)d_in[17];
    const float* pos_emb     = (const float*)d_in[18];
    const float* Wq          = (const float*)d_in[19];
    const float* Wk          = (const float*)d_in[20];
    const float* Wv          = (const float*)d_in[21];
    const float* Wo          = (const float*)d_in[22];
    const float* ln_g        = (const float*)d_in[23];
    const float* ln_b        = (const float*)d_in[24];
    const float* fc_W        = (const float*)d_in[25];
    const float* fc_b        = (const float*)d_in[26];
    float* out = (float*)d_out;

    float* base = nullptr;
    cudaGetSymbolAddress((void**)&base, g_s);
    float* roadx  = base + OFF_ROADX;
    float* roadq  = base + OFF_ROADQ;
    float* rpart  = base + OFF_RPART;
    float* rgkv   = base + OFF_RGKV;
    __half* AH = (__half*)(base + OFF_AH);
    __half* AL = (__half*)(base + OFF_AL);
    __half* BH = (__half*)(base + OFF_BH);
    float* kvpart = base + OFF_KVPART;
    float* objkv  = base + OFF_OBJKV;
    float* xo     = base + OFF_XO;
    float* qpbuf  = base + OFF_QP;
    float* favb   = base + OFF_FAV;
    float* attnb  = base + OFF_ATTN;
    float* nbuf   = base + OFF_N;
    float* ybuf   = base + OFF_Y;

    cudaFuncSetAttribute(k_kv_mma, cudaFuncAttributeMaxDynamicSharedMemorySize, 110592);

    // road stack
    k_road_dense<<<256, 256>>>(road_inputs, rg_dense_W, rg_dense_b, roadx);
    for (int i = 0; i < 2; i++) {
        k_road_favA<<<256, 256>>>(roadx, roadq, rg_qkv_W, rg_qkv_b,
                                  rg_Wk + i * 256, rg_Wv + i * 256, rpart);
        k_road_reduce<<<8, 80>>>(rpart, rgkv);
        k_road_favB<<<256, 256>>>(roadx, roadq, rg_Wq + i * 256, rg_Wo + i * 256,
                                  rgkv, rg_ln_g + i * 16, rg_ln_b + i * 16,
                                  rg_fc_W + i * 256, rg_fc_b + i * 16);
    }
    k_wpack<<<4096, 256>>>(Wk, Wv, BH);
    k_rg_expand_split<<<4096, 256>>>(roadx, rg_out_W, rg_out_b, AH, AL);

    // heavy tensor-core K/V + FAVOR reduction
    k_kv_mma<<<dim3(16, 512, 2), 256, 110592>>>(AH, AL, BH, kvpart);
    k_kv_reduce<<<dim3(17, 128, 2), 256>>>(kvpart, objkv);

    // obj stack
    k_sgemm64<<<dim3(16, 16), 256>>>(obj_inputs, dense_W, xo,
                                     1024, 1024, 512, 2, 0.f, dense_b, pos_emb);
    for (int i = 0; i < 2; i++) {
        k_sgemm64<<<dim3(16, 16), 256>>>(xo, Wq + (size_t)i * 1048576, qpbuf,
                                         1024, 1024, 1024, 3, NORM_OBJ, nullptr, nullptr);
        k_fav_apply<<<dim3(16, 8), 256>>>(qpbuf, objkv, favb, i);
        k_sgemm64<<<dim3(16, 16), 256>>>(favb, Wo + (size_t)i * 1048576, attnb,
                                         1024, 1024, 1024, 4, 0.f, nullptr, xo);
        k_ln1024<<<1024, 256>>>(attnb, nullptr, nbuf, ln_g + i * 1024, ln_b + i * 1024);
        k_sgemm64<<<dim3(16, 16), 256>>>(nbuf, fc_W + (size_t)i * 1048576, ybuf,
                                         1024, 1024, 1024, 1, 0.f, fc_b + i * 1024, nullptr);
        k_ln1024<<<1024, 256>>>(nbuf, ybuf, (i == 0) ? xo : out,
                                ln_g + i * 1024, ln_b + i * 1024);
    }
}

// round 8
// speedup vs baseline: 3.5018x; 1.0606x over previous
#include <cuda_runtime.h>
#include <cuda_fp16.h>
#include <mma.h>
#include <cstdint>
#include <cstddef>

using namespace nvcuda;

#define NORM_RG   0.70710678118654752f
#define NORM_OBJ  0.35355339059327376f
#define STABF     0.001f
#define LNEPS     0.001f

// ---------------- scratch layout (float offsets) ----------------
static constexpr size_t OFF_ROADX  = 0;
static constexpr size_t OFF_ROADQ  = OFF_ROADX  + 1048576;
static constexpr size_t OFF_RPART  = OFF_ROADQ  + 1048576;
static constexpr size_t OFF_RGKV   = OFF_RPART  + 20480;
static constexpr size_t OFF_AH     = OFF_RGKV   + 640;
static constexpr size_t OFF_AL     = OFF_AH     + 33554432;
static constexpr size_t OFF_BH     = OFF_AL     + 33554432;
static constexpr size_t OFF_BL     = OFF_BH     + 2097152;
static constexpr size_t OFF_KVPART = OFF_BL     + 2097152;
static constexpr size_t OFF_OBJKV  = OFF_KVPART + 68157440;
static constexpr size_t OFF_XO     = OFF_OBJKV  + 1064960;
static constexpr size_t OFF_QP     = OFF_XO     + 1048576;
static constexpr size_t OFF_FAV    = OFF_QP     + 1048576;
static constexpr size_t OFF_ATTN   = OFF_FAV    + 1048576;
static constexpr size_t OFF_N      = OFF_ATTN   + 1048576;
static constexpr size_t OFF_Y      = OFF_N      + 1048576;
static constexpr size_t SCRATCH_FLOATS = OFF_Y + 1048576;

__device__ __align__(256) float g_s[SCRATCH_FLOATS];

// cp.async helpers
#define CP16(dst, src) asm volatile("cp.async.ca.shared.global [%0], [%1], 16;" :: "r"(dst), "l"(src))
#define CPCOMMIT() asm volatile("cp.async.commit_group;" ::: "memory")
#define CPWAIT1() asm volatile("cp.async.wait_group 1;" ::: "memory")
#define CPWAIT0() asm volatile("cp.async.wait_group 0;" ::: "memory")

// =================== road stack (verified R3-R7) ===================
__global__ __launch_bounds__(256) void k_road_dense(
    const float* __restrict__ rin, const float* __restrict__ W,
    const float* __restrict__ b, float* __restrict__ xout)
{
    __shared__ float Ws[128], bs[16];
    int tid = threadIdx.x;
    if (tid < 128) Ws[tid] = W[tid];
    if (tid < 16)  bs[tid] = b[tid];
    __syncthreads();
    size_t tok = (size_t)blockIdx.x * 256 + tid;
    const float4* rp = (const float4*)(rin + tok * 8);
    float4 a0 = rp[0], a1 = rp[1];
    float x[8] = {a0.x, a0.y, a0.z, a0.w, a1.x, a1.y, a1.z, a1.w};
    float o[16];
#pragma unroll
    for (int c = 0; c < 16; c++) {
        float s = bs[c];
#pragma unroll
        for (int d = 0; d < 8; d++) s += x[d] * Ws[d * 16 + c];
        o[c] = fmaxf(s, 0.f);
    }
    float4* op = (float4*)(xout + tok * 16);
    op[0] = make_float4(o[0], o[1], o[2], o[3]);
    op[1] = make_float4(o[4], o[5], o[6], o[7]);
    op[2] = make_float4(o[8], o[9], o[10], o[11]);
    op[3] = make_float4(o[12], o[13], o[14], o[15]);
}

__global__ __launch_bounds__(256) void k_road_favA(
    const float* __restrict__ xin, float* __restrict__ qout,
    const float* __restrict__ qkvW, const float* __restrict__ qkvb,
    const float* __restrict__ Wk, const float* __restrict__ Wv,
    float* __restrict__ part)
{
    __shared__ float W16[256], b16[16], Wks[256], Wvs[256];
    __shared__ float wred[8 * 80];
    int tid = threadIdx.x;
    W16[tid] = qkvW[(tid >> 4) * 48 + (tid & 15)];
    Wks[tid] = Wk[tid];
    Wvs[tid] = Wv[tid];
    if (tid < 16) b16[tid] = qkvb[tid];
    __syncthreads();
    size_t tok = (size_t)blockIdx.x * 256 + tid;
    const float4* xp = (const float4*)(xin + tok * 16);
    float4 x0 = xp[0], x1 = xp[1], x2 = xp[2], x3 = xp[3];
    float x[16] = {x0.x, x0.y, x0.z, x0.w, x1.x, x1.y, x1.z, x1.w,
                   x2.x, x2.y, x2.z, x2.w, x3.x, x3.y, x3.z, x3.w};
    float q[16];
#pragma unroll
    for (int c = 0; c < 16; c++) {
        float s = b16[c];
#pragma unroll
        for (int d = 0; d < 16; d++) s += x[d] * W16[d * 16 + c];
        q[c] = fmaxf(s, 0.f);
    }
    float4* qo = (float4*)(qout + tok * 16);
    qo[0] = make_float4(q[0], q[1], q[2], q[3]);
    qo[1] = make_float4(q[4], q[5], q[6], q[7]);
    qo[2] = make_float4(q[8], q[9], q[10], q[11]);
    qo[3] = make_float4(q[12], q[13], q[14], q[15]);
    float kp[16], vh[16];
#pragma unroll
    for (int j = 0; j < 16; j++) {
        float sk = 0.f, sv = 0.f;
#pragma unroll
        for (int d = 0; d < 16; d++) {
            sk += q[d] * Wks[d * 16 + j];
            sv += q[d] * Wvs[d * 16 + j];
        }
        kp[j] = fmaxf(sk * NORM_RG, 0.f) + STABF;
        vh[j] = sv;
    }
    int lane = tid & 31, w = tid >> 5;
#pragma unroll
    for (int i = 0; i < 64; i++) {
        int hm = i >> 2;
        float v = kp[hm] * vh[(hm & 12) | (i & 3)];
#pragma unroll
        for (int off = 16; off > 0; off >>= 1) v += __shfl_down_sync(0xffffffffu, v, off);
        if (lane == 0) wred[w * 80 + i] = v;
    }
#pragma unroll
    for (int i = 0; i < 16; i++) {
        float v = kp[i];
#pragma unroll
        for (int off = 16; off > 0; off >>= 1) v += __shfl_down_sync(0xffffffffu, v, off);
        if (lane == 0) wred[w * 80 + 64 + i] = v;
    }
    __syncthreads();
    if (tid < 80) {
        float s = 0.f;
#pragma unroll
        for (int w2 = 0; w2 < 8; w2++) s += wred[w2 * 80 + tid];
        part[(size_t)blockIdx.x * 80 + tid] = s;
    }
}

__global__ void k_road_reduce(const float* __restrict__ part, float* __restrict__ kvout)
{
    int b = blockIdx.x, tid = threadIdx.x;
    float s = 0.f;
    for (int k = 0; k < 32; k++) s += part[(size_t)(b * 32 + k) * 80 + tid];
    kvout[(size_t)b * 80 + tid] = s;
}

__global__ __launch_bounds__(256) void k_road_favB(
    float* __restrict__ x, const float* __restrict__ qbuf,
    const float* __restrict__ Wq, const float* __restrict__ Wo,
    const float* __restrict__ kvg,
    const float* __restrict__ lng, const float* __restrict__ lnb,
    const float* __restrict__ fcW, const float* __restrict__ fcb)
{
    __shared__ float Wqs[256], Wos[256], fcWs[256];
    __shared__ float fcbs[16], gs[16], bbs[16], kvs[64], kss[16];
    int tid = threadIdx.x;
    Wqs[tid] = Wq[tid];
    Wos[tid] = Wo[tid];
    fcWs[tid] = fcW[tid];
    if (tid < 16) { fcbs[tid] = fcb[tid]; gs[tid] = lng[tid]; bbs[tid] = lnb[tid]; }
    int b = blockIdx.x >> 5;
    if (tid < 64) kvs[tid] = kvg[(size_t)b * 80 + tid];
    if (tid < 16) kss[tid] = kvg[(size_t)b * 80 + 64 + tid];
    __syncthreads();
    size_t tok = (size_t)blockIdx.x * 256 + tid;
    const float4* qp4 = (const float4*)(qbuf + tok * 16);
    float4 q0 = qp4[0], q1 = qp4[1], q2 = qp4[2], q3 = qp4[3];
    float q[16] = {q0.x, q0.y, q0.z, q0.w, q1.x, q1.y, q1.z, q1.w,
                   q2.x, q2.y, q2.z, q2.w, q3.x, q3.y, q3.z, q3.w};
    float qp[16];
#pragma unroll
    for (int j = 0; j < 16; j++) {
        float s = 0.f;
#pragma unroll
        for (int d = 0; d < 16; d++) s += q[d] * Wqs[d * 16 + j];
        qp[j] = fmaxf(s * NORM_RG, 0.f) + STABF;
    }
    float outv[16];
#pragma unroll
    for (int h = 0; h < 4; h++) {
        float den = 0.f;
#pragma unroll
        for (int m = 0; m < 4; m++) den += qp[h * 4 + m] * kss[h * 4 + m];
        float inv = 1.f / den;
#pragma unroll
        for (int d = 0; d < 4; d++) {
            float nu = 0.f;
#pragma unroll
            for (int m = 0; m < 4; m++) nu += qp[h * 4 + m] * kvs[(h * 4 + m) * 4 + d];
            outv[h * 4 + d] = nu * inv;
        }
    }
    float attn[16];
#pragma unroll
    for (int e = 0; e < 16; e++) {
        float s = 0.f;
#pragma unroll
        for (int j = 0; j < 16; j++) s += outv[j] * Wos[j * 16 + e];
        attn[e] = s;
    }
    const float4* xp = (const float4*)(x + tok * 16);
    float4 x0 = xp[0], x1 = xp[1], x2 = xp[2], x3 = xp[3];
    float xv[16] = {x0.x, x0.y, x0.z, x0.w, x1.x, x1.y, x1.z, x1.w,
                    x2.x, x2.y, x2.z, x2.w, x3.x, x3.y, x3.z, x3.w};
    float t1[16];
#pragma unroll
    for (int c = 0; c < 16; c++) t1[c] = attn[c] + xv[c];
    float mu = 0.f;
#pragma unroll
    for (int c = 0; c < 16; c++) mu += t1[c];
    mu *= (1.f / 16.f);
    float var = 0.f;
#pragma unroll
    for (int c = 0; c < 16; c++) { float d = t1[c] - mu; var += d * d; }
    var *= (1.f / 16.f);
    float rs = rsqrtf(var + LNEPS);
    float nn[16];
#pragma unroll
    for (int c = 0; c < 16; c++) nn[c] = (t1[c] - mu) * rs * gs[c] + bbs[c];
    float y[16];
#pragma unroll
    for (int c = 0; c < 16; c++) {
        float s = fcbs[c];
#pragma unroll
        for (int d = 0; d < 16; d++) s += nn[d] * fcWs[d * 16 + c];
        y[c] = fmaxf(s, 0.f);
    }
    float t2[16];
#pragma unroll
    for (int c = 0; c < 16; c++) t2[c] = nn[c] + y[c];
    mu = 0.f;
#pragma unroll
    for (int c = 0; c < 16; c++) mu += t2[c];
    mu *= (1.f / 16.f);
    var = 0.f;
#pragma unroll
    for (int c = 0; c < 16; c++) { float d = t2[c] - mu; var += d * d; }
    var *= (1.f / 16.f);
    rs = rsqrtf(var + LNEPS);
    float o[16];
#pragma unroll
    for (int c = 0; c < 16; c++) o[c] = (t2[c] - mu) * rs * gs[c] + bbs[c];
    float4* op = (float4*)(x + tok * 16);
    op[0] = make_float4(o[0], o[1], o[2], o[3]);
    op[1] = make_float4(o[4], o[5], o[6], o[7]);
    op[2] = make_float4(o[8], o[9], o[10], o[11]);
    op[3] = make_float4(o[12], o[13], o[14], o[15]);
}

// rg_out = relu(x16 @ W + b), emitted split into fp16 hi/lo
__global__ __launch_bounds__(256) void k_rg_expand_split(
    const float* __restrict__ x, const float* __restrict__ W,
    const float* __restrict__ b, __half* __restrict__ AH,
    __half* __restrict__ AL)
{
    __shared__ float xs[256];
    int tid = threadIdx.x;
    size_t tok0 = (size_t)blockIdx.x * 16;
    xs[tid] = x[tok0 * 16 + tid];
    __syncthreads();
    int c0 = tid * 4;
    float4 wv[16];
#pragma unroll
    for (int d = 0; d < 16; d++) wv[d] = *(const float4*)(W + d * 1024 + c0);
    float4 bb = *(const float4*)(b + c0);
#pragma unroll 4
    for (int tk = 0; tk < 16; tk++) {
        float4 a = bb;
#pragma unroll
        for (int d = 0; d < 16; d++) {
            float xv = xs[tk * 16 + d];
            a.x += xv * wv[d].x; a.y += xv * wv[d].y;
            a.z += xv * wv[d].z; a.w += xv * wv[d].w;
        }
        float o[4] = {fmaxf(a.x, 0.f), fmaxf(a.y, 0.f), fmaxf(a.z, 0.f), fmaxf(a.w, 0.f)};
        size_t base = (tok0 + tk) * 1024 + c0;
        __half hi[4], lo[4];
#pragma unroll
        for (int i = 0; i < 4; i++) {
            hi[i] = __float2half(o[i]);
            lo[i] = __float2half(o[i] - __half2float(hi[i]));
        }
        *(__half2*)(AH + base)     = __half2{hi[0], hi[1]};
        *(__half2*)(AH + base + 2) = __half2{hi[2], hi[3]};
        *(__half2*)(AL + base)     = __half2{lo[0], lo[1]};
        *(__half2*)(AL + base + 2) = __half2{lo[2], lo[3]};
    }
}

// pack Wk|Wv (N,H,h,d) -> B [layer][h][n=128][k=1024] fp16 (K-major rows)
__global__ void k_wpack(const float* __restrict__ Wk, const float* __restrict__ Wv,
                        __half* __restrict__ BH)
{
    int blk = blockIdx.x;
    int n = blk & 127, hh = (blk >> 7) & 15, l = blk >> 11;
    const float* src = (n < 64 ? Wk : Wv) + (size_t)l * 1048576 + hh * 64 + (n & 63);
    size_t dst = (size_t)blk * 1024;
    int k0 = threadIdx.x * 4;
#pragma unroll
    for (int i = 0; i < 4; i++) {
        int k = k0 + i;
        BH[dst + k] = __float2half(src[(size_t)k * 1024]);
    }
}

// ====== heavy kernel: WMMA fp16x2 K/V projection + FAVOR reduction ======
__global__ __launch_bounds__(256) void k_kv_mma(
    const __half* __restrict__ AH, const __half* __restrict__ AL,
    const __half* __restrict__ BH, float* __restrict__ part)
{
    extern __shared__ char sm[];
    int h = blockIdx.x, tile = blockIdx.y, layer = blockIdx.z;
    int tid = threadIdx.x, wid = tid >> 5;
    int wm = wid & 3, wn = wid >> 2;
    size_t abase = (size_t)tile * 128 * 1024;
    size_t bbase = (size_t)(layer * 16 + h) * 128 * 1024;
    uint32_t smb = (uint32_t)__cvta_generic_to_shared(sm);

    wmma::fragment<wmma::accumulator, 16, 16, 16, float> acc[2][4];
#pragma unroll
    for (int i = 0; i < 2; i++)
#pragma unroll
        for (int j = 0; j < 4; j++) wmma::fill_fragment(acc[i][j], 0.f);

    auto fill = [&](int st, int kb) {
#pragma unroll
        for (int it = 0; it < 12; it++) {
            int gslot = it * 256 + tid;
            int t = gslot >> 10, slot = gslot & 1023;
            int row = slot >> 3, ko = slot & 7;
            const __half* src =
                (t == 0 ? AH + abase : t == 1 ? AL + abase : BH + bbase)
                + (size_t)row * 1024 + kb + ko * 8;
            uint32_t dst = smb + st * 55296 + t * 18432 + row * 144 + ko * 16;
            CP16(dst, src);
        }
        CPCOMMIT();
    };

    fill(0, 0);
    for (int ib = 0; ib < 16; ib++) {
        if (ib < 15) { fill((ib + 1) & 1, (ib + 1) * 64); CPWAIT1(); }
        else         { CPWAIT0(); }
        __syncthreads();
        const __half* Ah = (const __half*)(sm + (ib & 1) * 55296);
        const __half* Al = Ah + 128 * 72;
        const __half* Bh = Al + 128 * 72;
#pragma unroll
        for (int ks = 0; ks < 4; ks++) {
            int k0 = ks * 16;
            wmma::fragment<wmma::matrix_a, 16, 16, 16, __half, wmma::row_major> fah[2], fal[2];
#pragma unroll
            for (int m = 0; m < 2; m++) {
                wmma::load_matrix_sync(fah[m], Ah + (wm * 32 + m * 16) * 72 + k0, 72);
                wmma::load_matrix_sync(fal[m], Al + (wm * 32 + m * 16) * 72 + k0, 72);
            }
#pragma unroll
            for (int n = 0; n < 4; n++) {
                wmma::fragment<wmma::matrix_b, 16, 16, 16, __half, wmma::col_major> fbh;
                wmma::load_matrix_sync(fbh, Bh + (wn * 64 + n * 16) * 72 + k0, 72);
#pragma unroll
                for (int m = 0; m < 2; m++) {
                    wmma::mma_sync(acc[m][n], fah[m], fbh, acc[m][n]);
                    wmma::mma_sync(acc[m][n], fal[m], fbh, acc[m][n]);
                }
            }
        }
        __syncthreads();
    }

    float* S = (float*)sm;
#pragma unroll
    for (int m = 0; m < 2; m++)
#pragma unroll
        for (int n = 0; n < 4; n++)
            wmma::store_matrix_sync(S + (size_t)(wm * 32 + m * 16) * 132 + wn * 64 + n * 16,
                                    acc[m][n], 132, wmma::mem_row_major);
    __syncthreads();

    int pm0 = (tid >> 4) * 4, pd0 = (tid & 15) * 4;
    float r[4][4] = {};
    for (int s = 0; s < 128; s++) {
        const float* row = &S[(size_t)s * 132];
        float4 kq = *(const float4*)&row[pm0];
        float4 vq = *(const float4*)&row[64 + pd0];
        float k0 = fmaxf(kq.x * NORM_OBJ, 0.f) + STABF;
        float k1 = fmaxf(kq.y * NORM_OBJ, 0.f) + STABF;
        float k2 = fmaxf(kq.z * NORM_OBJ, 0.f) + STABF;
        float k3 = fmaxf(kq.w * NORM_OBJ, 0.f) + STABF;
        r[0][0] += k0 * vq.x; r[0][1] += k0 * vq.y; r[0][2] += k0 * vq.z; r[0][3] += k0 * vq.w;
        r[1][0] += k1 * vq.x; r[1][1] += k1 * vq.y; r[1][2] += k1 * vq.z; r[1][3] += k1 * vq.w;
        r[2][0] += k2 * vq.x; r[2][1] += k2 * vq.y; r[2][2] += k2 * vq.z; r[2][3] += k2 * vq.w;
        r[3][0] += k3 * vq.x; r[3][1] += k3 * vq.y; r[3][2] += k3 * vq.z; r[3][3] += k3 * vq.w;
    }
    size_t pbase = ((((size_t)layer * 8 + (tile >> 6)) * 16 + h) * 64 + (tile & 63)) * 4160;
#pragma unroll
    for (int i = 0; i < 4; i++)
#pragma unroll
        for (int j = 0; j < 4; j++)
            part[pbase + (pm0 + i) * 64 + pd0 + j] = r[i][j];
    if (tid < 64) {
        float s = 0.f;
        for (int s2 = 0; s2 < 128; s2++)
            s += fmaxf(S[(size_t)s2 * 132 + tid] * NORM_OBJ, 0.f) + STABF;
        part[pbase + 4096 + tid] = s;
    }
}

__global__ void k_kv_reduce(const float* __restrict__ part, float* __restrict__ out)
{
    int j = blockIdx.x * 256 + threadIdx.x;
    if (j >= 4160) return;
    int bh = blockIdx.y, layer = blockIdx.z;
    size_t pb = ((size_t)layer * 128 + bh) * 64 * 4160;
    float s = 0.f;
#pragma unroll 8
    for (int t = 0; t < 64; t++) s += part[pb + (size_t)t * 4160 + j];
    out[((size_t)layer * 128 + bh) * 4160 + j] = s;
}

// ===== obj-stack GEMM on tensor cores: fp16x2 split, fused epilogues =====
// C[M,N] = A[M,K] @ B[K,N]; tiles 128(M)x64(N); grid (N/64, M/128); 256 thr
// modes: 1 bias+relu | 2 bias+relu+pos | 3 relu(x*scale)+STAB | 4 +aux
__global__ __launch_bounds__(256) void k_hgemm128(
    const float* __restrict__ A, const float* __restrict__ B, float* __restrict__ C,
    int M, int N, int K, int mode, float scale,
    const float* __restrict__ bias, const float* __restrict__ aux)
{
    __shared__ __align__(16) char smem[46080];
    __half* Ah = (__half*)smem;              // [128][72]
    __half* Al = Ah + 128 * 72;              // [128][72]
    __half* Bs = Al + 128 * 72;              // [64][72]  (n-major, k contiguous)
    float* S = (float*)smem;                 // [128][68] epilogue reuse
    int tid = threadIdx.x, wid = tid >> 5;
    int wm = wid & 3, wn = wid >> 2;         // 4x2 warps: 32 rows x 32 cols each
    int m0 = blockIdx.y * 128, n0 = blockIdx.x * 64;

    wmma::fragment<wmma::accumulator, 16, 16, 16, float> acc[2][2];
#pragma unroll
    for (int i = 0; i < 2; i++)
#pragma unroll
        for (int j = 0; j < 2; j++) wmma::fill_fragment(acc[i][j], 0.f);

    for (int kb = 0; kb < K; kb += 64) {
        // stage A 128x64 fp32 -> split hi/lo fp16
#pragma unroll
        for (int it = 0; it < 8; it++) {
            int slot = it * 256 + tid;           // 2048 float4 slots
            int row = slot >> 4, c4 = (slot & 15) * 4;
            float4 v = *(const float4*)(A + (size_t)(m0 + row) * K + kb + c4);
            float vv[4] = {v.x, v.y, v.z, v.w};
#pragma unroll
            for (int i = 0; i < 4; i++) {
                __half hi = __float2half(vv[i]);
                Ah[row * 72 + c4 + i] = hi;
                Al[row * 72 + c4 + i] = __float2half(vv[i] - __half2float(hi));
            }
        }
        // stage B 64k x 64n fp32 -> transpose to Bs[n][k] fp16
#pragma unroll
        for (int it = 0; it < 4; it++) {
            int slot = it * 256 + tid;           // 1024 float4 slots
            int krow = slot >> 4, c4 = (slot & 15) * 4;
            float4 v = *(const float4*)(B + (size_t)(kb + krow) * N + n0 + c4);
            Bs[(c4 + 0) * 72 + krow] = __float2half(v.x);
            Bs[(c4 + 1) * 72 + krow] = __float2half(v.y);
            Bs[(c4 + 2) * 72 + krow] = __float2half(v.z);
            Bs[(c4 + 3) * 72 + krow] = __float2half(v.w);
        }
        __syncthreads();
#pragma unroll
        for (int ks = 0; ks < 4; ks++) {
            int k0 = ks * 16;
            wmma::fragment<wmma::matrix_a, 16, 16, 16, __half, wmma::row_major> fah[2], fal[2];
#pragma unroll
            for (int m = 0; m < 2; m++) {
                wmma::load_matrix_sync(fah[m], Ah + (wm * 32 + m * 16) * 72 + k0, 72);
                wmma::load_matrix_sync(fal[m], Al + (wm * 32 + m * 16) * 72 + k0, 72);
            }
#pragma unroll
            for (int n = 0; n < 2; n++) {
                wmma::fragment<wmma::matrix_b, 16, 16, 16, __half, wmma::col_major> fbh;
                wmma::load_matrix_sync(fbh, Bs + (wn * 32 + n * 16) * 72 + k0, 72);
#pragma unroll
                for (int m = 0; m < 2; m++) {
                    wmma::mma_sync(acc[m][n], fah[m], fbh, acc[m][n]);
                    wmma::mma_sync(acc[m][n], fal[m], fbh, acc[m][n]);
                }
            }
        }
        __syncthreads();
    }

    // epilogue via SMEM
#pragma unroll
    for (int m = 0; m < 2; m++)
#pragma unroll
        for (int n = 0; n < 2; n++)
            wmma::store_matrix_sync(S + (size_t)(wm * 32 + m * 16) * 68 + wn * 32 + n * 16,
                                    acc[m][n], 68, wmma::mem_row_major);
    __syncthreads();
#pragma unroll
    for (int it = 0; it < 32; it++) {
        int e = it * 256 + tid;                  // 8192 elements
        int row = e >> 6, col = e & 63;
        int gm = m0 + row, gn = n0 + col;
        float v = S[row * 68 + col];
        if (mode == 1)      v = fmaxf(v + bias[gn], 0.f);
        else if (mode == 2) v = fmaxf(v + bias[gn], 0.f) + aux[(size_t)(gm & 127) * N + gn];
        else if (mode == 3) v = fmaxf(v * scale, 0.f) + STABF;
        else if (mode == 4) v = v + aux[(size_t)gm * N + gn];
        C[(size_t)gm * N + gn] = v;
    }
}

__global__ __launch_bounds__(256) void k_fav_apply(
    const float* __restrict__ qp, const float* __restrict__ kvg,
    float* __restrict__ fav, int layer)
{
    __shared__ float kvs[4096];
    __shared__ float kss[64];
    __shared__ float den[128];
    int h = blockIdx.x, b = blockIdx.y, tid = threadIdx.x;
    size_t base = ((size_t)layer * 128 + b * 16 + h) * 4160;
#pragma unroll
    for (int i = 0; i < 16; i++) kvs[tid + i * 256] = kvg[base + tid + i * 256];
    if (tid < 64) kss[tid] = kvg[base + 4096 + tid];
    __syncthreads();
    if (tid < 128) {
        const float* qr = qp + ((size_t)(b * 128 + tid)) * 1024 + h * 64;
        float s = 0.f;
#pragma unroll
        for (int m = 0; m < 64; m++) s += qr[m] * kss[m];
        den[tid] = s;
    }
    __syncthreads();
    int t = tid >> 1, d0 = (tid & 1) * 32;
    const float* qr = qp + ((size_t)(b * 128 + t)) * 1024 + h * 64;
    float a[32] = {};
    for (int m = 0; m < 64; m++) {
        float qv = qr[m];
#pragma unroll
        for (int j = 0; j < 32; j++) a[j] += qv * kvs[m * 64 + d0 + j];
    }
    float inv = 1.f / den[t];
    float* op = fav + ((size_t)(b * 128 + t)) * 1024 + h * 64 + d0;
#pragma unroll
    for (int j = 0; j < 32; j++) op[j] = a[j] * inv;
}

__global__ __launch_bounds__(256) void k_ln1024(
    const float* __restrict__ a, const float* __restrict__ b2,
    float* __restrict__ o, const float* __restrict__ g, const float* __restrict__ be)
{
    __shared__ float red[256];
    int row = blockIdx.x, tid = threadIdx.x;
    const float* ap = a + (size_t)row * 1024;
    float v[4];
    float s = 0.f;
#pragma unroll
    for (int j = 0; j < 4; j++) {
        int c = tid + j * 256;
        float x = ap[c];
        if (b2) x += b2[(size_t)row * 1024 + c];
        v[j] = x; s += x;
    }
    red[tid] = s; __syncthreads();
    for (int off = 128; off; off >>= 1) {
        if (tid < off) red[tid] += red[tid + off];
        __syncthreads();
    }
    float mu = red[0] * (1.f / 1024.f);
    __syncthreads();
    float s2 = 0.f;
#pragma unroll
    for (int j = 0; j < 4; j++) { float d = v[j] - mu; s2 += d * d; }
    red[tid] = s2; __syncthreads();
    for (int off = 128; off; off >>= 1) {
        if (tid < off) red[tid] += red[tid + off];
        __syncthreads();
    }
    float rs = rsqrtf(red[0] * (1.f / 1024.f) + LNEPS);
    float* op = o + (size_t)row * 1024;
#pragma unroll
    for (int j = 0; j < 4; j++) {
        int c = tid + j * 256;
        op[c] = (v[j] - mu) * rs * g[c] + be[c];
    }
}

// =================== launch ===================
extern "C" void kernel_launch(void* const* d_in, const int* in_sizes, int n_in,
                              void* d_out, int out_size)
{
    const float* obj_inputs  = (const float*)d_in[0];
    const float* road_inputs = (const float*)d_in[1];
    const float* rg_dense_W  = (const float*)d_in[2];
    const float* rg_dense_b  = (const float*)d_in[3];
    const float* rg_qkv_W    = (const float*)d_in[4];
    const float* rg_qkv_b    = (const float*)d_in[5];
    const float* rg_Wq       = (const float*)d_in[6];
    const float* rg_Wk       = (const float*)d_in[7];
    const float* rg_Wv       = (const float*)d_in[8];
    const float* rg_Wo       = (const float*)d_in[9];
    const float* rg_ln_g     = (const float*)d_in[10];
    const float* rg_ln_b     = (const float*)d_in[11];
    const float* rg_fc_W     = (const float*)d_in[12];
    const float* rg_fc_b     = (const float*)d_in[13];
    const float* rg_out_W    = (const float*)d_in[14];
    const float* rg_out_b    = (const float*)d_in[15];
    const float* dense_W     = (const float*)d_in[16];
    const float* dense_b     = (const float*)d_in[17];
    const float* pos_emb     = (const float*)d_in[18];
    const float* Wq          = (const float*)d_in[19];
    const float* Wk          = (const float*)d_in[20];
    const float* Wv          = (const float*)d_in[21];
    const float* Wo          = (const float*)d_in[22];
    const float* ln_g        = (const float*)d_in[23];
    const float* ln_b        = (const float*)d_in[24];
    const float* fc_W        = (const float*)d_in[25];
    const float* fc_b        = (const float*)d_in[26];
    float* out = (float*)d_out;

    float* base = nullptr;
    cudaGetSymbolAddress((void**)&base, g_s);
    float* roadx  = base + OFF_ROADX;
    float* roadq  = base + OFF_ROADQ;
    float* rpart  = base + OFF_RPART;
    float* rgkv   = base + OFF_RGKV;
    __half* AH = (__half*)(base + OFF_AH);
    __half* AL = (__half*)(base + OFF_AL);
    __half* BH = (__half*)(base + OFF_BH);
    float* kvpart = base + OFF_KVPART;
    float* objkv  = base + OFF_OBJKV;
    float* xo     = base + OFF_XO;
    float* qpbuf  = base + OFF_QP;
    float* favb   = base + OFF_FAV;
    float* attnb  = base + OFF_ATTN;
    float* nbuf   = base + OFF_N;
    float* ybuf   = base + OFF_Y;

    cudaFuncSetAttribute(k_kv_mma, cudaFuncAttributeMaxDynamicSharedMemorySize, 110592);

    // road stack
    k_road_dense<<<256, 256>>>(road_inputs, rg_dense_W, rg_dense_b, roadx);
    for (int i = 0; i < 2; i++) {
        k_road_favA<<<256, 256>>>(roadx, roadq, rg_qkv_W, rg_qkv_b,
                                  rg_Wk + i * 256, rg_Wv + i * 256, rpart);
        k_road_reduce<<<8, 80>>>(rpart, rgkv);
        k_road_favB<<<256, 256>>>(roadx, roadq, rg_Wq + i * 256, rg_Wo + i * 256,
                                  rgkv, rg_ln_g + i * 16, rg_ln_b + i * 16,
                                  rg_fc_W + i * 256, rg_fc_b + i * 16);
    }
    k_wpack<<<4096, 256>>>(Wk, Wv, BH);
    k_rg_expand_split<<<4096, 256>>>(roadx, rg_out_W, rg_out_b, AH, AL);

    // heavy tensor-core K/V + FAVOR reduction
    k_kv_mma<<<dim3(16, 512, 2), 256, 110592>>>(AH, AL, BH, kvpart);
    k_kv_reduce<<<dim3(17, 128, 2), 256>>>(kvpart, objkv);

    // obj stack (tensor-core GEMMs)
    k_hgemm128<<<dim3(16, 8), 256>>>(obj_inputs, dense_W, xo,
                                     1024, 1024, 512, 2, 0.f, dense_b, pos_emb);
    for (int i = 0; i < 2; i++) {
        k_hgemm128<<<dim3(16, 8), 256>>>(xo, Wq + (size_t)i * 1048576, qpbuf,
                                         1024, 1024, 1024, 3, NORM_OBJ, nullptr, nullptr);
        k_fav_apply<<<dim3(16, 8), 256>>>(qpbuf, objkv, favb, i);
        k_hgemm128<<<dim3(16, 8), 256>>>(favb, Wo + (size_t)i * 1048576, attnb,
                                         1024, 1024, 1024, 4, 0.f, nullptr, xo);
        k_ln1024<<<1024, 256>>>(attnb, nullptr, nbuf, ln_g + i * 1024, ln_b + i * 1024);
        k_hgemm128<<<dim3(16, 8), 256>>>(nbuf, fc_W + (size_t)i * 1048576, ybuf,
                                         1024, 1024, 1024, 1, 0.f, fc_b + i * 1024, nullptr);
        k_ln1024<<<1024, 256>>>(nbuf, ybuf, (i == 0) ? xo : out,
                                ln_g + i * 1024, ln_b + i * 1024);
    }
}

// round 10
// speedup vs baseline: 3.6218x; 1.0343x over previous
#include <cuda_runtime.h>
#include <cuda_fp16.h>
#include <mma.h>
#include <cstdint>
#include <cstddef>

using namespace nvcuda;

#define NORM_RG   0.70710678118654752f
#define NORM_OBJ  0.35355339059327376f
#define STABF     0.001f
#define LNEPS     0.001f

// ---------------- scratch layout (float offsets) ----------------
static constexpr size_t OFF_ROADX  = 0;
static constexpr size_t OFF_ROADQ  = OFF_ROADX  + 1048576;
static constexpr size_t OFF_RPART  = OFF_ROADQ  + 1048576;
static constexpr size_t OFF_RGKV   = OFF_RPART  + 20480;
static constexpr size_t OFF_AH     = OFF_RGKV   + 640;
static constexpr size_t OFF_AL     = OFF_AH     + 33554432;
static constexpr size_t OFF_BH     = OFF_AL     + 33554432;
static constexpr size_t OFF_BL     = OFF_BH     + 2097152;
static constexpr size_t OFF_KVPART = OFF_BL     + 2097152;
static constexpr size_t OFF_OBJKV  = OFF_KVPART + 68157440;
static constexpr size_t OFF_XO     = OFF_OBJKV  + 1064960;
static constexpr size_t OFF_QP     = OFF_XO     + 1048576;
static constexpr size_t OFF_FAV    = OFF_QP     + 1048576;
static constexpr size_t OFF_ATTN   = OFF_FAV    + 1048576;
static constexpr size_t OFF_N      = OFF_ATTN   + 1048576;
static constexpr size_t OFF_Y      = OFF_N      + 1048576;
static constexpr size_t SCRATCH_FLOATS = OFF_Y + 1048576;

__device__ __align__(256) float g_s[SCRATCH_FLOATS];

// cp.async helpers
#define CP16(dst, src) asm volatile("cp.async.ca.shared.global [%0], [%1], 16;" :: "r"(dst), "l"(src))
#define CPCOMMIT() asm volatile("cp.async.commit_group;" ::: "memory")
#define CPWAIT1() asm volatile("cp.async.wait_group 1;" ::: "memory")
#define CPWAIT0() asm volatile("cp.async.wait_group 0;" ::: "memory")

// =================== road stack (verified R3-R8) ===================
__global__ __launch_bounds__(256) void k_road_dense(
    const float* __restrict__ rin, const float* __restrict__ W,
    const float* __restrict__ b, float* __restrict__ xout)
{
    __shared__ float Ws[128], bs[16];
    int tid = threadIdx.x;
    if (tid < 128) Ws[tid] = W[tid];
    if (tid < 16)  bs[tid] = b[tid];
    __syncthreads();
    size_t tok = (size_t)blockIdx.x * 256 + tid;
    const float4* rp = (const float4*)(rin + tok * 8);
    float4 a0 = rp[0], a1 = rp[1];
    float x[8] = {a0.x, a0.y, a0.z, a0.w, a1.x, a1.y, a1.z, a1.w};
    float o[16];
#pragma unroll
    for (int c = 0; c < 16; c++) {
        float s = bs[c];
#pragma unroll
        for (int d = 0; d < 8; d++) s += x[d] * Ws[d * 16 + c];
        o[c] = fmaxf(s, 0.f);
    }
    float4* op = (float4*)(xout + tok * 16);
    op[0] = make_float4(o[0], o[1], o[2], o[3]);
    op[1] = make_float4(o[4], o[5], o[6], o[7]);
    op[2] = make_float4(o[8], o[9], o[10], o[11]);
    op[3] = make_float4(o[12], o[13], o[14], o[15]);
}

__global__ __launch_bounds__(256) void k_road_favA(
    const float* __restrict__ xin, float* __restrict__ qout,
    const float* __restrict__ qkvW, const float* __restrict__ qkvb,
    const float* __restrict__ Wk, const float* __restrict__ Wv,
    float* __restrict__ part)
{
    __shared__ float W16[256], b16[16], Wks[256], Wvs[256];
    __shared__ float wred[8 * 80];
    int tid = threadIdx.x;
    W16[tid] = qkvW[(tid >> 4) * 48 + (tid & 15)];
    Wks[tid] = Wk[tid];
    Wvs[tid] = Wv[tid];
    if (tid < 16) b16[tid] = qkvb[tid];
    __syncthreads();
    size_t tok = (size_t)blockIdx.x * 256 + tid;
    const float4* xp = (const float4*)(xin + tok * 16);
    float4 x0 = xp[0], x1 = xp[1], x2 = xp[2], x3 = xp[3];
    float x[16] = {x0.x, x0.y, x0.z, x0.w, x1.x, x1.y, x1.z, x1.w,
                   x2.x, x2.y, x2.z, x2.w, x3.x, x3.y, x3.z, x3.w};
    float q[16];
#pragma unroll
    for (int c = 0; c < 16; c++) {
        float s = b16[c];
#pragma unroll
        for (int d = 0; d < 16; d++) s += x[d] * W16[d * 16 + c];
        q[c] = fmaxf(s, 0.f);
    }
    float4* qo = (float4*)(qout + tok * 16);
    qo[0] = make_float4(q[0], q[1], q[2], q[3]);
    qo[1] = make_float4(q[4], q[5], q[6], q[7]);
    qo[2] = make_float4(q[8], q[9], q[10], q[11]);
    qo[3] = make_float4(q[12], q[13], q[14], q[15]);
    float kp[16], vh[16];
#pragma unroll
    for (int j = 0; j < 16; j++) {
        float sk = 0.f, sv = 0.f;
#pragma unroll
        for (int d = 0; d < 16; d++) {
            sk += q[d] * Wks[d * 16 + j];
            sv += q[d] * Wvs[d * 16 + j];
        }
        kp[j] = fmaxf(sk * NORM_RG, 0.f) + STABF;
        vh[j] = sv;
    }
    int lane = tid & 31, w = tid >> 5;
#pragma unroll
    for (int i = 0; i < 64; i++) {
        int hm = i >> 2;
        float v = kp[hm] * vh[(hm & 12) | (i & 3)];
#pragma unroll
        for (int off = 16; off > 0; off >>= 1) v += __shfl_down_sync(0xffffffffu, v, off);
        if (lane == 0) wred[w * 80 + i] = v;
    }
#pragma unroll
    for (int i = 0; i < 16; i++) {
        float v = kp[i];
#pragma unroll
        for (int off = 16; off > 0; off >>= 1) v += __shfl_down_sync(0xffffffffu, v, off);
        if (lane == 0) wred[w * 80 + 64 + i] = v;
    }
    __syncthreads();
    if (tid < 80) {
        float s = 0.f;
#pragma unroll
        for (int w2 = 0; w2 < 8; w2++) s += wred[w2 * 80 + tid];
        part[(size_t)blockIdx.x * 80 + tid] = s;
    }
}

__global__ void k_road_reduce(const float* __restrict__ part, float* __restrict__ kvout)
{
    int b = blockIdx.x, tid = threadIdx.x;
    float s = 0.f;
    for (int k = 0; k < 32; k++) s += part[(size_t)(b * 32 + k) * 80 + tid];
    kvout[(size_t)b * 80 + tid] = s;
}

__global__ __launch_bounds__(256) void k_road_favB(
    float* __restrict__ x, const float* __restrict__ qbuf,
    const float* __restrict__ Wq, const float* __restrict__ Wo,
    const float* __restrict__ kvg,
    const float* __restrict__ lng, const float* __restrict__ lnb,
    const float* __restrict__ fcW, const float* __restrict__ fcb)
{
    __shared__ float Wqs[256], Wos[256], fcWs[256];
    __shared__ float fcbs[16], gs[16], bbs[16], kvs[64], kss[16];
    int tid = threadIdx.x;
    Wqs[tid] = Wq[tid];
    Wos[tid] = Wo[tid];
    fcWs[tid] = fcW[tid];
    if (tid < 16) { fcbs[tid] = fcb[tid]; gs[tid] = lng[tid]; bbs[tid] = lnb[tid]; }
    int b = blockIdx.x >> 5;
    if (tid < 64) kvs[tid] = kvg[(size_t)b * 80 + tid];
    if (tid < 16) kss[tid] = kvg[(size_t)b * 80 + 64 + tid];
    __syncthreads();
    size_t tok = (size_t)blockIdx.x * 256 + tid;
    const float4* qp4 = (const float4*)(qbuf + tok * 16);
    float4 q0 = qp4[0], q1 = qp4[1], q2 = qp4[2], q3 = qp4[3];
    float q[16] = {q0.x, q0.y, q0.z, q0.w, q1.x, q1.y, q1.z, q1.w,
                   q2.x, q2.y, q2.z, q2.w, q3.x, q3.y, q3.z, q3.w};
    float qp[16];
#pragma unroll
    for (int j = 0; j < 16; j++) {
        float s = 0.f;
#pragma unroll
        for (int d = 0; d < 16; d++) s += q[d] * Wqs[d * 16 + j];
        qp[j] = fmaxf(s * NORM_RG, 0.f) + STABF;
    }
    float outv[16];
#pragma unroll
    for (int h = 0; h < 4; h++) {
        float den = 0.f;
#pragma unroll
        for (int m = 0; m < 4; m++) den += qp[h * 4 + m] * kss[h * 4 + m];
        float inv = 1.f / den;
#pragma unroll
        for (int d = 0; d < 4; d++) {
            float nu = 0.f;
#pragma unroll
            for (int m = 0; m < 4; m++) nu += qp[h * 4 + m] * kvs[(h * 4 + m) * 4 + d];
            outv[h * 4 + d] = nu * inv;
        }
    }
    float attn[16];
#pragma unroll
    for (int e = 0; e < 16; e++) {
        float s = 0.f;
#pragma unroll
        for (int j = 0; j < 16; j++) s += outv[j] * Wos[j * 16 + e];
        attn[e] = s;
    }
    const float4* xp = (const float4*)(x + tok * 16);
    float4 x0 = xp[0], x1 = xp[1], x2 = xp[2], x3 = xp[3];
    float xv[16] = {x0.x, x0.y, x0.z, x0.w, x1.x, x1.y, x1.z, x1.w,
                    x2.x, x2.y, x2.z, x2.w, x3.x, x3.y, x3.z, x3.w};
    float t1[16];
#pragma unroll
    for (int c = 0; c < 16; c++) t1[c] = attn[c] + xv[c];
    float mu = 0.f;
#pragma unroll
    for (int c = 0; c < 16; c++) mu += t1[c];
    mu *= (1.f / 16.f);
    float var = 0.f;
#pragma unroll
    for (int c = 0; c < 16; c++) { float d = t1[c] - mu; var += d * d; }
    var *= (1.f / 16.f);
    float rs = rsqrtf(var + LNEPS);
    float nn[16];
#pragma unroll
    for (int c = 0; c < 16; c++) nn[c] = (t1[c] - mu) * rs * gs[c] + bbs[c];
    float y[16];
#pragma unroll
    for (int c = 0; c < 16; c++) {
        float s = fcbs[c];
#pragma unroll
        for (int d = 0; d < 16; d++) s += nn[d] * fcWs[d * 16 + c];
        y[c] = fmaxf(s, 0.f);
    }
    float t2[16];
#pragma unroll
    for (int c = 0; c < 16; c++) t2[c] = nn[c] + y[c];
    mu = 0.f;
#pragma unroll
    for (int c = 0; c < 16; c++) mu += t2[c];
    mu *= (1.f / 16.f);
    var = 0.f;
#pragma unroll
    for (int c = 0; c < 16; c++) { float d = t2[c] - mu; var += d * d; }
    var *= (1.f / 16.f);
    rs = rsqrtf(var + LNEPS);
    float o[16];
#pragma unroll
    for (int c = 0; c < 16; c++) o[c] = (t2[c] - mu) * rs * gs[c] + bbs[c];
    float4* op = (float4*)(x + tok * 16);
    op[0] = make_float4(o[0], o[1], o[2], o[3]);
    op[1] = make_float4(o[4], o[5], o[6], o[7]);
    op[2] = make_float4(o[8], o[9], o[10], o[11]);
    op[3] = make_float4(o[12], o[13], o[14], o[15]);
}

// rg_out = relu(x16 @ W + b), emitted split into fp16 hi/lo
__global__ __launch_bounds__(256) void k_rg_expand_split(
    const float* __restrict__ x, const float* __restrict__ W,
    const float* __restrict__ b, __half* __restrict__ AH,
    __half* __restrict__ AL)
{
    __shared__ float xs[256];
    int tid = threadIdx.x;
    size_t tok0 = (size_t)blockIdx.x * 16;
    xs[tid] = x[tok0 * 16 + tid];
    __syncthreads();
    int c0 = tid * 4;
    float4 wv[16];
#pragma unroll
    for (int d = 0; d < 16; d++) wv[d] = *(const float4*)(W + d * 1024 + c0);
    float4 bb = *(const float4*)(b + c0);
#pragma unroll 4
    for (int tk = 0; tk < 16; tk++) {
        float4 a = bb;
#pragma unroll
        for (int d = 0; d < 16; d++) {
            float xv = xs[tk * 16 + d];
            a.x += xv * wv[d].x; a.y += xv * wv[d].y;
            a.z += xv * wv[d].z; a.w += xv * wv[d].w;
        }
        float o[4] = {fmaxf(a.x, 0.f), fmaxf(a.y, 0.f), fmaxf(a.z, 0.f), fmaxf(a.w, 0.f)};
        size_t base = (tok0 + tk) * 1024 + c0;
        __half hi[4], lo[4];
#pragma unroll
        for (int i = 0; i < 4; i++) {
            hi[i] = __float2half(o[i]);
            lo[i] = __float2half(o[i] - __half2float(hi[i]));
        }
        *(__half2*)(AH + base)     = __half2{hi[0], hi[1]};
        *(__half2*)(AH + base + 2) = __half2{hi[2], hi[3]};
        *(__half2*)(AL + base)     = __half2{lo[0], lo[1]};
        *(__half2*)(AL + base + 2) = __half2{lo[2], lo[3]};
    }
}

// pack Wk|Wv (N,H,h,d) -> B [layer][h][n=128][k=1024] fp16, coalesced transpose
// grid (h=16, kband=32, layer=2), 256 thr
__global__ __launch_bounds__(256) void k_wpack2(
    const float* __restrict__ Wk, const float* __restrict__ Wv,
    __half* __restrict__ BH)
{
    __shared__ float ws[32 * 129];
    int h = blockIdx.x, kb = blockIdx.y, l = blockIdx.z;
    int tid = threadIdx.x;
#pragma unroll
    for (int it = 0; it < 16; it++) {
        int slot = it * 256 + tid;          // 4096: 32 k-rows x 128 n-cols
        int kr = slot >> 7, c = slot & 127;
        const float* W = (c < 64) ? Wk : Wv;
        ws[kr * 129 + c] = W[(size_t)l * 1048576 + (size_t)(kb * 32 + kr) * 1024 + h * 64 + (c & 63)];
    }
    __syncthreads();
#pragma unroll
    for (int it = 0; it < 16; it++) {
        int slot = it * 256 + tid;          // n-major for coalesced writes
        int n = slot >> 5, kk = slot & 31;
        BH[((size_t)(l * 16 + h) * 128 + n) * 1024 + kb * 32 + kk] = __float2half(ws[kk * 129 + n]);
    }
}

// ====== heavy kernel: WMMA fp16x2 K/V projection + MMA FAVOR reduction ======
__global__ __launch_bounds__(256) void k_kv_mma(
    const __half* __restrict__ AH, const __half* __restrict__ AL,
    const __half* __restrict__ BH, float* __restrict__ part)
{
    extern __shared__ char sm[];
    int h = blockIdx.x, tile = blockIdx.y, layer = blockIdx.z;
    int tid = threadIdx.x, wid = tid >> 5;
    int wm = wid & 3, wn = wid >> 2;
    size_t abase = (size_t)tile * 128 * 1024;
    size_t bbase = (size_t)(layer * 16 + h) * 128 * 1024;
    uint32_t smb = (uint32_t)__cvta_generic_to_shared(sm);

    wmma::fragment<wmma::accumulator, 16, 16, 16, float> acc[2][4];
#pragma unroll
    for (int i = 0; i < 2; i++)
#pragma unroll
        for (int j = 0; j < 4; j++) wmma::fill_fragment(acc[i][j], 0.f);

    auto fill = [&](int st, int kb) {
#pragma unroll
        for (int it = 0; it < 12; it++) {
            int gslot = it * 256 + tid;
            int t = gslot >> 10, slot = gslot & 1023;
            int row = slot >> 3, ko = slot & 7;
            const __half* src =
                (t == 0 ? AH + abase : t == 1 ? AL + abase : BH + bbase)
                + (size_t)row * 1024 + kb + ko * 8;
            uint32_t dst = smb + st * 55296 + t * 18432 + row * 144 + ko * 16;
            CP16(dst, src);
        }
        CPCOMMIT();
    };

    fill(0, 0);
    for (int ib = 0; ib < 16; ib++) {
        if (ib < 15) { fill((ib + 1) & 1, (ib + 1) * 64); CPWAIT1(); }
        else         { CPWAIT0(); }
        __syncthreads();
        const __half* Ah = (const __half*)(sm + (ib & 1) * 55296);
        const __half* Al = Ah + 128 * 72;
        const __half* Bh = Al + 128 * 72;
#pragma unroll
        for (int ks = 0; ks < 4; ks++) {
            int k0 = ks * 16;
            wmma::fragment<wmma::matrix_a, 16, 16, 16, __half, wmma::row_major> fah[2], fal[2];
#pragma unroll
            for (int m = 0; m < 2; m++) {
                wmma::load_matrix_sync(fah[m], Ah + (wm * 32 + m * 16) * 72 + k0, 72);
                wmma::load_matrix_sync(fal[m], Al + (wm * 32 + m * 16) * 72 + k0, 72);
            }
#pragma unroll
            for (int n = 0; n < 4; n++) {
                wmma::fragment<wmma::matrix_b, 16, 16, 16, __half, wmma::col_major> fbh;
                wmma::load_matrix_sync(fbh, Bh + (wn * 64 + n * 16) * 72 + k0, 72);
#pragma unroll
                for (int m = 0; m < 2; m++) {
                    wmma::mma_sync(acc[m][n], fah[m], fbh, acc[m][n]);
                    wmma::mma_sync(acc[m][n], fal[m], fbh, acc[m][n]);
                }
            }
        }
        __syncthreads();
    }

    // stage D[128 tokens][128 cols] (cols 0..63 raw K, 64..127 V), stride 132
    float* S = (float*)sm;
#pragma unroll
    for (int m = 0; m < 2; m++)
#pragma unroll
        for (int n = 0; n < 4; n++)
            wmma::store_matrix_sync(S + (size_t)(wm * 32 + m * 16) * 132 + wn * 64 + n * 16,
                                    acc[m][n], 132, wmma::mem_row_major);
    __syncthreads();

    // convert: Kh[s][m] = fp16(relu(K*norm)+stab), Vh[s][n] = fp16(V)
    __half* Kh = (__half*)(sm + 67584);     // [128][72]
    __half* Vh = Kh + 128 * 72;             // [128][72]  (ends at 104448)
#pragma unroll
    for (int it = 0; it < 32; it++) {
        int e = it * 256 + tid;             // 8192
        int s = e >> 6, c = e & 63;
        Kh[s * 72 + c] = __float2half(fmaxf(S[s * 132 + c] * NORM_OBJ, 0.f) + STABF);
        Vh[s * 72 + c] = __float2half(S[s * 132 + 64 + c]);
    }
    __syncthreads();

    // epilogue GEMM: kv[64,64] = Kp^T (64x128) @ V (128x64) via WMMA
    // warp wid -> mf = wid>>1 (m-frag), nf0 = (wid&1)*2 (2 n-frags)
    int mf = wid >> 1, nf0 = (wid & 1) * 2;
    wmma::fragment<wmma::accumulator, 16, 16, 16, float> acc2[2];
    wmma::fill_fragment(acc2[0], 0.f);
    wmma::fill_fragment(acc2[1], 0.f);
#pragma unroll
    for (int ks = 0; ks < 8; ks++) {
        wmma::fragment<wmma::matrix_a, 16, 16, 16, __half, wmma::col_major> fa;
        wmma::load_matrix_sync(fa, Kh + (ks * 16) * 72 + mf * 16, 72);
#pragma unroll
        for (int n2 = 0; n2 < 2; n2++) {
            wmma::fragment<wmma::matrix_b, 16, 16, 16, __half, wmma::row_major> fb;
            wmma::load_matrix_sync(fb, Vh + (ks * 16) * 72 + (nf0 + n2) * 16, 72);
            wmma::mma_sync(acc2[n2], fa, fb, acc2[n2]);
        }
    }
    __syncthreads();                         // all Kh/Vh reads done
    float* Sout = (float*)(sm + 67584);      // [64][68], overwrites Kh
#pragma unroll
    for (int n2 = 0; n2 < 2; n2++)
        wmma::store_matrix_sync(Sout + (size_t)(mf * 16) * 68 + (nf0 + n2) * 16,
                                acc2[n2], 68, wmma::mem_row_major);
    __syncthreads();

    size_t pbase = ((((size_t)layer * 8 + (tile >> 6)) * 16 + h) * 64 + (tile & 63)) * 4160;
#pragma unroll
    for (int i = 0; i < 16; i++) {
        int e = tid * 16 + i;
        int m = e >> 6, d = e & 63;
        part[pbase + m * 64 + d] = Sout[m * 68 + d];
    }
    if (tid < 64) {
        float s = 0.f;
        for (int s2 = 0; s2 < 128; s2++)
            s += fmaxf(S[(size_t)s2 * 132 + tid] * NORM_OBJ, 0.f) + STABF;
        part[pbase + 4096 + tid] = s;
    }
}

__global__ void k_kv_reduce(const float* __restrict__ part, float* __restrict__ out)
{
    int j = blockIdx.x * 256 + threadIdx.x;
    if (j >= 4160) return;
    int bh = blockIdx.y, layer = blockIdx.z;
    size_t pb = ((size_t)layer * 128 + bh) * 64 * 4160;
    float s = 0.f;
#pragma unroll 8
    for (int t = 0; t < 64; t++) s += part[pb + (size_t)t * 4160 + j];
    out[((size_t)layer * 128 + bh) * 4160 + j] = s;
}

// ===== obj-stack GEMM on tensor cores: fp16x2 split, fused epilogues =====
__global__ __launch_bounds__(256) void k_hgemm128(
    const float* __restrict__ A, const float* __restrict__ B, float* __restrict__ C,
    int M, int N, int K, int mode, float scale,
    const float* __restrict__ bias, const float* __restrict__ aux)
{
    __shared__ __align__(16) char smem[46080];
    __half* Ah = (__half*)smem;
    __half* Al = Ah + 128 * 72;
    __half* Bs = Al + 128 * 72;
    float* S = (float*)smem;
    int tid = threadIdx.x, wid = tid >> 5;
    int wm = wid & 3, wn = wid >> 2;
    int m0 = blockIdx.y * 128, n0 = blockIdx.x * 64;

    wmma::fragment<wmma::accumulator, 16, 16, 16, float> acc[2][2];
#pragma unroll
    for (int i = 0; i < 2; i++)
#pragma unroll
        for (int j = 0; j < 2; j++) wmma::fill_fragment(acc[i][j], 0.f);

    for (int kb = 0; kb < K; kb += 64) {
#pragma unroll
        for (int it = 0; it < 8; it++) {
            int slot = it * 256 + tid;
            int row = slot >> 4, c4 = (slot & 15) * 4;
            float4 v = *(const float4*)(A + (size_t)(m0 + row) * K + kb + c4);
            float vv[4] = {v.x, v.y, v.z, v.w};
#pragma unroll
            for (int i = 0; i < 4; i++) {
                __half hi = __float2half(vv[i]);
                Ah[row * 72 + c4 + i] = hi;
                Al[row * 72 + c4 + i] = __float2half(vv[i] - __half2float(hi));
            }
        }
#pragma unroll
        for (int it = 0; it < 4; it++) {
            int slot = it * 256 + tid;
            int krow = slot >> 4, c4 = (slot & 15) * 4;
            float4 v = *(const float4*)(B + (size_t)(kb + krow) * N + n0 + c4);
            Bs[(c4 + 0) * 72 + krow] = __float2half(v.x);
            Bs[(c4 + 1) * 72 + krow] = __float2half(v.y);
            Bs[(c4 + 2) * 72 + krow] = __float2half(v.z);
            Bs[(c4 + 3) * 72 + krow] = __float2half(v.w);
        }
        __syncthreads();
#pragma unroll
        for (int ks = 0; ks < 4; ks++) {
            int k0 = ks * 16;
            wmma::fragment<wmma::matrix_a, 16, 16, 16, __half, wmma::row_major> fah[2], fal[2];
#pragma unroll
            for (int m = 0; m < 2; m++) {
                wmma::load_matrix_sync(fah[m], Ah + (wm * 32 + m * 16) * 72 + k0, 72);
                wmma::load_matrix_sync(fal[m], Al + (wm * 32 + m * 16) * 72 + k0, 72);
            }
#pragma unroll
            for (int n = 0; n < 2; n++) {
                wmma::fragment<wmma::matrix_b, 16, 16, 16, __half, wmma::col_major> fbh;
                wmma::load_matrix_sync(fbh, Bs + (wn * 32 + n * 16) * 72 + k0, 72);
#pragma unroll
                for (int m = 0; m < 2; m++) {
                    wmma::mma_sync(acc[m][n], fah[m], fbh, acc[m][n]);
                    wmma::mma_sync(acc[m][n], fal[m], fbh, acc[m][n]);
                }
            }
        }
        __syncthreads();
    }

#pragma unroll
    for (int m = 0; m < 2; m++)
#pragma unroll
        for (int n = 0; n < 2; n++)
            wmma::store_matrix_sync(S + (size_t)(wm * 32 + m * 16) * 68 + wn * 32 + n * 16,
                                    acc[m][n], 68, wmma::mem_row_major);
    __syncthreads();
#pragma unroll
    for (int it = 0; it < 32; it++) {
        int e = it * 256 + tid;
        int row = e >> 6, col = e & 63;
        int gm = m0 + row, gn = n0 + col;
        float v = S[row * 68 + col];
        if (mode == 1)      v = fmaxf(v + bias[gn], 0.f);
        else if (mode == 2) v = fmaxf(v + bias[gn], 0.f) + aux[(size_t)(gm & 127) * N + gn];
        else if (mode == 3) v = fmaxf(v * scale, 0.f) + STABF;
        else if (mode == 4) v = v + aux[(size_t)gm * N + gn];
        C[(size_t)gm * N + gn] = v;
    }
}

__global__ __launch_bounds__(256) void k_fav_apply(
    const float* __restrict__ qp, const float* __restrict__ kvg,
    float* __restrict__ fav, int layer)
{
    __shared__ float kvs[4096];
    __shared__ float kss[64];
    __shared__ float den[128];
    int h = blockIdx.x, b = blockIdx.y, tid = threadIdx.x;
    size_t base = ((size_t)layer * 128 + b * 16 + h) * 4160;
#pragma unroll
    for (int i = 0; i < 16; i++) kvs[tid + i * 256] = kvg[base + tid + i * 256];
    if (tid < 64) kss[tid] = kvg[base + 4096 + tid];
    __syncthreads();
    if (tid < 128) {
        const float* qr = qp + ((size_t)(b * 128 + tid)) * 1024 + h * 64;
        float s = 0.f;
#pragma unroll
        for (int m = 0; m < 64; m++) s += qr[m] * kss[m];
        den[tid] = s;
    }
    __syncthreads();
    int t = tid >> 1, d0 = (tid & 1) * 32;
    const float* qr = qp + ((size_t)(b * 128 + t)) * 1024 + h * 64;
    float a[32] = {};
    for (int m = 0; m < 64; m++) {
        float qv = qr[m];
#pragma unroll
        for (int j = 0; j < 32; j++) a[j] += qv * kvs[m * 64 + d0 + j];
    }
    float inv = 1.f / den[t];
    float* op = fav + ((size_t)(b * 128 + t)) * 1024 + h * 64 + d0;
#pragma unroll
    for (int j = 0; j < 32; j++) op[j] = a[j] * inv;
}

__global__ __launch_bounds__(256) void k_ln1024(
    const float* __restrict__ a, const float* __restrict__ b2,
    float* __restrict__ o, const float* __restrict__ g, const float* __restrict__ be)
{
    __shared__ float red[256];
    int row = blockIdx.x, tid = threadIdx.x;
    const float* ap = a + (size_t)row * 1024;
    float v[4];
    float s = 0.f;
#pragma unroll
    for (int j = 0; j < 4; j++) {
        int c = tid + j * 256;
        float x = ap[c];
        if (b2) x += b2[(size_t)row * 1024 + c];
        v[j] = x; s += x;
    }
    red[tid] = s; __syncthreads();
    for (int off = 128; off; off >>= 1) {
        if (tid < off) red[tid] += red[tid + off];
        __syncthreads();
    }
    float mu = red[0] * (1.f / 1024.f);
    __syncthreads();
    float s2 = 0.f;
#pragma unroll
    for (int j = 0; j < 4; j++) { float d = v[j] - mu; s2 += d * d; }
    red[tid] = s2; __syncthreads();
    for (int off = 128; off; off >>= 1) {
        if (tid < off) red[tid] += red[tid + off];
        __syncthreads();
    }
    float rs = rsqrtf(red[0] * (1.f / 1024.f) + LNEPS);
    float* op = o + (size_t)row * 1024;
#pragma unroll
    for (int j = 0; j < 4; j++) {
        int c = tid + j * 256;
        op[c] = (v[j] - mu) * rs * g[c] + be[c];
    }
}

// =================== launch ===================
extern "C" void kernel_launch(void* const* d_in, const int* in_sizes, int n_in,
                              void* d_out, int out_size)
{
    const float* obj_inputs  = (const float*)d_in[0];
    const float* road_inputs = (const float*)d_in[1];
    const float* rg_dense_W  = (const float*)d_in[2];
    const float* rg_dense_b  = (const float*)d_in[3];
    const float* rg_qkv_W    = (const float*)d_in[4];
    const float* rg_qkv_b    = (const float*)d_in[5];
    const float* rg_Wq       = (const float*)d_in[6];
    const float* rg_Wk       = (const float*)d_in[7];
    const float* rg_Wv       = (const float*)d_in[8];
    const float* rg_Wo       = (const float*)d_in[9];
    const float* rg_ln_g     = (const float*)d_in[10];
    const float* rg_ln_b     = (const float*)d_in[11];
    const float* rg_fc_W     = (const float*)d_in[12];
    const float* rg_fc_b     = (const float*)d_in[13];
    const float* rg_out_W    = (const float*)d_in[14];
    const float* rg_out_b    = (const float*)d_in[15];
    const float* dense_W     = (const float*)d_in[16];
    const float* dense_b     = (const float*)d_in[17];
    const float* pos_emb     = (const float*)d_in[18];
    const float* Wq          = (const float*)d_in[19];
    const float* Wk          = (const float*)d_in[20];
    const float* Wv          = (const float*)d_in[21];
    const float* Wo          = (const float*)d_in[22];
    const float* ln_g        = (const float*)d_in[23];
    const float* ln_b        = (const float*)d_in[24];
    const float* fc_W        = (const float*)d_in[25];
    const float* fc_b        = (const float*)d_in[26];
    float* out = (float*)d_out;

    float* base = nullptr;
    cudaGetSymbolAddress((void**)&base, g_s);
    float* roadx  = base + OFF_ROADX;
    float* roadq  = base + OFF_ROADQ;
    float* rpart  = base + OFF_RPART;
    float* rgkv   = base + OFF_RGKV;
    __half* AH = (__half*)(base + OFF_AH);
    __half* AL = (__half*)(base + OFF_AL);
    __half* BH = (__half*)(base + OFF_BH);
    float* kvpart = base + OFF_KVPART;
    float* objkv  = base + OFF_OBJKV;
    float* xo     = base + OFF_XO;
    float* qpbuf  = base + OFF_QP;
    float* favb   = base + OFF_FAV;
    float* attnb  = base + OFF_ATTN;
    float* nbuf   = base + OFF_N;
    float* ybuf   = base + OFF_Y;

    cudaFuncSetAttribute(k_kv_mma, cudaFuncAttributeMaxDynamicSharedMemorySize, 110592);

    // road stack
    k_road_dense<<<256, 256>>>(road_inputs, rg_dense_W, rg_dense_b, roadx);
    for (int i = 0; i < 2; i++) {
        k_road_favA<<<256, 256>>>(roadx, roadq, rg_qkv_W, rg_qkv_b,
                                  rg_Wk + i * 256, rg_Wv + i * 256, rpart);
        k_road_reduce<<<8, 80>>>(rpart, rgkv);
        k_road_favB<<<256, 256>>>(roadx, roadq, rg_Wq + i * 256, rg_Wo + i * 256,
                                  rgkv, rg_ln_g + i * 16, rg_ln_b + i * 16,
                                  rg_fc_W + i * 256, rg_fc_b + i * 16);
    }
    k_wpack2<<<dim3(16, 32, 2), 256>>>(Wk, Wv, BH);
    k_rg_expand_split<<<4096, 256>>>(roadx, rg_out_W, rg_out_b, AH, AL);

    // heavy tensor-core K/V + FAVOR reduction
    k_kv_mma<<<dim3(16, 512, 2), 256, 110592>>>(AH, AL, BH, kvpart);
    k_kv_reduce<<<dim3(17, 128, 2), 256>>>(kvpart, objkv);

    // obj stack (tensor-core GEMMs)
    k_hgemm128<<<dim3(16, 8), 256>>>(obj_inputs, dense_W, xo,
                                     1024, 1024, 512, 2, 0.f, dense_b, pos_emb);
    for (int i = 0; i < 2; i++) {
        k_hgemm128<<<dim3(16, 8), 256>>>(xo, Wq + (size_t)i * 1048576, qpbuf,
                                         1024, 1024, 1024, 3, NORM_OBJ, nullptr, nullptr);
        k_fav_apply<<<dim3(16, 8), 256>>>(qpbuf, objkv, favb, i);
        k_hgemm128<<<dim3(16, 8), 256>>>(favb, Wo + (size_t)i * 1048576, attnb,
                                         1024, 1024, 1024, 4, 0.f, nullptr, xo);
        k_ln1024<<<1024, 256>>>(attnb, nullptr, nbuf, ln_g + i * 1024, ln_b + i * 1024);
        k_hgemm128<<<dim3(16, 8), 256>>>(nbuf, fc_W + (size_t)i * 1048576, ybuf,
                                         1024, 1024, 1024, 1, 0.f, fc_b + i * 1024, nullptr);
        k_ln1024<<<1024, 256>>>(nbuf, ybuf, (i == 0) ? xo : out,
                                ln_g + i * 1024, ln_b + i * 1024);
    }
}

// round 16
// speedup vs baseline: 5.1347x; 1.4177x over previous
#include <cuda_runtime.h>
#include <cuda_fp16.h>
#include <mma.h>
#include <cstdint>
#include <cstddef>

using namespace nvcuda;

#define NORM_RG   0.70710678118654752f
#define NORM_OBJ  0.35355339059327376f
#define STABF     0.001f
#define LNEPS     0.001f

// ---------------- scratch layout (float offsets) ----------------
static constexpr size_t OFF_ROADX  = 0;
static constexpr size_t OFF_ROADQ  = OFF_ROADX  + 1048576;
static constexpr size_t OFF_RPART  = OFF_ROADQ  + 1048576;
static constexpr size_t OFF_RGKV   = OFF_RPART  + 20480;
static constexpr size_t OFF_AH     = OFF_RGKV   + 640;
static constexpr size_t OFF_AL     = OFF_AH     + 33554432;   // (unused)
static constexpr size_t OFF_BH     = OFF_AL     + 33554432;
static constexpr size_t OFF_BL     = OFF_BH     + 2097152;    // (unused)
static constexpr size_t OFF_KVPART = OFF_BL     + 2097152;
static constexpr size_t OFF_OBJKV  = OFF_KVPART + 68157440;
static constexpr size_t OFF_XO     = OFF_OBJKV  + 1064960;
static constexpr size_t OFF_QP     = OFF_XO     + 1048576;
static constexpr size_t OFF_FAV    = OFF_QP     + 1048576;
static constexpr size_t OFF_ATTN   = OFF_FAV    + 1048576;
static constexpr size_t OFF_N      = OFF_ATTN   + 1048576;
static constexpr size_t OFF_Y      = OFF_N      + 1048576;
static constexpr size_t SCRATCH_FLOATS = OFF_Y + 1048576;

__device__ __align__(256) float g_s[SCRATCH_FLOATS];

// cp.async helpers
#define CP16(dst, src) asm volatile("cp.async.ca.shared.global [%0], [%1], 16;" :: "r"(dst), "l"(src))
#define CPCOMMIT() asm volatile("cp.async.commit_group;" ::: "memory")
#define CPWAIT2() asm volatile("cp.async.wait_group 2;" ::: "memory")
#define CPWAIT1() asm volatile("cp.async.wait_group 1;" ::: "memory")
#define CPWAIT0() asm volatile("cp.async.wait_group 0;" ::: "memory")

// =================== road stack (verified R3-R10) ===================
__global__ __launch_bounds__(256) void k_road_dense(
    const float* __restrict__ rin, const float* __restrict__ W,
    const float* __restrict__ b, float* __restrict__ xout)
{
    __shared__ float Ws[128], bs[16];
    int tid = threadIdx.x;
    if (tid < 128) Ws[tid] = W[tid];
    if (tid < 16)  bs[tid] = b[tid];
    __syncthreads();
    size_t tok = (size_t)blockIdx.x * 256 + tid;
    const float4* rp = (const float4*)(rin + tok * 8);
    float4 a0 = rp[0], a1 = rp[1];
    float x[8] = {a0.x, a0.y, a0.z, a0.w, a1.x, a1.y, a1.z, a1.w};
    float o[16];
#pragma unroll
    for (int c = 0; c < 16; c++) {
        float s = bs[c];
#pragma unroll
        for (int d = 0; d < 8; d++) s += x[d] * Ws[d * 16 + c];
        o[c] = fmaxf(s, 0.f);
    }
    float4* op = (float4*)(xout + tok * 16);
    op[0] = make_float4(o[0], o[1], o[2], o[3]);
    op[1] = make_float4(o[4], o[5], o[6], o[7]);
    op[2] = make_float4(o[8], o[9], o[10], o[11]);
    op[3] = make_float4(o[12], o[13], o[14], o[15]);
}

__global__ __launch_bounds__(256) void k_road_favA(
    const float* __restrict__ xin, float* __restrict__ qout,
    const float* __restrict__ qkvW, const float* __restrict__ qkvb,
    const float* __restrict__ Wk, const float* __restrict__ Wv,
    float* __restrict__ part)
{
    __shared__ float W16[256], b16[16], Wks[256], Wvs[256];
    __shared__ float wred[8 * 80];
    int tid = threadIdx.x;
    W16[tid] = qkvW[(tid >> 4) * 48 + (tid & 15)];
    Wks[tid] = Wk[tid];
    Wvs[tid] = Wv[tid];
    if (tid < 16) b16[tid] = qkvb[tid];
    __syncthreads();
    size_t tok = (size_t)blockIdx.x * 256 + tid;
    const float4* xp = (const float4*)(xin + tok * 16);
    float4 x0 = xp[0], x1 = xp[1], x2 = xp[2], x3 = xp[3];
    float x[16] = {x0.x, x0.y, x0.z, x0.w, x1.x, x1.y, x1.z, x1.w,
                   x2.x, x2.y, x2.z, x2.w, x3.x, x3.y, x3.z, x3.w};
    float q[16];
#pragma unroll
    for (int c = 0; c < 16; c++) {
        float s = b16[c];
#pragma unroll
        for (int d = 0; d < 16; d++) s += x[d] * W16[d * 16 + c];
        q[c] = fmaxf(s, 0.f);
    }
    float4* qo = (float4*)(qout + tok * 16);
    qo[0] = make_float4(q[0], q[1], q[2], q[3]);
    qo[1] = make_float4(q[4], q[5], q[6], q[7]);
    qo[2] = make_float4(q[8], q[9], q[10], q[11]);
    qo[3] = make_float4(q[12], q[13], q[14], q[15]);
    float kp[16], vh[16];
#pragma unroll
    for (int j = 0; j < 16; j++) {
        float sk = 0.f, sv = 0.f;
#pragma unroll
        for (int d = 0; d < 16; d++) {
            sk += q[d] * Wks[d * 16 + j];
            sv += q[d] * Wvs[d * 16 + j];
        }
        kp[j] = fmaxf(sk * NORM_RG, 0.f) + STABF;
        vh[j] = sv;
    }
    int lane = tid & 31, w = tid >> 5;
#pragma unroll
    for (int i = 0; i < 64; i++) {
        int hm = i >> 2;
        float v = kp[hm] * vh[(hm & 12) | (i & 3)];
#pragma unroll
        for (int off = 16; off > 0; off >>= 1) v += __shfl_down_sync(0xffffffffu, v, off);
        if (lane == 0) wred[w * 80 + i] = v;
    }
#pragma unroll
    for (int i = 0; i < 16; i++) {
        float v = kp[i];
#pragma unroll
        for (int off = 16; off > 0; off >>= 1) v += __shfl_down_sync(0xffffffffu, v, off);
        if (lane == 0) wred[w * 80 + 64 + i] = v;
    }
    __syncthreads();
    if (tid < 80) {
        float s = 0.f;
#pragma unroll
        for (int w2 = 0; w2 < 8; w2++) s += wred[w2 * 80 + tid];
        part[(size_t)blockIdx.x * 80 + tid] = s;
    }
}

__global__ void k_road_reduce(const float* __restrict__ part, float* __restrict__ kvout)
{
    int b = blockIdx.x, tid = threadIdx.x;
    float s = 0.f;
    for (int k = 0; k < 32; k++) s += part[(size_t)(b * 32 + k) * 80 + tid];
    kvout[(size_t)b * 80 + tid] = s;
}

__global__ __launch_bounds__(256) void k_road_favB(
    float* __restrict__ x, const float* __restrict__ qbuf,
    const float* __restrict__ Wq, const float* __restrict__ Wo,
    const float* __restrict__ kvg,
    const float* __restrict__ lng, const float* __restrict__ lnb,
    const float* __restrict__ fcW, const float* __restrict__ fcb)
{
    __shared__ float Wqs[256], Wos[256], fcWs[256];
    __shared__ float fcbs[16], gs[16], bbs[16], kvs[64], kss[16];
    int tid = threadIdx.x;
    Wqs[tid] = Wq[tid];
    Wos[tid] = Wo[tid];
    fcWs[tid] = fcW[tid];
    if (tid < 16) { fcbs[tid] = fcb[tid]; gs[tid] = lng[tid]; bbs[tid] = lnb[tid]; }
    int b = blockIdx.x >> 5;
    if (tid < 64) kvs[tid] = kvg[(size_t)b * 80 + tid];
    if (tid < 16) kss[tid] = kvg[(size_t)b * 80 + 64 + tid];
    __syncthreads();
    size_t tok = (size_t)blockIdx.x * 256 + tid;
    const float4* qp4 = (const float4*)(qbuf + tok * 16);
    float4 q0 = qp4[0], q1 = qp4[1], q2 = qp4[2], q3 = qp4[3];
    float q[16] = {q0.x, q0.y, q0.z, q0.w, q1.x, q1.y, q1.z, q1.w,
                   q2.x, q2.y, q2.z, q2.w, q3.x, q3.y, q3.z, q3.w};
    float qp[16];
#pragma unroll
    for (int j = 0; j < 16; j++) {
        float s = 0.f;
#pragma unroll
        for (int d = 0; d < 16; d++) s += q[d] * Wqs[d * 16 + j];
        qp[j] = fmaxf(s * NORM_RG, 0.f) + STABF;
    }
    float outv[16];
#pragma unroll
    for (int h = 0; h < 4; h++) {
        float den = 0.f;
#pragma unroll
        for (int m = 0; m < 4; m++) den += qp[h * 4 + m] * kss[h * 4 + m];
        float inv = 1.f / den;
#pragma unroll
        for (int d = 0; d < 4; d++) {
            float nu = 0.f;
#pragma unroll
            for (int m = 0; m < 4; m++) nu += qp[h * 4 + m] * kvs[(h * 4 + m) * 4 + d];
            outv[h * 4 + d] = nu * inv;
        }
    }
    float attn[16];
#pragma unroll
    for (int e = 0; e < 16; e++) {
        float s = 0.f;
#pragma unroll
        for (int j = 0; j < 16; j++) s += outv[j] * Wos[j * 16 + e];
        attn[e] = s;
    }
    const float4* xp = (const float4*)(x + tok * 16);
    float4 x0 = xp[0], x1 = xp[1], x2 = xp[2], x3 = xp[3];
    float xv[16] = {x0.x, x0.y, x0.z, x0.w, x1.x, x1.y, x1.z, x1.w,
                    x2.x, x2.y, x2.z, x2.w, x3.x, x3.y, x3.z, x3.w};
    float t1[16];
#pragma unroll
    for (int c = 0; c < 16; c++) t1[c] = attn[c] + xv[c];
    float mu = 0.f;
#pragma unroll
    for (int c = 0; c < 16; c++) mu += t1[c];
    mu *= (1.f / 16.f);
    float var = 0.f;
#pragma unroll
    for (int c = 0; c < 16; c++) { float d = t1[c] - mu; var += d * d; }
    var *= (1.f / 16.f);
    float rs = rsqrtf(var + LNEPS);
    float nn[16];
#pragma unroll
    for (int c = 0; c < 16; c++) nn[c] = (t1[c] - mu) * rs * gs[c] + bbs[c];
    float y[16];
#pragma unroll
    for (int c = 0; c < 16; c++) {
        float s = fcbs[c];
#pragma unroll
        for (int d = 0; d < 16; d++) s += nn[d] * fcWs[d * 16 + c];
        y[c] = fmaxf(s, 0.f);
    }
    float t2[16];
#pragma unroll
    for (int c = 0; c < 16; c++) t2[c] = nn[c] + y[c];
    mu = 0.f;
#pragma unroll
    for (int c = 0; c < 16; c++) mu += t2[c];
    mu *= (1.f / 16.f);
    var = 0.f;
#pragma unroll
    for (int c = 0; c < 16; c++) { float d = t2[c] - mu; var += d * d; }
    var *= (1.f / 16.f);
    rs = rsqrtf(var + LNEPS);
    float o[16];
#pragma unroll
    for (int c = 0; c < 16; c++) o[c] = (t2[c] - mu) * rs * gs[c] + bbs[c];
    float4* op = (float4*)(x + tok * 16);
    op[0] = make_float4(o[0], o[1], o[2], o[3]);
    op[1] = make_float4(o[4], o[5], o[6], o[7]);
    op[2] = make_float4(o[8], o[9], o[10], o[11]);
    op[3] = make_float4(o[12], o[13], o[14], o[15]);
}

// rg_out = relu(x16 @ W + b), emitted as fp16 (single term)
__global__ __launch_bounds__(256) void k_rg_expand_h(
    const float* __restrict__ x, const float* __restrict__ W,
    const float* __restrict__ b, __half* __restrict__ AH)
{
    __shared__ float xs[256];
    int tid = threadIdx.x;
    size_t tok0 = (size_t)blockIdx.x * 16;
    xs[tid] = x[tok0 * 16 + tid];
    __syncthreads();
    int c0 = tid * 4;
    float4 wv[16];
#pragma unroll
    for (int d = 0; d < 16; d++) wv[d] = *(const float4*)(W + d * 1024 + c0);
    float4 bb = *(const float4*)(b + c0);
#pragma unroll 4
    for (int tk = 0; tk < 16; tk++) {
        float4 a = bb;
#pragma unroll
        for (int d = 0; d < 16; d++) {
            float xv = xs[tk * 16 + d];
            a.x += xv * wv[d].x; a.y += xv * wv[d].y;
            a.z += xv * wv[d].z; a.w += xv * wv[d].w;
        }
        size_t base = (tok0 + tk) * 1024 + c0;
        __half h0 = __float2half(fmaxf(a.x, 0.f));
        __half h1 = __float2half(fmaxf(a.y, 0.f));
        __half h2 = __float2half(fmaxf(a.z, 0.f));
        __half h3 = __float2half(fmaxf(a.w, 0.f));
        *(__half2*)(AH + base)     = __half2{h0, h1};
        *(__half2*)(AH + base + 2) = __half2{h2, h3};
    }
}

// pack Wk|Wv (N,H,h,d) -> B [layer][h][n=128][k=1024] fp16, coalesced transpose
__global__ __launch_bounds__(256) void k_wpack2(
    const float* __restrict__ Wk, const float* __restrict__ Wv,
    __half* __restrict__ BH)
{
    __shared__ float ws[32 * 129];
    int h = blockIdx.x, kb = blockIdx.y, l = blockIdx.z;
    int tid = threadIdx.x;
#pragma unroll
    for (int it = 0; it < 16; it++) {
        int slot = it * 256 + tid;
        int kr = slot >> 7, c = slot & 127;
        const float* W = (c < 64) ? Wk : Wv;
        ws[kr * 129 + c] = W[(size_t)l * 1048576 + (size_t)(kb * 32 + kr) * 1024 + h * 64 + (c & 63)];
    }
    __syncthreads();
#pragma unroll
    for (int it = 0; it < 16; it++) {
        int slot = it * 256 + tid;
        int n = slot >> 5, kk = slot & 31;
        BH[((size_t)(l * 16 + h) * 128 + n) * 1024 + kb * 32 + kk] = __float2half(ws[kk * 129 + n]);
    }
}

// ====== heavy kernel: WMMA fp16 (1-term) K/V projection, 3-stage pipeline ======
// grid (h=16, tile=512, layer=2), 256 thr, dyn smem 110592 (3 stages x 36864)
__global__ __launch_bounds__(256) void k_kv_mma(
    const __half* __restrict__ AH, const __half* __restrict__ BH,
    float* __restrict__ part)
{
    extern __shared__ char sm[];
    int h = blockIdx.x, tile = blockIdx.y, layer = blockIdx.z;
    int tid = threadIdx.x, wid = tid >> 5;
    int wm = wid & 3, wn = wid >> 2;
    size_t abase = (size_t)tile * 128 * 1024;
    size_t bbase = (size_t)(layer * 16 + h) * 128 * 1024;
    uint32_t smb = (uint32_t)__cvta_generic_to_shared(sm);

    wmma::fragment<wmma::accumulator, 16, 16, 16, float> acc[2][4];
#pragma unroll
    for (int i = 0; i < 2; i++)
#pragma unroll
        for (int j = 0; j < 4; j++) wmma::fill_fragment(acc[i][j], 0.f);

    // stage layout: st*36864 + {A[128][72] fp16, B[128][72] fp16}
    auto fill = [&](int st, int kb) {
#pragma unroll
        for (int it = 0; it < 8; it++) {
            int gslot = it * 256 + tid;          // 2048 x 16B chunks
            int t = gslot >> 10, slot = gslot & 1023;
            int row = slot >> 3, ko = slot & 7;
            const __half* src = (t == 0 ? AH + abase : BH + bbase)
                                + (size_t)row * 1024 + kb + ko * 8;
            uint32_t dst = smb + st * 36864 + t * 18432 + row * 144 + ko * 16;
            CP16(dst, src);
        }
        CPCOMMIT();
    };

    fill(0, 0);
    fill(1, 64);
    for (int ib = 0; ib < 16; ib++) {
        if (ib < 14) { fill((ib + 2) % 3, (ib + 2) * 64); CPWAIT2(); }
        else if (ib == 14) CPWAIT1();
        else CPWAIT0();
        __syncthreads();
        const __half* Ah = (const __half*)(sm + (ib % 3) * 36864);
        const __half* Bh = Ah + 128 * 72;
#pragma unroll
        for (int ks = 0; ks < 4; ks++) {
            int k0 = ks * 16;
            wmma::fragment<wmma::matrix_a, 16, 16, 16, __half, wmma::row_major> fah[2];
#pragma unroll
            for (int m = 0; m < 2; m++)
                wmma::load_matrix_sync(fah[m], Ah + (wm * 32 + m * 16) * 72 + k0, 72);
#pragma unroll
            for (int n = 0; n < 4; n++) {
                wmma::fragment<wmma::matrix_b, 16, 16, 16, __half, wmma::col_major> fbh;
                wmma::load_matrix_sync(fbh, Bh + (wn * 64 + n * 16) * 72 + k0, 72);
#pragma unroll
                for (int m = 0; m < 2; m++)
                    wmma::mma_sync(acc[m][n], fah[m], fbh, acc[m][n]);
            }
        }
        __syncthreads();
    }

    // stage D[128 tokens][128 cols] (cols 0..63 raw K, 64..127 V), stride 132
    float* S = (float*)sm;
#pragma unroll
    for (int m = 0; m < 2; m++)
#pragma unroll
        for (int n = 0; n < 4; n++)
            wmma::store_matrix_sync(S + (size_t)(wm * 32 + m * 16) * 132 + wn * 64 + n * 16,
                                    acc[m][n], 132, wmma::mem_row_major);
    __syncthreads();

    // convert: Kh[s][m] = fp16(relu(K*norm)+stab), Vh[s][n] = fp16(V)
    __half* Kh = (__half*)(sm + 67584);     // [128][72]
    __half* Vh = Kh + 128 * 72;             // ends at 104448 < 110592
#pragma unroll
    for (int it = 0; it < 32; it++) {
        int e = it * 256 + tid;             // 8192
        int s = e >> 6, c = e & 63;
        Kh[s * 72 + c] = __float2half(fmaxf(S[s * 132 + c] * NORM_OBJ, 0.f) + STABF);
        Vh[s * 72 + c] = __float2half(S[s * 132 + 64 + c]);
    }
    __syncthreads();

    // epilogue GEMM: kv[64,64] = Kp^T (64x128) @ V (128x64) via WMMA
    int mf = wid >> 1, nf0 = (wid & 1) * 2;
    wmma::fragment<wmma::accumulator, 16, 16, 16, float> acc2[2];
    wmma::fill_fragment(acc2[0], 0.f);
    wmma::fill_fragment(acc2[1], 0.f);
#pragma unroll
    for (int ks = 0; ks < 8; ks++) {
        wmma::fragment<wmma::matrix_a, 16, 16, 16, __half, wmma::col_major> fa;
        wmma::load_matrix_sync(fa, Kh + (ks * 16) * 72 + mf * 16, 72);
#pragma unroll
        for (int n2 = 0; n2 < 2; n2++) {
            wmma::fragment<wmma::matrix_b, 16, 16, 16, __half, wmma::row_major> fb;
            wmma::load_matrix_sync(fb, Vh + (ks * 16) * 72 + (nf0 + n2) * 16, 72);
            wmma::mma_sync(acc2[n2], fa, fb, acc2[n2]);
        }
    }
    __syncthreads();
    float* Sout = (float*)(sm + 67584);      // [64][68], overwrites Kh
#pragma unroll
    for (int n2 = 0; n2 < 2; n2++)
        wmma::store_matrix_sync(Sout + (size_t)(mf * 16) * 68 + (nf0 + n2) * 16,
                                acc2[n2], 68, wmma::mem_row_major);
    __syncthreads();

    size_t pbase = ((((size_t)layer * 8 + (tile >> 6)) * 16 + h) * 64 + (tile & 63)) * 4160;
#pragma unroll
    for (int i = 0; i < 16; i++) {
        int e = tid * 16 + i;
        int m = e >> 6, d = e & 63;
        part[pbase + m * 64 + d] = Sout[m * 68 + d];
    }
    if (tid < 64) {
        float s = 0.f;
        for (int s2 = 0; s2 < 128; s2++)
            s += fmaxf(S[(size_t)s2 * 132 + tid] * NORM_OBJ, 0.f) + STABF;
        part[pbase + 4096 + tid] = s;
    }
}

__global__ void k_kv_reduce(const float* __restrict__ part, float* __restrict__ out)
{
    int j = blockIdx.x * 256 + threadIdx.x;
    if (j >= 4160) return;
    int bh = blockIdx.y, layer = blockIdx.z;
    size_t pb = ((size_t)layer * 128 + bh) * 64 * 4160;
    float s = 0.f;
#pragma unroll 8
    for (int t = 0; t < 64; t++) s += part[pb + (size_t)t * 4160 + j];
    out[((size_t)layer * 128 + bh) * 4160 + j] = s;
}

// ===== obj-stack GEMM on tensor cores: fp16x2 split, fused epilogues =====
__global__ __launch_bounds__(256) void k_hgemm128(
    const float* __restrict__ A, const float* __restrict__ B, float* __restrict__ C,
    int M, int N, int K, int mode, float scale,
    const float* __restrict__ bias, const float* __restrict__ aux)
{
    __shared__ __align__(16) char smem[46080];
    __half* Ah = (__half*)smem;
    __half* Al = Ah + 128 * 72;
    __half* Bs = Al + 128 * 72;
    float* S = (float*)smem;
    int tid = threadIdx.x, wid = tid >> 5;
    int wm = wid & 3, wn = wid >> 2;
    int m0 = blockIdx.y * 128, n0 = blockIdx.x * 64;

    wmma::fragment<wmma::accumulator, 16, 16, 16, float> acc[2][2];
#pragma unroll
    for (int i = 0; i < 2; i++)
#pragma unroll
        for (int j = 0; j < 2; j++) wmma::fill_fragment(acc[i][j], 0.f);

    for (int kb = 0; kb < K; kb += 64) {
#pragma unroll
        for (int it = 0; it < 8; it++) {
            int slot = it * 256 + tid;
            int row = slot >> 4, c4 = (slot & 15) * 4;
            float4 v = *(const float4*)(A + (size_t)(m0 + row) * K + kb + c4);
            float vv[4] = {v.x, v.y, v.z, v.w};
#pragma unroll
            for (int i = 0; i < 4; i++) {
                __half hi = __float2half(vv[i]);
                Ah[row * 72 + c4 + i] = hi;
                Al[row * 72 + c4 + i] = __float2half(vv[i] - __half2float(hi));
            }
        }
#pragma unroll
        for (int it = 0; it < 4; it++) {
            int slot = it * 256 + tid;
            int krow = slot >> 4, c4 = (slot & 15) * 4;
            float4 v = *(const float4*)(B + (size_t)(kb + krow) * N + n0 + c4);
            Bs[(c4 + 0) * 72 + krow] = __float2half(v.x);
            Bs[(c4 + 1) * 72 + krow] = __float2half(v.y);
            Bs[(c4 + 2) * 72 + krow] = __float2half(v.z);
            Bs[(c4 + 3) * 72 + krow] = __float2half(v.w);
        }
        __syncthreads();
#pragma unroll
        for (int ks = 0; ks < 4; ks++) {
            int k0 = ks * 16;
            wmma::fragment<wmma::matrix_a, 16, 16, 16, __half, wmma::row_major> fah[2], fal[2];
#pragma unroll
            for (int m = 0; m < 2; m++) {
                wmma::load_matrix_sync(fah[m], Ah + (wm * 32 + m * 16) * 72 + k0, 72);
                wmma::load_matrix_sync(fal[m], Al + (wm * 32 + m * 16) * 72 + k0, 72);
            }
#pragma unroll
            for (int n = 0; n < 2; n++) {
                wmma::fragment<wmma::matrix_b, 16, 16, 16, __half, wmma::col_major> fbh;
                wmma::load_matrix_sync(fbh, Bs + (wn * 32 + n * 16) * 72 + k0, 72);
#pragma unroll
                for (int m = 0; m < 2; m++) {
                    wmma::mma_sync(acc[m][n], fah[m], fbh, acc[m][n]);
                    wmma::mma_sync(acc[m][n], fal[m], fbh, acc[m][n]);
                }
            }
        }
        __syncthreads();
    }

#pragma unroll
    for (int m = 0; m < 2; m++)
#pragma unroll
        for (int n = 0; n < 2; n++)
            wmma::store_matrix_sync(S + (size_t)(wm * 32 + m * 16) * 68 + wn * 32 + n * 16,
                                    acc[m][n], 68, wmma::mem_row_major);
    __syncthreads();
#pragma unroll
    for (int it = 0; it < 32; it++) {
        int e = it * 256 + tid;
        int row = e >> 6, col = e & 63;
        int gm = m0 + row, gn = n0 + col;
        float v = S[row * 68 + col];
        if (mode == 1)      v = fmaxf(v + bias[gn], 0.f);
        else if (mode == 2) v = fmaxf(v + bias[gn], 0.f) + aux[(size_t)(gm & 127) * N + gn];
        else if (mode == 3) v = fmaxf(v * scale, 0.f) + STABF;
        else if (mode == 4) v = v + aux[(size_t)gm * N + gn];
        C[(size_t)gm * N + gn] = v;
    }
}

__global__ __launch_bounds__(256) void k_fav_apply(
    const float* __restrict__ qp, const float* __restrict__ kvg,
    float* __restrict__ fav, int layer)
{
    __shared__ float kvs[4096];
    __shared__ float kss[64];
    __shared__ float den[128];
    int h = blockIdx.x, b = blockIdx.y, tid = threadIdx.x;
    size_t base = ((size_t)layer * 128 + b * 16 + h) * 4160;
#pragma unroll
    for (int i = 0; i < 16; i++) kvs[tid + i * 256] = kvg[base + tid + i * 256];
    if (tid < 64) kss[tid] = kvg[base + 4096 + tid];
    __syncthreads();
    if (tid < 128) {
        const float* qr = qp + ((size_t)(b * 128 + tid)) * 1024 + h * 64;
        float s = 0.f;
#pragma unroll
        for (int m = 0; m < 64; m++) s += qr[m] * kss[m];
        den[tid] = s;
    }
    __syncthreads();
    int t = tid >> 1, d0 = (tid & 1) * 32;
    const float* qr = qp + ((size_t)(b * 128 + t)) * 1024 + h * 64;
    float a[32] = {};
    for (int m = 0; m < 64; m++) {
        float qv = qr[m];
#pragma unroll
        for (int j = 0; j < 32; j++) a[j] += qv * kvs[m * 64 + d0 + j];
    }
    float inv = 1.f / den[t];
    float* op = fav + ((size_t)(b * 128 + t)) * 1024 + h * 64 + d0;
#pragma unroll
    for (int j = 0; j < 32; j++) op[j] = a[j] * inv;
}

__global__ __launch_bounds__(256) void k_ln1024(
    const float* __restrict__ a, const float* __restrict__ b2,
    float* __restrict__ o, const float* __restrict__ g, const float* __restrict__ be)
{
    __shared__ float red[256];
    int row = blockIdx.x, tid = threadIdx.x;
    const float* ap = a + (size_t)row * 1024;
    float v[4];
    float s = 0.f;
#pragma unroll
    for (int j = 0; j < 4; j++) {
        int c = tid + j * 256;
        float x = ap[c];
        if (b2) x += b2[(size_t)row * 1024 + c];
        v[j] = x; s += x;
    }
    red[tid] = s; __syncthreads();
    for (int off = 128; off; off >>= 1) {
        if (tid < off) red[tid] += red[tid + off];
        __syncthreads();
    }
    float mu = red[0] * (1.f / 1024.f);
    __syncthreads();
    float s2 = 0.f;
#pragma unroll
    for (int j = 0; j < 4; j++) { float d = v[j] - mu; s2 += d * d; }
    red[tid] = s2; __syncthreads();
    for (int off = 128; off; off >>= 1) {
        if (tid < off) red[tid] += red[tid + off];
        __syncthreads();
    }
    float rs = rsqrtf(red[0] * (1.f / 1024.f) + LNEPS);
    float* op = o + (size_t)row * 1024;
#pragma unroll
    for (int j = 0; j < 4; j++) {
        int c = tid + j * 256;
        op[c] = (v[j] - mu) * rs * g[c] + be[c];
    }
}

// =================== launch ===================
extern "C" void kernel_launch(void* const* d_in, const int* in_sizes, int n_in,
                              void* d_out, int out_size)
{
    const float* obj_inputs  = (const float*)d_in[0];
    const float* road_inputs = (const float*)d_in[1];
    const float* rg_dense_W  = (const float*)d_in[2];
    const float* rg_dense_b  = (const float*)d_in[3];
    const float* rg_qkv_W    = (const float*)d_in[4];
    const float* rg_qkv_b    = (const float*)d_in[5];
    const float* rg_Wq       = (const float*)d_in[6];
    const float* rg_Wk       = (const float*)d_in[7];
    const float* rg_Wv       = (const float*)d_in[8];
    const float* rg_Wo       = (const float*)d_in[9];
    const float* rg_ln_g     = (const float*)d_in[10];
    const float* rg_ln_b     = (const float*)d_in[11];
    const float* rg_fc_W     = (const float*)d_in[12];
    const float* rg_fc_b     = (const float*)d_in[13];
    const float* rg_out_W    = (const float*)d_in[14];
    const float* rg_out_b    = (const float*)d_in[15];
    const float* dense_W     = (const float*)d_in[16];
    const float* dense_b     = (const float*)d_in[17];
    const float* pos_emb     = (const float*)d_in[18];
    const float* Wq          = (const float*)d_in[19];
    const float* Wk          = (const float*)d_in[20];
    const float* Wv          = (const float*)d_in[21];
    const float* Wo          = (const float*)d_in[22];
    const float* ln_g        = (const float*)d_in[23];
    const float* ln_b        = (const float*)d_in[24];
    const float* fc_W        = (const float*)d_in[25];
    const float* fc_b        = (const float*)d_in[26];
    float* out = (float*)d_out;

    float* base = nullptr;
    cudaGetSymbolAddress((void**)&base, g_s);
    float* roadx  = base + OFF_ROADX;
    float* roadq  = base + OFF_ROADQ;
    float* rpart  = base + OFF_RPART;
    float* rgkv   = base + OFF_RGKV;
    __half* AH = (__half*)(base + OFF_AH);
    __half* BH = (__half*)(base + OFF_BH);
    float* kvpart = base + OFF_KVPART;
    float* objkv  = base + OFF_OBJKV;
    float* xo     = base + OFF_XO;
    float* qpbuf  = base + OFF_QP;
    float* favb   = base + OFF_FAV;
    float* attnb  = base + OFF_ATTN;
    float* nbuf   = base + OFF_N;
    float* ybuf   = base + OFF_Y;

    cudaFuncSetAttribute(k_kv_mma, cudaFuncAttributeMaxDynamicSharedMemorySize, 110592);

    // road stack
    k_road_dense<<<256, 256>>>(road_inputs, rg_dense_W, rg_dense_b, roadx);
    for (int i = 0; i < 2; i++) {
        k_road_favA<<<256, 256>>>(roadx, roadq, rg_qkv_W, rg_qkv_b,
                                  rg_Wk + i * 256, rg_Wv + i * 256, rpart);
        k_road_reduce<<<8, 80>>>(rpart, rgkv);
        k_road_favB<<<256, 256>>>(roadx, roadq, rg_Wq + i * 256, rg_Wo + i * 256,
                                  rgkv, rg_ln_g + i * 16, rg_ln_b + i * 16,
                                  rg_fc_W + i * 256, rg_fc_b + i * 16);
    }
    k_wpack2<<<dim3(16, 32, 2), 256>>>(Wk, Wv, BH);
    k_rg_expand_h<<<4096, 256>>>(roadx, rg_out_W, rg_out_b, AH);

    // heavy tensor-core K/V + FAVOR reduction
    k_kv_mma<<<dim3(16, 512, 2), 256, 110592>>>(AH, BH, kvpart);
    k_kv_reduce<<<dim3(17, 128, 2), 256>>>(kvpart, objkv);

    // obj stack (tensor-core GEMMs)
    k_hgemm128<<<dim3(16, 8), 256>>>(obj_inputs, dense_W, xo,
                                     1024, 1024, 512, 2, 0.f, dense_b, pos_emb);
    for (int i = 0; i < 2; i++) {
        k_hgemm128<<<dim3(16, 8), 256>>>(xo, Wq + (size_t)i * 1048576, qpbuf,
                                         1024, 1024, 1024, 3, NORM_OBJ, nullptr, nullptr);
        k_fav_apply<<<dim3(16, 8), 256>>>(qpbuf, objkv, favb, i);
        k_hgemm128<<<dim3(16, 8), 256>>>(favb, Wo + (size_t)i * 1048576, attnb,
                                         1024, 1024, 1024, 4, 0.f, nullptr, xo);
        k_ln1024<<<1024, 256>>>(attnb, nullptr, nbuf, ln_g + i * 1024, ln_b + i * 1024);
        k_hgemm128<<<dim3(16, 8), 256>>>(nbuf, fc_W + (size_t)i * 1048576, ybuf,
                                         1024, 1024, 1024, 1, 0.f, fc_b + i * 1024, nullptr);
        k_ln1024<<<1024, 256>>>(nbuf, ybuf, (i == 0) ? xo : out,
                                ln_g + i * 1024, ln_b + i * 1024);
    }
}